// round 3
// baseline (speedup 1.0000x reference)
#include <cuda_runtime.h>
#include <math_constants.h>
#include <cstddef>

#define NB 8
#define NH 12
#define HD 64
#define DM 768
#define NSEQ 1024
#define NBH 96
#define SCALE 0.125f
#define EPSV 1e-6f
#define EPSN (1e-6f/1024.0f)

__device__ float g_Q[NBH*NSEQ*HD];
__device__ float g_K[NBH*NSEQ*HD];
__device__ float g_V[NBH*NSEQ*HD];
__device__ float g_relh[NBH*NSEQ*32];
__device__ float g_relw[NBH*NSEQ*32];
__device__ float g_vsum[NBH*HD];
__device__ float g_tmp[NB*NSEQ*DM];

// ---------------------------------------------------------------------------
// GEMM: C[m][c] = sum_k A[m][k]*W[c][k] + bias[c].  M=8192, K=768.
// mode 0: C=2304, scatter into g_Q/g_K/g_V (bh,n,d).  mode 1: C=768, plain out.
// 128x128 tile, BK=16, 256 threads, 8x8 micro-tile (cols strided by 16).
// ---------------------------------------------------------------------------
__global__ __launch_bounds__(256) void gemm_kernel(
    const float* __restrict__ A, const float* __restrict__ W,
    const float* __restrict__ bias, float* __restrict__ out, int mode)
{
    const int BKP = 20;
    __shared__ float As[128*BKP];
    __shared__ float Bs[128*BKP];
    const int m0 = blockIdx.y*128, c0 = blockIdx.x*128;
    const int tid = threadIdx.x, tx = tid & 15, ty = tid >> 4;
    const int r0 = tid >> 2, k4 = tid & 3;
    const float* Ap = (mode == 0) ? A : g_tmp;

    float4 pa0 = *(const float4*)&Ap[(size_t)(m0+r0)*DM    + k4*4];
    float4 pa1 = *(const float4*)&Ap[(size_t)(m0+r0+64)*DM + k4*4];
    float4 pb0 = *(const float4*)&W [(size_t)(c0+r0)*DM    + k4*4];
    float4 pb1 = *(const float4*)&W [(size_t)(c0+r0+64)*DM + k4*4];

    float acc[8][8];
    #pragma unroll
    for (int i=0;i<8;i++)
        #pragma unroll
        for (int j=0;j<8;j++) acc[i][j] = 0.f;

    for (int kt=0; kt<DM; kt+=16) {
        *(float4*)&As[(r0)*BKP    + k4*4] = pa0;
        *(float4*)&As[(r0+64)*BKP + k4*4] = pa1;
        *(float4*)&Bs[(r0)*BKP    + k4*4] = pb0;
        *(float4*)&Bs[(r0+64)*BKP + k4*4] = pb1;
        __syncthreads();
        const int ktn = kt + 16;
        if (ktn < DM) {
            pa0 = *(const float4*)&Ap[(size_t)(m0+r0)*DM    + ktn + k4*4];
            pa1 = *(const float4*)&Ap[(size_t)(m0+r0+64)*DM + ktn + k4*4];
            pb0 = *(const float4*)&W [(size_t)(c0+r0)*DM    + ktn + k4*4];
            pb1 = *(const float4*)&W [(size_t)(c0+r0+64)*DM + ktn + k4*4];
        }
        #pragma unroll
        for (int kk=0; kk<16; kk+=4) {
            float4 a[8];
            #pragma unroll
            for (int i=0;i<8;i++) a[i] = *(const float4*)&As[(ty*8+i)*BKP + kk];
            #pragma unroll
            for (int j=0;j<8;j++) {
                float4 b = *(const float4*)&Bs[(tx + j*16)*BKP + kk];
                #pragma unroll
                for (int i=0;i<8;i++) {
                    acc[i][j] = fmaf(a[i].x, b.x, acc[i][j]);
                    acc[i][j] = fmaf(a[i].y, b.y, acc[i][j]);
                    acc[i][j] = fmaf(a[i].z, b.z, acc[i][j]);
                    acc[i][j] = fmaf(a[i].w, b.w, acc[i][j]);
                }
            }
        }
        __syncthreads();
    }

    #pragma unroll
    for (int i=0;i<8;i++) {
        const int m = m0 + ty*8 + i;
        #pragma unroll
        for (int j=0;j<8;j++) {
            const int c = c0 + tx + j*16;
            const float v = acc[i][j] + bias[c];
            if (mode == 1) {
                out[(size_t)m*DM + c] = v;
            } else {
                const int t  = (c >= 1536) ? 2 : (c >= 768 ? 1 : 0);
                const int r  = c - t*DM;
                const int hh = r >> 6, d = r & 63;
                const int b_ = m >> 10, n = m & 1023;
                float* dst = (t==0) ? g_Q : (t==1) ? g_K : g_V;
                dst[((size_t)((b_*NH+hh)*NSEQ + n))*HD + d] = v;
            }
        }
    }
}

// ---------------------------------------------------------------------------
// relh[bh,n,kh] = q[bh,n,:] . rel_pos_h[qh-kh+31,:],  relw analogous.
// Block handles (bh, 4 consecutive n). 256 threads.
// ---------------------------------------------------------------------------
__global__ __launch_bounds__(256) void rel_kernel(
    const float* __restrict__ rph, const float* __restrict__ rpw)
{
    __shared__ float qs[4*64];
    const int blk = blockIdx.x;          // bh*256 + ng
    const int bh = blk >> 8, ng = blk & 255;
    const int tid = threadIdx.x, ln = tid >> 6, t = tid & 63;
    const int n = (ng << 2) + ln;
    qs[ln*64 + t] = g_Q[((size_t)(bh*NSEQ + n))*HD + t];
    __syncthreads();

    const int j = t & 31, half = t >> 5;
    const int qh = n >> 5, qw = n & 31;
    const float* tab = half ? rpw : rph;
    const int ref = half ? qw : qh;
    const float4* row = (const float4*)&tab[(ref - j + 31)*HD];
    const float4* q4  = (const float4*)&qs[ln*64];
    float a = 0.f;
    #pragma unroll
    for (int d4=0; d4<16; ++d4) {
        float4 rr = row[d4], qq = q4[d4];
        a += rr.x*qq.x + rr.y*qq.y + rr.z*qq.z + rr.w*qq.w;
    }
    float* dst = half ? g_relw : g_relh;
    dst[((size_t)(bh*NSEQ + n))*32 + j] = a;
}

// ---------------------------------------------------------------------------
// vsum[bh][d] = sum_k V[bh][k][d]
// ---------------------------------------------------------------------------
__global__ void vsum_kernel()
{
    __shared__ float red[256];
    const int bh = blockIdx.x, tid = threadIdx.x;
    const int d = tid & 63, part = tid >> 6;
    float s = 0.f;
    for (int k = part*256; k < part*256 + 256; ++k)
        s += g_V[((size_t)(bh*NSEQ + k))*HD + d];
    red[tid] = s;
    __syncthreads();
    if (tid < 64)
        g_vsum[bh*HD + tid] = red[tid] + red[tid+64] + red[tid+128] + red[tid+192];
}

// ---------------------------------------------------------------------------
// Fused flash attention with decomposed rel-pos bias + policy-masked softmax.
// Block = (q-tile 128, bh). 256 threads (16x16). S cols strided by 16.
// out = (sum_k e*v + EPSN*sum_v) / (sum_k e + EPSV),  e = exp(S-rowmax)*ap
// ---------------------------------------------------------------------------
#define FLASH_SMEM_FLOATS (128*68*3 + 128*129 + 128*32 + 128*4 + 128)
#define FLASH_SMEM_BYTES  (FLASH_SMEM_FLOATS*4)

__global__ __launch_bounds__(256,1) void flash_kernel(const float* __restrict__ policy)
{
    extern __shared__ float sm[];
    float* Qs    = sm;                 // [128][68]
    float* Ks    = Qs   + 128*68;      // [128][68]
    float* Vs    = Ks   + 128*68;      // [128][68]
    float* Ps    = Vs   + 128*68;      // [128][129]
    float* rw_s  = Ps   + 128*129;     // [128][32]
    float* rh_s  = rw_s + 128*32;      // [128][4]
    float* pol_s = rh_s + 128*4;       // [128]

    const int bh = blockIdx.y, q0 = blockIdx.x << 7;
    const int b_ = bh / NH, hh = bh - b_*NH;
    const int tid = threadIdx.x, tx = tid & 15, ty = tid >> 4;

    #pragma unroll
    for (int it=0; it<8; ++it) {
        int idx = it*256 + tid, mrow = idx >> 4, d4 = idx & 15;
        *(float4*)&Qs[mrow*68 + (d4<<2)] =
            *(const float4*)&g_Q[((size_t)(bh*NSEQ + q0 + mrow))*HD + (d4<<2)];
    }
    #pragma unroll
    for (int it=0; it<4; ++it) {
        int idx = it*256 + tid, mrow = idx >> 3, w4 = idx & 7;
        *(float4*)&rw_s[mrow*32 + (w4<<2)] =
            *(const float4*)&g_relw[((size_t)(bh*NSEQ + q0 + mrow))*32 + (w4<<2)];
    }

    float m[8], l[8], oa[8][4];
    #pragma unroll
    for (int i=0;i<8;i++) {
        m[i] = -CUDART_INF_F; l[i] = 0.f;
        oa[i][0]=oa[i][1]=oa[i][2]=oa[i][3]=0.f;
    }

    for (int k0=0; k0<NSEQ; k0+=128) {
        __syncthreads();   // previous PV done with Ps/Vs/Ks
        #pragma unroll
        for (int it=0; it<8; ++it) {
            int idx = it*256 + tid, mrow = idx >> 4, d4 = idx & 15;
            *(float4*)&Ks[mrow*68 + (d4<<2)] =
                *(const float4*)&g_K[((size_t)(bh*NSEQ + k0 + mrow))*HD + (d4<<2)];
            *(float4*)&Vs[mrow*68 + (d4<<2)] =
                *(const float4*)&g_V[((size_t)(bh*NSEQ + k0 + mrow))*HD + (d4<<2)];
        }
        if (tid < 128) {
            *(float4*)&rh_s[tid*4] =
                *(const float4*)&g_relh[((size_t)(bh*NSEQ + q0 + tid))*32 + (k0>>5)];
            pol_s[tid] = policy[(b_<<10) + k0 + tid];
        }
        __syncthreads();

        // S = scale*Q.K^T
        float acc[8][8];
        #pragma unroll
        for (int i=0;i<8;i++)
            #pragma unroll
            for (int j=0;j<8;j++) acc[i][j] = 0.f;

        #pragma unroll
        for (int kk=0; kk<16; ++kk) {
            float4 a[8];
            #pragma unroll
            for (int i=0;i<8;i++) a[i] = *(const float4*)&Qs[(ty*8+i)*68 + (kk<<2)];
            #pragma unroll
            for (int j=0;j<8;j++) {
                float4 b = *(const float4*)&Ks[(tx + j*16)*68 + (kk<<2)];
                #pragma unroll
                for (int i=0;i<8;i++) {
                    acc[i][j] = fmaf(a[i].x, b.x, acc[i][j]);
                    acc[i][j] = fmaf(a[i].y, b.y, acc[i][j]);
                    acc[i][j] = fmaf(a[i].z, b.z, acc[i][j]);
                    acc[i][j] = fmaf(a[i].w, b.w, acc[i][j]);
                }
            }
        }

        // bias + online masked softmax
        #pragma unroll
        for (int i=0;i<8;i++) {
            const int r = ty*8 + i, qg = q0 + r;
            float tmax = -CUDART_INF_F;
            #pragma unroll
            for (int j=0;j<8;j++) {
                float s = acc[i][j]*SCALE + rh_s[r*4 + (j>>1)]
                        + rw_s[r*32 + ((j&1)<<4) + tx];
                acc[i][j] = s;
                tmax = fmaxf(tmax, s);
            }
            #pragma unroll
            for (int o_=1;o_<16;o_<<=1)
                tmax = fmaxf(tmax, __shfl_xor_sync(0xffffffffu, tmax, o_));
            const float mnew = fmaxf(m[i], tmax);
            const float f = __expf(m[i] - mnew);
            m[i] = mnew;
            float rs = 0.f;
            #pragma unroll
            for (int j=0;j<8;j++) {
                const int c = tx + j*16;
                const int kg = k0 + c;
                const float ap = (kg == qg) ? 1.f : pol_s[c];
                const float e = __expf(acc[i][j] - mnew) * ap;
                rs += e;
                Ps[r*129 + c] = e;
            }
            #pragma unroll
            for (int o_=1;o_<16;o_<<=1)
                rs += __shfl_xor_sync(0xffffffffu, rs, o_);
            l[i] = l[i]*f + rs;
            oa[i][0]*=f; oa[i][1]*=f; oa[i][2]*=f; oa[i][3]*=f;
        }
        __syncthreads();

        // O += P.V
        #pragma unroll 4
        for (int c=0; c<128; ++c) {
            const float4 vv = *(const float4*)&Vs[c*68 + (tx<<2)];
            #pragma unroll
            for (int i=0;i<8;i++) {
                const float p = Ps[(ty*8+i)*129 + c];
                oa[i][0] = fmaf(p, vv.x, oa[i][0]);
                oa[i][1] = fmaf(p, vv.y, oa[i][1]);
                oa[i][2] = fmaf(p, vv.z, oa[i][2]);
                oa[i][3] = fmaf(p, vv.w, oa[i][3]);
            }
        }
    }

    // epilogue: out = (o + EPSN*vsum) / (l + EPSV)
    const float4 vs4 = *(const float4*)&g_vsum[bh*HD + (tx<<2)];
    #pragma unroll
    for (int i=0;i<8;i++) {
        const int r = ty*8 + i;
        const float inv = 1.f / (l[i] + EPSV);
        float4 o4;
        o4.x = (oa[i][0] + EPSN*vs4.x) * inv;
        o4.y = (oa[i][1] + EPSN*vs4.y) * inv;
        o4.z = (oa[i][2] + EPSN*vs4.z) * inv;
        o4.w = (oa[i][3] + EPSN*vs4.w) * inv;
        *(float4*)&g_tmp[((size_t)(b_*NSEQ + q0 + r))*DM + hh*HD + (tx<<2)] = o4;
    }
}

// ---------------------------------------------------------------------------
extern "C" void kernel_launch(void* const* d_in, const int* in_sizes, int n_in,
                              void* d_out, int out_size)
{
    const float* x      = (const float*)d_in[0];
    const float* policy = (const float*)d_in[1];
    const float* qkv_w  = (const float*)d_in[2];
    const float* qkv_b  = (const float*)d_in[3];
    const float* proj_w = (const float*)d_in[4];
    const float* proj_b = (const float*)d_in[5];
    const float* rph    = (const float*)d_in[6];
    const float* rpw    = (const float*)d_in[7];
    float* out = (float*)d_out;

    cudaFuncSetAttribute(flash_kernel,
        cudaFuncAttributeMaxDynamicSharedMemorySize, FLASH_SMEM_BYTES);

    gemm_kernel<<<dim3(18,64),256>>>(x, qkv_w, qkv_b, nullptr, 0);
    rel_kernel<<<NBH*256,256>>>(rph, rpw);
    vsum_kernel<<<NBH,256>>>();
    flash_kernel<<<dim3(8,NBH),256,FLASH_SMEM_BYTES>>>(policy);
    gemm_kernel<<<dim3(6,64),256>>>(nullptr, proj_w, proj_b, out, 1);
}

// round 4
// speedup vs baseline: 1.0009x; 1.0009x over previous
#include <cuda_runtime.h>
#include <math_constants.h>
#include <cstddef>

#define NB 8
#define NH 12
#define HD 64
#define DM 768
#define NSEQ 1024
#define NBH 96
#define SCALE 0.125f
#define EPSV 1e-6f
#define EPSN (1e-6f/1024.0f)

__device__ float g_Q[NBH*NSEQ*HD];
__device__ float g_K[NBH*NSEQ*HD];
__device__ float g_V[NBH*NSEQ*HD];
__device__ float g_relh[NBH*NSEQ*32];
__device__ float g_relw[NBH*NSEQ*32];
__device__ float g_vsum[NBH*HD];
__device__ float g_tmp[NB*NSEQ*DM];

// ---------------------------------------------------------------------------
// GEMM: C[m][c] = sum_k A[m][k]*W[c][k] + bias[c].  M=8192, K=768.
// mode 0: C=2304, scatter into g_Q/g_K/g_V (bh,n,d).  mode 1: C=768, plain out.
// 128x128 tile, BK=16, 256 threads, 8x8 micro-tile (cols strided by 16).
// ---------------------------------------------------------------------------
__global__ __launch_bounds__(256) void gemm_kernel(
    const float* __restrict__ A, const float* __restrict__ W,
    const float* __restrict__ bias, float* __restrict__ out, int mode)
{
    const int BKP = 20;
    __shared__ float As[128*BKP];
    __shared__ float Bs[128*BKP];
    const int m0 = blockIdx.y*128, c0 = blockIdx.x*128;
    const int tid = threadIdx.x, tx = tid & 15, ty = tid >> 4;
    const int r0 = tid >> 2, k4 = tid & 3;
    const float* Ap = (mode == 0) ? A : g_tmp;

    float4 pa0 = *(const float4*)&Ap[(size_t)(m0+r0)*DM    + k4*4];
    float4 pa1 = *(const float4*)&Ap[(size_t)(m0+r0+64)*DM + k4*4];
    float4 pb0 = *(const float4*)&W [(size_t)(c0+r0)*DM    + k4*4];
    float4 pb1 = *(const float4*)&W [(size_t)(c0+r0+64)*DM + k4*4];

    float acc[8][8];
    #pragma unroll
    for (int i=0;i<8;i++)
        #pragma unroll
        for (int j=0;j<8;j++) acc[i][j] = 0.f;

    for (int kt=0; kt<DM; kt+=16) {
        *(float4*)&As[(r0)*BKP    + k4*4] = pa0;
        *(float4*)&As[(r0+64)*BKP + k4*4] = pa1;
        *(float4*)&Bs[(r0)*BKP    + k4*4] = pb0;
        *(float4*)&Bs[(r0+64)*BKP + k4*4] = pb1;
        __syncthreads();
        const int ktn = kt + 16;
        if (ktn < DM) {
            pa0 = *(const float4*)&Ap[(size_t)(m0+r0)*DM    + ktn + k4*4];
            pa1 = *(const float4*)&Ap[(size_t)(m0+r0+64)*DM + ktn + k4*4];
            pb0 = *(const float4*)&W [(size_t)(c0+r0)*DM    + ktn + k4*4];
            pb1 = *(const float4*)&W [(size_t)(c0+r0+64)*DM + ktn + k4*4];
        }
        #pragma unroll
        for (int kk=0; kk<16; kk+=4) {
            float4 a[8];
            #pragma unroll
            for (int i=0;i<8;i++) a[i] = *(const float4*)&As[(ty*8+i)*BKP + kk];
            #pragma unroll
            for (int j=0;j<8;j++) {
                float4 b = *(const float4*)&Bs[(tx + j*16)*BKP + kk];
                #pragma unroll
                for (int i=0;i<8;i++) {
                    acc[i][j] = fmaf(a[i].x, b.x, acc[i][j]);
                    acc[i][j] = fmaf(a[i].y, b.y, acc[i][j]);
                    acc[i][j] = fmaf(a[i].z, b.z, acc[i][j]);
                    acc[i][j] = fmaf(a[i].w, b.w, acc[i][j]);
                }
            }
        }
        __syncthreads();
    }

    #pragma unroll
    for (int i=0;i<8;i++) {
        const int m = m0 + ty*8 + i;
        #pragma unroll
        for (int j=0;j<8;j++) {
            const int c = c0 + tx + j*16;
            const float v = acc[i][j] + bias[c];
            if (mode == 1) {
                out[(size_t)m*DM + c] = v;
            } else {
                const int t  = (c >= 1536) ? 2 : (c >= 768 ? 1 : 0);
                const int r  = c - t*DM;
                const int hh = r >> 6, d = r & 63;
                const int b_ = m >> 10, n = m & 1023;
                float* dst = (t==0) ? g_Q : (t==1) ? g_K : g_V;
                dst[((size_t)((b_*NH+hh)*NSEQ + n))*HD + d] = v;
            }
        }
    }
}

// ---------------------------------------------------------------------------
// relh[bh,n,kh] = q[bh,n,:] . rel_pos_h[qh-kh+31,:],  relw analogous.
// Block handles (bh, 4 consecutive n). 256 threads.
// ---------------------------------------------------------------------------
__global__ __launch_bounds__(256) void rel_kernel(
    const float* __restrict__ rph, const float* __restrict__ rpw)
{
    __shared__ float qs[4*64];
    const int blk = blockIdx.x;          // bh*256 + ng
    const int bh = blk >> 8, ng = blk & 255;
    const int tid = threadIdx.x, ln = tid >> 6, t = tid & 63;
    const int n = (ng << 2) + ln;
    qs[ln*64 + t] = g_Q[((size_t)(bh*NSEQ + n))*HD + t];
    __syncthreads();

    const int j = t & 31, half = t >> 5;
    const int qh = n >> 5, qw = n & 31;
    const float* tab = half ? rpw : rph;
    const int ref = half ? qw : qh;
    const float4* row = (const float4*)&tab[(ref - j + 31)*HD];
    const float4* q4  = (const float4*)&qs[ln*64];
    float a = 0.f;
    #pragma unroll
    for (int d4=0; d4<16; ++d4) {
        float4 rr = row[d4], qq = q4[d4];
        a += rr.x*qq.x + rr.y*qq.y + rr.z*qq.z + rr.w*qq.w;
    }
    float* dst = half ? g_relw : g_relh;
    dst[((size_t)(bh*NSEQ + n))*32 + j] = a;
}

// ---------------------------------------------------------------------------
// vsum[bh][d] = sum_k V[bh][k][d]
// ---------------------------------------------------------------------------
__global__ void vsum_kernel()
{
    __shared__ float red[256];
    const int bh = blockIdx.x, tid = threadIdx.x;
    const int d = tid & 63, part = tid >> 6;
    float s = 0.f;
    for (int k = part*256; k < part*256 + 256; ++k)
        s += g_V[((size_t)(bh*NSEQ + k))*HD + d];
    red[tid] = s;
    __syncthreads();
    if (tid < 64)
        g_vsum[bh*HD + tid] = red[tid] + red[tid+64] + red[tid+128] + red[tid+192];
}

// ---------------------------------------------------------------------------
// Fused flash attention with decomposed rel-pos bias + policy-masked softmax.
// Block = (q-tile 128, bh). 256 threads (16x16). S cols strided by 16.
// out = (sum_k e*v + EPSN*sum_v) / (sum_k e + EPSV),  e = exp(S-rowmax)*ap
// ---------------------------------------------------------------------------
#define FLASH_SMEM_FLOATS (128*68*3 + 128*129 + 128*32 + 128*4 + 128)
#define FLASH_SMEM_BYTES  (FLASH_SMEM_FLOATS*4)

__global__ __launch_bounds__(256,1) void flash_kernel(const float* __restrict__ policy)
{
    extern __shared__ float sm[];
    float* Qs    = sm;                 // [128][68]
    float* Ks    = Qs   + 128*68;      // [128][68]
    float* Vs    = Ks   + 128*68;      // [128][68]
    float* Ps    = Vs   + 128*68;      // [128][129]
    float* rw_s  = Ps   + 128*129;     // [128][32]
    float* rh_s  = rw_s + 128*32;      // [128][4]
    float* pol_s = rh_s + 128*4;       // [128]

    const int bh = blockIdx.y, q0 = blockIdx.x << 7;
    const int b_ = bh / NH, hh = bh - b_*NH;
    const int tid = threadIdx.x, tx = tid & 15, ty = tid >> 4;

    #pragma unroll
    for (int it=0; it<8; ++it) {
        int idx = it*256 + tid, mrow = idx >> 4, d4 = idx & 15;
        *(float4*)&Qs[mrow*68 + (d4<<2)] =
            *(const float4*)&g_Q[((size_t)(bh*NSEQ + q0 + mrow))*HD + (d4<<2)];
    }
    #pragma unroll
    for (int it=0; it<4; ++it) {
        int idx = it*256 + tid, mrow = idx >> 3, w4 = idx & 7;
        *(float4*)&rw_s[mrow*32 + (w4<<2)] =
            *(const float4*)&g_relw[((size_t)(bh*NSEQ + q0 + mrow))*32 + (w4<<2)];
    }

    float m[8], l[8], oa[8][4];
    #pragma unroll
    for (int i=0;i<8;i++) {
        m[i] = -CUDART_INF_F; l[i] = 0.f;
        oa[i][0]=oa[i][1]=oa[i][2]=oa[i][3]=0.f;
    }

    for (int k0=0; k0<NSEQ; k0+=128) {
        __syncthreads();   // previous PV done with Ps/Vs/Ks
        #pragma unroll
        for (int it=0; it<8; ++it) {
            int idx = it*256 + tid, mrow = idx >> 4, d4 = idx & 15;
            *(float4*)&Ks[mrow*68 + (d4<<2)] =
                *(const float4*)&g_K[((size_t)(bh*NSEQ + k0 + mrow))*HD + (d4<<2)];
            *(float4*)&Vs[mrow*68 + (d4<<2)] =
                *(const float4*)&g_V[((size_t)(bh*NSEQ + k0 + mrow))*HD + (d4<<2)];
        }
        if (tid < 128) {
            *(float4*)&rh_s[tid*4] =
                *(const float4*)&g_relh[((size_t)(bh*NSEQ + q0 + tid))*32 + (k0>>5)];
            pol_s[tid] = policy[(b_<<10) + k0 + tid];
        }
        __syncthreads();

        // S = scale*Q.K^T
        float acc[8][8];
        #pragma unroll
        for (int i=0;i<8;i++)
            #pragma unroll
            for (int j=0;j<8;j++) acc[i][j] = 0.f;

        #pragma unroll
        for (int kk=0; kk<16; ++kk) {
            float4 a[8];
            #pragma unroll
            for (int i=0;i<8;i++) a[i] = *(const float4*)&Qs[(ty*8+i)*68 + (kk<<2)];
            #pragma unroll
            for (int j=0;j<8;j++) {
                float4 b = *(const float4*)&Ks[(tx + j*16)*68 + (kk<<2)];
                #pragma unroll
                for (int i=0;i<8;i++) {
                    acc[i][j] = fmaf(a[i].x, b.x, acc[i][j]);
                    acc[i][j] = fmaf(a[i].y, b.y, acc[i][j]);
                    acc[i][j] = fmaf(a[i].z, b.z, acc[i][j]);
                    acc[i][j] = fmaf(a[i].w, b.w, acc[i][j]);
                }
            }
        }

        // bias + online masked softmax
        #pragma unroll
        for (int i=0;i<8;i++) {
            const int r = ty*8 + i, qg = q0 + r;
            float tmax = -CUDART_INF_F;
            #pragma unroll
            for (int j=0;j<8;j++) {
                float s = acc[i][j]*SCALE + rh_s[r*4 + (j>>1)]
                        + rw_s[r*32 + ((j&1)<<4) + tx];
                acc[i][j] = s;
                tmax = fmaxf(tmax, s);
            }
            #pragma unroll
            for (int o_=1;o_<16;o_<<=1)
                tmax = fmaxf(tmax, __shfl_xor_sync(0xffffffffu, tmax, o_));
            const float mnew = fmaxf(m[i], tmax);
            const float f = __expf(m[i] - mnew);
            m[i] = mnew;
            float rs = 0.f;
            #pragma unroll
            for (int j=0;j<8;j++) {
                const int c = tx + j*16;
                const int kg = k0 + c;
                const float ap = (kg == qg) ? 1.f : pol_s[c];
                const float e = __expf(acc[i][j] - mnew) * ap;
                rs += e;
                Ps[r*129 + c] = e;
            }
            #pragma unroll
            for (int o_=1;o_<16;o_<<=1)
                rs += __shfl_xor_sync(0xffffffffu, rs, o_);
            l[i] = l[i]*f + rs;
            oa[i][0]*=f; oa[i][1]*=f; oa[i][2]*=f; oa[i][3]*=f;
        }
        __syncthreads();

        // O += P.V
        #pragma unroll 4
        for (int c=0; c<128; ++c) {
            const float4 vv = *(const float4*)&Vs[c*68 + (tx<<2)];
            #pragma unroll
            for (int i=0;i<8;i++) {
                const float p = Ps[(ty*8+i)*129 + c];
                oa[i][0] = fmaf(p, vv.x, oa[i][0]);
                oa[i][1] = fmaf(p, vv.y, oa[i][1]);
                oa[i][2] = fmaf(p, vv.z, oa[i][2]);
                oa[i][3] = fmaf(p, vv.w, oa[i][3]);
            }
        }
    }

    // epilogue: out = (o + EPSN*vsum) / (l + EPSV)
    const float4 vs4 = *(const float4*)&g_vsum[bh*HD + (tx<<2)];
    #pragma unroll
    for (int i=0;i<8;i++) {
        const int r = ty*8 + i;
        const float inv = 1.f / (l[i] + EPSV);
        float4 o4;
        o4.x = (oa[i][0] + EPSN*vs4.x) * inv;
        o4.y = (oa[i][1] + EPSN*vs4.y) * inv;
        o4.z = (oa[i][2] + EPSN*vs4.z) * inv;
        o4.w = (oa[i][3] + EPSN*vs4.w) * inv;
        *(float4*)&g_tmp[((size_t)(b_*NSEQ + q0 + r))*DM + hh*HD + (tx<<2)] = o4;
    }
}

// ---------------------------------------------------------------------------
extern "C" void kernel_launch(void* const* d_in, const int* in_sizes, int n_in,
                              void* d_out, int out_size)
{
    const float* x      = (const float*)d_in[0];
    const float* policy = (const float*)d_in[1];
    const float* qkv_w  = (const float*)d_in[2];
    const float* qkv_b  = (const float*)d_in[3];
    const float* proj_w = (const float*)d_in[4];
    const float* proj_b = (const float*)d_in[5];
    const float* rph    = (const float*)d_in[6];
    const float* rpw    = (const float*)d_in[7];
    float* out = (float*)d_out;

    cudaFuncSetAttribute(flash_kernel,
        cudaFuncAttributeMaxDynamicSharedMemorySize, FLASH_SMEM_BYTES);

    gemm_kernel<<<dim3(18,64),256>>>(x, qkv_w, qkv_b, nullptr, 0);
    rel_kernel<<<NBH*256,256>>>(rph, rpw);
    vsum_kernel<<<NBH,256>>>();
    flash_kernel<<<dim3(8,NBH),256,FLASH_SMEM_BYTES>>>(policy);
    gemm_kernel<<<dim3(6,64),256>>>(nullptr, proj_w, proj_b, out, 1);
}

// round 5
// speedup vs baseline: 1.0013x; 1.0004x over previous
#include <cuda_runtime.h>
#include <math_constants.h>
#include <cstddef>

#define NB 8
#define NH 12
#define HD 64
#define DM 768
#define NSEQ 1024
#define NBH 96
#define SCALE 0.125f
#define EPSV 1e-6f
#define EPSN (1e-6f/1024.0f)

__device__ float g_Q[NBH*NSEQ*HD];
__device__ float g_K[NBH*NSEQ*HD];
__device__ float g_V[NBH*NSEQ*HD];
__device__ float g_relh[NBH*NSEQ*32];
__device__ float g_relw[NBH*NSEQ*32];
__device__ float g_vsum[NBH*HD];
__device__ float g_tmp[NB*NSEQ*DM];

// ---------------------------------------------------------------------------
// GEMM: C[m][c] = sum_k A[m][k]*W[c][k] + bias[c].  M=8192, K=768.
// mode 0: C=2304, scatter into g_Q/g_K/g_V (bh,n,d).  mode 1: C=768, plain out.
// 128x128 tile, BK=16, 256 threads, 8x8 micro-tile (cols strided by 16).
// ---------------------------------------------------------------------------
__global__ __launch_bounds__(256) void gemm_kernel(
    const float* __restrict__ A, const float* __restrict__ W,
    const float* __restrict__ bias, float* __restrict__ out, int mode)
{
    const int BKP = 20;
    __shared__ float As[128*BKP];
    __shared__ float Bs[128*BKP];
    const int m0 = blockIdx.y*128, c0 = blockIdx.x*128;
    const int tid = threadIdx.x, tx = tid & 15, ty = tid >> 4;
    const int r0 = tid >> 2, k4 = tid & 3;
    const float* Ap = (mode == 0) ? A : g_tmp;

    float4 pa0 = *(const float4*)&Ap[(size_t)(m0+r0)*DM    + k4*4];
    float4 pa1 = *(const float4*)&Ap[(size_t)(m0+r0+64)*DM + k4*4];
    float4 pb0 = *(const float4*)&W [(size_t)(c0+r0)*DM    + k4*4];
    float4 pb1 = *(const float4*)&W [(size_t)(c0+r0+64)*DM + k4*4];

    float acc[8][8];
    #pragma unroll
    for (int i=0;i<8;i++)
        #pragma unroll
        for (int j=0;j<8;j++) acc[i][j] = 0.f;

    for (int kt=0; kt<DM; kt+=16) {
        *(float4*)&As[(r0)*BKP    + k4*4] = pa0;
        *(float4*)&As[(r0+64)*BKP + k4*4] = pa1;
        *(float4*)&Bs[(r0)*BKP    + k4*4] = pb0;
        *(float4*)&Bs[(r0+64)*BKP + k4*4] = pb1;
        __syncthreads();
        const int ktn = kt + 16;
        if (ktn < DM) {
            pa0 = *(const float4*)&Ap[(size_t)(m0+r0)*DM    + ktn + k4*4];
            pa1 = *(const float4*)&Ap[(size_t)(m0+r0+64)*DM + ktn + k4*4];
            pb0 = *(const float4*)&W [(size_t)(c0+r0)*DM    + ktn + k4*4];
            pb1 = *(const float4*)&W [(size_t)(c0+r0+64)*DM + ktn + k4*4];
        }
        #pragma unroll
        for (int kk=0; kk<16; kk+=4) {
            float4 a[8];
            #pragma unroll
            for (int i=0;i<8;i++) a[i] = *(const float4*)&As[(ty*8+i)*BKP + kk];
            #pragma unroll
            for (int j=0;j<8;j++) {
                float4 b = *(const float4*)&Bs[(tx + j*16)*BKP + kk];
                #pragma unroll
                for (int i=0;i<8;i++) {
                    acc[i][j] = fmaf(a[i].x, b.x, acc[i][j]);
                    acc[i][j] = fmaf(a[i].y, b.y, acc[i][j]);
                    acc[i][j] = fmaf(a[i].z, b.z, acc[i][j]);
                    acc[i][j] = fmaf(a[i].w, b.w, acc[i][j]);
                }
            }
        }
        __syncthreads();
    }

    #pragma unroll
    for (int i=0;i<8;i++) {
        const int m = m0 + ty*8 + i;
        #pragma unroll
        for (int j=0;j<8;j++) {
            const int c = c0 + tx + j*16;
            const float v = acc[i][j] + bias[c];
            if (mode == 1) {
                out[(size_t)m*DM + c] = v;
            } else {
                const int t  = (c >= 1536) ? 2 : (c >= 768 ? 1 : 0);
                const int r  = c - t*DM;
                const int hh = r >> 6, d = r & 63;
                const int b_ = m >> 10, n = m & 1023;
                float* dst = (t==0) ? g_Q : (t==1) ? g_K : g_V;
                dst[((size_t)((b_*NH+hh)*NSEQ + n))*HD + d] = v;
            }
        }
    }
}

// ---------------------------------------------------------------------------
// relh[bh,n,kh] = q[bh,n,:] . rel_pos_h[qh-kh+31,:],  relw analogous.
// Block handles (bh, 4 consecutive n). 256 threads.
// ---------------------------------------------------------------------------
__global__ __launch_bounds__(256) void rel_kernel(
    const float* __restrict__ rph, const float* __restrict__ rpw)
{
    __shared__ float qs[4*64];
    const int blk = blockIdx.x;          // bh*256 + ng
    const int bh = blk >> 8, ng = blk & 255;
    const int tid = threadIdx.x, ln = tid >> 6, t = tid & 63;
    const int n = (ng << 2) + ln;
    qs[ln*64 + t] = g_Q[((size_t)(bh*NSEQ + n))*HD + t];
    __syncthreads();

    const int j = t & 31, half = t >> 5;
    const int qh = n >> 5, qw = n & 31;
    const float* tab = half ? rpw : rph;
    const int ref = half ? qw : qh;
    const float4* row = (const float4*)&tab[(ref - j + 31)*HD];
    const float4* q4  = (const float4*)&qs[ln*64];
    float a = 0.f;
    #pragma unroll
    for (int d4=0; d4<16; ++d4) {
        float4 rr = row[d4], qq = q4[d4];
        a += rr.x*qq.x + rr.y*qq.y + rr.z*qq.z + rr.w*qq.w;
    }
    float* dst = half ? g_relw : g_relh;
    dst[((size_t)(bh*NSEQ + n))*32 + j] = a;
}

// ---------------------------------------------------------------------------
// vsum[bh][d] = sum_k V[bh][k][d]
// ---------------------------------------------------------------------------
__global__ void vsum_kernel()
{
    __shared__ float red[256];
    const int bh = blockIdx.x, tid = threadIdx.x;
    const int d = tid & 63, part = tid >> 6;
    float s = 0.f;
    for (int k = part*256; k < part*256 + 256; ++k)
        s += g_V[((size_t)(bh*NSEQ + k))*HD + d];
    red[tid] = s;
    __syncthreads();
    if (tid < 64)
        g_vsum[bh*HD + tid] = red[tid] + red[tid+64] + red[tid+128] + red[tid+192];
}

// ---------------------------------------------------------------------------
// Fused flash attention with decomposed rel-pos bias + policy-masked softmax.
// Block = (q-tile 128, bh). 256 threads (16x16). S cols strided by 16.
// out = (sum_k e*v + EPSN*sum_v) / (sum_k e + EPSV),  e = exp(S-rowmax)*ap
// ---------------------------------------------------------------------------
#define FLASH_SMEM_FLOATS (128*68*3 + 128*129 + 128*32 + 128*4 + 128)
#define FLASH_SMEM_BYTES  (FLASH_SMEM_FLOATS*4)

__global__ __launch_bounds__(256,1) void flash_kernel(const float* __restrict__ policy)
{
    extern __shared__ float sm[];
    float* Qs    = sm;                 // [128][68]
    float* Ks    = Qs   + 128*68;      // [128][68]
    float* Vs    = Ks   + 128*68;      // [128][68]
    float* Ps    = Vs   + 128*68;      // [128][129]
    float* rw_s  = Ps   + 128*129;     // [128][32]
    float* rh_s  = rw_s + 128*32;      // [128][4]
    float* pol_s = rh_s + 128*4;       // [128]

    const int bh = blockIdx.y, q0 = blockIdx.x << 7;
    const int b_ = bh / NH, hh = bh - b_*NH;
    const int tid = threadIdx.x, tx = tid & 15, ty = tid >> 4;

    #pragma unroll
    for (int it=0; it<8; ++it) {
        int idx = it*256 + tid, mrow = idx >> 4, d4 = idx & 15;
        *(float4*)&Qs[mrow*68 + (d4<<2)] =
            *(const float4*)&g_Q[((size_t)(bh*NSEQ + q0 + mrow))*HD + (d4<<2)];
    }
    #pragma unroll
    for (int it=0; it<4; ++it) {
        int idx = it*256 + tid, mrow = idx >> 3, w4 = idx & 7;
        *(float4*)&rw_s[mrow*32 + (w4<<2)] =
            *(const float4*)&g_relw[((size_t)(bh*NSEQ + q0 + mrow))*32 + (w4<<2)];
    }

    float m[8], l[8], oa[8][4];
    #pragma unroll
    for (int i=0;i<8;i++) {
        m[i] = -CUDART_INF_F; l[i] = 0.f;
        oa[i][0]=oa[i][1]=oa[i][2]=oa[i][3]=0.f;
    }

    for (int k0=0; k0<NSEQ; k0+=128) {
        __syncthreads();   // previous PV done with Ps/Vs/Ks
        #pragma unroll
        for (int it=0; it<8; ++it) {
            int idx = it*256 + tid, mrow = idx >> 4, d4 = idx & 15;
            *(float4*)&Ks[mrow*68 + (d4<<2)] =
                *(const float4*)&g_K[((size_t)(bh*NSEQ + k0 + mrow))*HD + (d4<<2)];
            *(float4*)&Vs[mrow*68 + (d4<<2)] =
                *(const float4*)&g_V[((size_t)(bh*NSEQ + k0 + mrow))*HD + (d4<<2)];
        }
        if (tid < 128) {
            *(float4*)&rh_s[tid*4] =
                *(const float4*)&g_relh[((size_t)(bh*NSEQ + q0 + tid))*32 + (k0>>5)];
            pol_s[tid] = policy[(b_<<10) + k0 + tid];
        }
        __syncthreads();

        // S = scale*Q.K^T
        float acc[8][8];
        #pragma unroll
        for (int i=0;i<8;i++)
            #pragma unroll
            for (int j=0;j<8;j++) acc[i][j] = 0.f;

        #pragma unroll
        for (int kk=0; kk<16; ++kk) {
            float4 a[8];
            #pragma unroll
            for (int i=0;i<8;i++) a[i] = *(const float4*)&Qs[(ty*8+i)*68 + (kk<<2)];
            #pragma unroll
            for (int j=0;j<8;j++) {
                float4 b = *(const float4*)&Ks[(tx + j*16)*68 + (kk<<2)];
                #pragma unroll
                for (int i=0;i<8;i++) {
                    acc[i][j] = fmaf(a[i].x, b.x, acc[i][j]);
                    acc[i][j] = fmaf(a[i].y, b.y, acc[i][j]);
                    acc[i][j] = fmaf(a[i].z, b.z, acc[i][j]);
                    acc[i][j] = fmaf(a[i].w, b.w, acc[i][j]);
                }
            }
        }

        // bias + online masked softmax
        #pragma unroll
        for (int i=0;i<8;i++) {
            const int r = ty*8 + i, qg = q0 + r;
            float tmax = -CUDART_INF_F;
            #pragma unroll
            for (int j=0;j<8;j++) {
                float s = acc[i][j]*SCALE + rh_s[r*4 + (j>>1)]
                        + rw_s[r*32 + ((j&1)<<4) + tx];
                acc[i][j] = s;
                tmax = fmaxf(tmax, s);
            }
            #pragma unroll
            for (int o_=1;o_<16;o_<<=1)
                tmax = fmaxf(tmax, __shfl_xor_sync(0xffffffffu, tmax, o_));
            const float mnew = fmaxf(m[i], tmax);
            const float f = __expf(m[i] - mnew);
            m[i] = mnew;
            float rs = 0.f;
            #pragma unroll
            for (int j=0;j<8;j++) {
                const int c = tx + j*16;
                const int kg = k0 + c;
                const float ap = (kg == qg) ? 1.f : pol_s[c];
                const float e = __expf(acc[i][j] - mnew) * ap;
                rs += e;
                Ps[r*129 + c] = e;
            }
            #pragma unroll
            for (int o_=1;o_<16;o_<<=1)
                rs += __shfl_xor_sync(0xffffffffu, rs, o_);
            l[i] = l[i]*f + rs;
            oa[i][0]*=f; oa[i][1]*=f; oa[i][2]*=f; oa[i][3]*=f;
        }
        __syncthreads();

        // O += P.V
        #pragma unroll 4
        for (int c=0; c<128; ++c) {
            const float4 vv = *(const float4*)&Vs[c*68 + (tx<<2)];
            #pragma unroll
            for (int i=0;i<8;i++) {
                const float p = Ps[(ty*8+i)*129 + c];
                oa[i][0] = fmaf(p, vv.x, oa[i][0]);
                oa[i][1] = fmaf(p, vv.y, oa[i][1]);
                oa[i][2] = fmaf(p, vv.z, oa[i][2]);
                oa[i][3] = fmaf(p, vv.w, oa[i][3]);
            }
        }
    }

    // epilogue: out = (o + EPSN*vsum) / (l + EPSV)
    const float4 vs4 = *(const float4*)&g_vsum[bh*HD + (tx<<2)];
    #pragma unroll
    for (int i=0;i<8;i++) {
        const int r = ty*8 + i;
        const float inv = 1.f / (l[i] + EPSV);
        float4 o4;
        o4.x = (oa[i][0] + EPSN*vs4.x) * inv;
        o4.y = (oa[i][1] + EPSN*vs4.y) * inv;
        o4.z = (oa[i][2] + EPSN*vs4.z) * inv;
        o4.w = (oa[i][3] + EPSN*vs4.w) * inv;
        *(float4*)&g_tmp[((size_t)(b_*NSEQ + q0 + r))*DM + hh*HD + (tx<<2)] = o4;
    }
}

// ---------------------------------------------------------------------------
extern "C" void kernel_launch(void* const* d_in, const int* in_sizes, int n_in,
                              void* d_out, int out_size)
{
    const float* x      = (const float*)d_in[0];
    const float* policy = (const float*)d_in[1];
    const float* qkv_w  = (const float*)d_in[2];
    const float* qkv_b  = (const float*)d_in[3];
    const float* proj_w = (const float*)d_in[4];
    const float* proj_b = (const float*)d_in[5];
    const float* rph    = (const float*)d_in[6];
    const float* rpw    = (const float*)d_in[7];
    float* out = (float*)d_out;

    cudaFuncSetAttribute(flash_kernel,
        cudaFuncAttributeMaxDynamicSharedMemorySize, FLASH_SMEM_BYTES);

    gemm_kernel<<<dim3(18,64),256>>>(x, qkv_w, qkv_b, nullptr, 0);
    rel_kernel<<<NBH*256,256>>>(rph, rpw);
    vsum_kernel<<<NBH,256>>>();
    flash_kernel<<<dim3(8,NBH),256,FLASH_SMEM_BYTES>>>(policy);
    gemm_kernel<<<dim3(6,64),256>>>(nullptr, proj_w, proj_b, out, 1);
}

// round 6
// speedup vs baseline: 1.2807x; 1.2791x over previous
#include <cuda_runtime.h>
#include <cuda_bf16.h>
#include <math_constants.h>
#include <cstddef>
#include <cstdint>

#define NB 8
#define NH 12
#define HD 64
#define DM 768
#define NSEQ 1024
#define NBH 96
#define SCALE 0.125f
#define EPSV 1e-6f
#define EPSN (1e-6f/1024.0f)
#define WOFF (2304*768)

__device__ float g_Q[NBH*NSEQ*HD];
__device__ float g_K[NBH*NSEQ*HD];
__device__ float g_V[NBH*NSEQ*HD];
__device__ float g_relh[NBH*NSEQ*32];
__device__ float g_relw[NBH*NSEQ*32];
__device__ float g_vsum[NBH*HD];

__device__ __nv_bfloat16 g_Xhi[NB*NSEQ*DM], g_Xlo[NB*NSEQ*DM];
__device__ __nv_bfloat16 g_Whi[3072*DM],    g_Wlo[3072*DM];      // qkv_w (2304) ++ proj_w (768)
__device__ __nv_bfloat16 g_Thi[NB*NSEQ*DM], g_Tlo[NB*NSEQ*DM];   // attention output, split

// ---------------------------------------------------------------------------
// split fp32 -> bf16 hi + bf16 lo.  which: 0 = x, 1 = qkv_w, 2 = proj_w
// ---------------------------------------------------------------------------
__global__ void split_kernel(const float* __restrict__ src, int which, int n4)
{
    int i = blockIdx.x*256 + threadIdx.x;
    if (i >= n4) return;
    __nv_bfloat16 *hi, *lo;
    if (which == 0)      { hi = g_Xhi;        lo = g_Xlo; }
    else if (which == 1) { hi = g_Whi;        lo = g_Wlo; }
    else                 { hi = g_Whi + WOFF; lo = g_Wlo + WOFF; }
    float4 v = ((const float4*)src)[i];
    __nv_bfloat16 h0 = __float2bfloat16(v.x), h1 = __float2bfloat16(v.y);
    __nv_bfloat16 h2 = __float2bfloat16(v.z), h3 = __float2bfloat16(v.w);
    __nv_bfloat162 hh0; hh0.x = h0; hh0.y = h1;
    __nv_bfloat162 hh1; hh1.x = h2; hh1.y = h3;
    __nv_bfloat162 ll0, ll1;
    ll0.x = __float2bfloat16(v.x - __bfloat162float(h0));
    ll0.y = __float2bfloat16(v.y - __bfloat162float(h1));
    ll1.x = __float2bfloat16(v.z - __bfloat162float(h2));
    ll1.y = __float2bfloat16(v.w - __bfloat162float(h3));
    ((__nv_bfloat162*)hi)[i*2]   = hh0;
    ((__nv_bfloat162*)hi)[i*2+1] = hh1;
    ((__nv_bfloat162*)lo)[i*2]   = ll0;
    ((__nv_bfloat162*)lo)[i*2+1] = ll1;
}

// ---------------------------------------------------------------------------
// Tensor-core GEMM (bf16 split, fp32 accum): C[m][c] = sum_k A[m][k]*W[c][k]+b
// M=8192, K=768.  mode 0: A=g_X*, W off 0, C=2304, scatter into g_Q/K/V.
//                 mode 1: A=g_T*, W off WOFF, C=768, plain out.
// CTA 128x128, BK=32, 8 warps (4 M x 2 N), warp tile 32x64 via m16n8k16.
// ---------------------------------------------------------------------------
#define MMA_BF16(d, a, b0, b1)                                             \
  asm volatile("mma.sync.aligned.m16n8k16.row.col.f32.bf16.bf16.f32 "      \
    "{%0,%1,%2,%3},{%4,%5,%6,%7},{%8,%9},{%0,%1,%2,%3};\n"                 \
    : "+f"(d[0]), "+f"(d[1]), "+f"(d[2]), "+f"(d[3])                       \
    : "r"(a[0]), "r"(a[1]), "r"(a[2]), "r"(a[3]), "r"(b0), "r"(b1))

__global__ __launch_bounds__(256) void gemm_mma(
    const float* __restrict__ bias, float* __restrict__ out, int mode)
{
    __shared__ __nv_bfloat16 As[2][128*40];
    __shared__ __nv_bfloat16 Bs[2][128*40];
    const __nv_bfloat16* Ah = mode ? g_Thi : g_Xhi;
    const __nv_bfloat16* Al = mode ? g_Tlo : g_Xlo;
    const __nv_bfloat16* Wh = g_Whi + (mode ? WOFF : 0);
    const __nv_bfloat16* Wl = g_Wlo + (mode ? WOFF : 0);

    const int m0 = blockIdx.y*128, c0 = blockIdx.x*128;
    const int tid = threadIdx.x, lane = tid & 31, wid = tid >> 5;
    const int wm = wid & 3, wn = wid >> 2;
    const int grp = lane >> 2, tig = lane & 3;
    const int ra = tid >> 2, qa = tid & 3;

    const size_t oA0 = (size_t)(m0+ra)*DM    + qa*8;
    const size_t oA1 = (size_t)(m0+ra+64)*DM + qa*8;
    const size_t oB0 = (size_t)(c0+ra)*DM    + qa*8;
    const size_t oB1 = (size_t)(c0+ra+64)*DM + qa*8;
    const int s0 = ra*40 + qa*8, s1 = (ra+64)*40 + qa*8;

    uint4 pAh0 = *(const uint4*)&Ah[oA0];
    uint4 pAh1 = *(const uint4*)&Ah[oA1];
    uint4 pAl0 = *(const uint4*)&Al[oA0];
    uint4 pAl1 = *(const uint4*)&Al[oA1];
    uint4 pBh0 = *(const uint4*)&Wh[oB0];
    uint4 pBh1 = *(const uint4*)&Wh[oB1];
    uint4 pBl0 = *(const uint4*)&Wl[oB0];
    uint4 pBl1 = *(const uint4*)&Wl[oB1];

    float acc[2][8][4];
    #pragma unroll
    for (int mi=0;mi<2;mi++)
        #pragma unroll
        for (int ni=0;ni<8;ni++)
            #pragma unroll
            for (int c=0;c<4;c++) acc[mi][ni][c] = 0.f;

    for (int kt=0; kt<DM; kt+=32) {
        *(uint4*)&As[0][s0] = pAh0;  *(uint4*)&As[0][s1] = pAh1;
        *(uint4*)&As[1][s0] = pAl0;  *(uint4*)&As[1][s1] = pAl1;
        *(uint4*)&Bs[0][s0] = pBh0;  *(uint4*)&Bs[0][s1] = pBh1;
        *(uint4*)&Bs[1][s0] = pBl0;  *(uint4*)&Bs[1][s1] = pBl1;
        __syncthreads();
        if (kt + 32 < DM) {
            const int kn = kt + 32;
            pAh0 = *(const uint4*)&Ah[oA0 + kn];
            pAh1 = *(const uint4*)&Ah[oA1 + kn];
            pAl0 = *(const uint4*)&Al[oA0 + kn];
            pAl1 = *(const uint4*)&Al[oA1 + kn];
            pBh0 = *(const uint4*)&Wh[oB0 + kn];
            pBh1 = *(const uint4*)&Wh[oB1 + kn];
            pBl0 = *(const uint4*)&Wl[oB0 + kn];
            pBl1 = *(const uint4*)&Wl[oB1 + kn];
        }
        #pragma unroll
        for (int ks=0; ks<2; ++ks) {
            const int kb = ks*16 + tig*2;
            uint32_t ah[2][4], al[2][4];
            #pragma unroll
            for (int mi=0;mi<2;mi++) {
                const int row = wm*32 + mi*16 + grp;
                ah[mi][0] = *(const uint32_t*)&As[0][row*40     + kb];
                ah[mi][1] = *(const uint32_t*)&As[0][(row+8)*40 + kb];
                ah[mi][2] = *(const uint32_t*)&As[0][row*40     + kb + 8];
                ah[mi][3] = *(const uint32_t*)&As[0][(row+8)*40 + kb + 8];
                al[mi][0] = *(const uint32_t*)&As[1][row*40     + kb];
                al[mi][1] = *(const uint32_t*)&As[1][(row+8)*40 + kb];
                al[mi][2] = *(const uint32_t*)&As[1][row*40     + kb + 8];
                al[mi][3] = *(const uint32_t*)&As[1][(row+8)*40 + kb + 8];
            }
            #pragma unroll
            for (int ni=0;ni<8;ni++) {
                const int col = wn*64 + ni*8 + grp;
                const uint32_t bh0 = *(const uint32_t*)&Bs[0][col*40 + kb];
                const uint32_t bh1 = *(const uint32_t*)&Bs[0][col*40 + kb + 8];
                const uint32_t bl0 = *(const uint32_t*)&Bs[1][col*40 + kb];
                const uint32_t bl1 = *(const uint32_t*)&Bs[1][col*40 + kb + 8];
                #pragma unroll
                for (int mi=0;mi<2;mi++) {
                    MMA_BF16(acc[mi][ni], ah[mi], bh0, bh1);
                    MMA_BF16(acc[mi][ni], ah[mi], bl0, bl1);
                    MMA_BF16(acc[mi][ni], al[mi], bh0, bh1);
                }
            }
        }
        __syncthreads();
    }

    #pragma unroll
    for (int mi=0;mi<2;mi++) {
        #pragma unroll
        for (int ni=0;ni<8;ni++) {
            const int c = c0 + wn*64 + ni*8 + tig*2;
            const float b0v = bias[c], b1v = bias[c+1];
            #pragma unroll
            for (int hr=0;hr<2;hr++) {
                const int m = m0 + wm*32 + mi*16 + grp + hr*8;
                const float v0 = acc[mi][ni][hr*2+0] + b0v;
                const float v1 = acc[mi][ni][hr*2+1] + b1v;
                if (mode == 1) {
                    *(float2*)&out[(size_t)m*DM + c] = make_float2(v0, v1);
                } else {
                    const int t  = (c >= 1536) ? 2 : (c >= 768 ? 1 : 0);
                    const int rr = c - t*DM;
                    const int hh = rr >> 6, d = rr & 63;
                    const int b_ = m >> 10, n = m & 1023;
                    float* dst = (t==0) ? g_Q : (t==1) ? g_K : g_V;
                    *(float2*)&dst[((size_t)((b_*NH+hh)*NSEQ + n))*HD + d]
                        = make_float2(v0, v1);
                }
            }
        }
    }
}

// ---------------------------------------------------------------------------
// relh[bh,n,kh] = q[bh,n,:] . rel_pos_h[qh-kh+31,:],  relw analogous.
// ---------------------------------------------------------------------------
__global__ __launch_bounds__(256) void rel_kernel(
    const float* __restrict__ rph, const float* __restrict__ rpw)
{
    __shared__ float qs[4*64];
    const int blk = blockIdx.x;
    const int bh = blk >> 8, ng = blk & 255;
    const int tid = threadIdx.x, ln = tid >> 6, t = tid & 63;
    const int n = (ng << 2) + ln;
    qs[ln*64 + t] = g_Q[((size_t)(bh*NSEQ + n))*HD + t];
    __syncthreads();

    const int j = t & 31, half = t >> 5;
    const int qh = n >> 5, qw = n & 31;
    const float* tab = half ? rpw : rph;
    const int ref = half ? qw : qh;
    const float4* row = (const float4*)&tab[(ref - j + 31)*HD];
    const float4* q4  = (const float4*)&qs[ln*64];
    float a = 0.f;
    #pragma unroll
    for (int d4=0; d4<16; ++d4) {
        float4 rr = row[d4], qq = q4[d4];
        a += rr.x*qq.x + rr.y*qq.y + rr.z*qq.z + rr.w*qq.w;
    }
    float* dst = half ? g_relw : g_relh;
    dst[((size_t)(bh*NSEQ + n))*32 + j] = a;
}

// ---------------------------------------------------------------------------
__global__ void vsum_kernel()
{
    __shared__ float red[256];
    const int bh = blockIdx.x, tid = threadIdx.x;
    const int d = tid & 63, part = tid >> 6;
    float s = 0.f;
    for (int k = part*256; k < part*256 + 256; ++k)
        s += g_V[((size_t)(bh*NSEQ + k))*HD + d];
    red[tid] = s;
    __syncthreads();
    if (tid < 64)
        g_vsum[bh*HD + tid] = red[tid] + red[tid+64] + red[tid+128] + red[tid+192];
}

// ---------------------------------------------------------------------------
// Fused flash attention (fp32) — epilogue now emits bf16 hi/lo for proj GEMM.
// ---------------------------------------------------------------------------
#define FLASH_SMEM_FLOATS (128*68*3 + 128*129 + 128*32 + 128*4 + 128)
#define FLASH_SMEM_BYTES  (FLASH_SMEM_FLOATS*4)

__global__ __launch_bounds__(256,1) void flash_kernel(const float* __restrict__ policy)
{
    extern __shared__ float sm[];
    float* Qs    = sm;
    float* Ks    = Qs   + 128*68;
    float* Vs    = Ks   + 128*68;
    float* Ps    = Vs   + 128*68;
    float* rw_s  = Ps   + 128*129;
    float* rh_s  = rw_s + 128*32;
    float* pol_s = rh_s + 128*4;

    const int bh = blockIdx.y, q0 = blockIdx.x << 7;
    const int b_ = bh / NH, hh = bh - b_*NH;
    const int tid = threadIdx.x, tx = tid & 15, ty = tid >> 4;

    #pragma unroll
    for (int it=0; it<8; ++it) {
        int idx = it*256 + tid, mrow = idx >> 4, d4 = idx & 15;
        *(float4*)&Qs[mrow*68 + (d4<<2)] =
            *(const float4*)&g_Q[((size_t)(bh*NSEQ + q0 + mrow))*HD + (d4<<2)];
    }
    #pragma unroll
    for (int it=0; it<4; ++it) {
        int idx = it*256 + tid, mrow = idx >> 3, w4 = idx & 7;
        *(float4*)&rw_s[mrow*32 + (w4<<2)] =
            *(const float4*)&g_relw[((size_t)(bh*NSEQ + q0 + mrow))*32 + (w4<<2)];
    }

    float m[8], l[8], oa[8][4];
    #pragma unroll
    for (int i=0;i<8;i++) {
        m[i] = -CUDART_INF_F; l[i] = 0.f;
        oa[i][0]=oa[i][1]=oa[i][2]=oa[i][3]=0.f;
    }

    for (int k0=0; k0<NSEQ; k0+=128) {
        __syncthreads();
        #pragma unroll
        for (int it=0; it<8; ++it) {
            int idx = it*256 + tid, mrow = idx >> 4, d4 = idx & 15;
            *(float4*)&Ks[mrow*68 + (d4<<2)] =
                *(const float4*)&g_K[((size_t)(bh*NSEQ + k0 + mrow))*HD + (d4<<2)];
            *(float4*)&Vs[mrow*68 + (d4<<2)] =
                *(const float4*)&g_V[((size_t)(bh*NSEQ + k0 + mrow))*HD + (d4<<2)];
        }
        if (tid < 128) {
            *(float4*)&rh_s[tid*4] =
                *(const float4*)&g_relh[((size_t)(bh*NSEQ + q0 + tid))*32 + (k0>>5)];
            pol_s[tid] = policy[(b_<<10) + k0 + tid];
        }
        __syncthreads();

        float acc[8][8];
        #pragma unroll
        for (int i=0;i<8;i++)
            #pragma unroll
            for (int j=0;j<8;j++) acc[i][j] = 0.f;

        #pragma unroll
        for (int kk=0; kk<16; ++kk) {
            float4 a[8];
            #pragma unroll
            for (int i=0;i<8;i++) a[i] = *(const float4*)&Qs[(ty*8+i)*68 + (kk<<2)];
            #pragma unroll
            for (int j=0;j<8;j++) {
                float4 b = *(const float4*)&Ks[(tx + j*16)*68 + (kk<<2)];
                #pragma unroll
                for (int i=0;i<8;i++) {
                    acc[i][j] = fmaf(a[i].x, b.x, acc[i][j]);
                    acc[i][j] = fmaf(a[i].y, b.y, acc[i][j]);
                    acc[i][j] = fmaf(a[i].z, b.z, acc[i][j]);
                    acc[i][j] = fmaf(a[i].w, b.w, acc[i][j]);
                }
            }
        }

        #pragma unroll
        for (int i=0;i<8;i++) {
            const int r = ty*8 + i, qg = q0 + r;
            float tmax = -CUDART_INF_F;
            #pragma unroll
            for (int j=0;j<8;j++) {
                float s = acc[i][j]*SCALE + rh_s[r*4 + (j>>1)]
                        + rw_s[r*32 + ((j&1)<<4) + tx];
                acc[i][j] = s;
                tmax = fmaxf(tmax, s);
            }
            #pragma unroll
            for (int o_=1;o_<16;o_<<=1)
                tmax = fmaxf(tmax, __shfl_xor_sync(0xffffffffu, tmax, o_));
            const float mnew = fmaxf(m[i], tmax);
            const float f = __expf(m[i] - mnew);
            m[i] = mnew;
            float rs = 0.f;
            #pragma unroll
            for (int j=0;j<8;j++) {
                const int c = tx + j*16;
                const int kg = k0 + c;
                const float ap = (kg == qg) ? 1.f : pol_s[c];
                const float e = __expf(acc[i][j] - mnew) * ap;
                rs += e;
                Ps[r*129 + c] = e;
            }
            #pragma unroll
            for (int o_=1;o_<16;o_<<=1)
                rs += __shfl_xor_sync(0xffffffffu, rs, o_);
            l[i] = l[i]*f + rs;
            oa[i][0]*=f; oa[i][1]*=f; oa[i][2]*=f; oa[i][3]*=f;
        }
        __syncthreads();

        #pragma unroll 4
        for (int c=0; c<128; ++c) {
            const float4 vv = *(const float4*)&Vs[c*68 + (tx<<2)];
            #pragma unroll
            for (int i=0;i<8;i++) {
                const float p = Ps[(ty*8+i)*129 + c];
                oa[i][0] = fmaf(p, vv.x, oa[i][0]);
                oa[i][1] = fmaf(p, vv.y, oa[i][1]);
                oa[i][2] = fmaf(p, vv.z, oa[i][2]);
                oa[i][3] = fmaf(p, vv.w, oa[i][3]);
            }
        }
    }

    // epilogue: out = (o + EPSN*vsum) / (l + EPSV), split to bf16 hi/lo
    const float4 vs4 = *(const float4*)&g_vsum[bh*HD + (tx<<2)];
    #pragma unroll
    for (int i=0;i<8;i++) {
        const int r = ty*8 + i;
        const float inv = 1.f / (l[i] + EPSV);
        float o[4];
        o[0] = (oa[i][0] + EPSN*vs4.x) * inv;
        o[1] = (oa[i][1] + EPSN*vs4.y) * inv;
        o[2] = (oa[i][2] + EPSN*vs4.z) * inv;
        o[3] = (oa[i][3] + EPSN*vs4.w) * inv;
        const size_t base = ((size_t)(b_*NSEQ + q0 + r))*DM + hh*HD + (tx<<2);
        __nv_bfloat16 h0 = __float2bfloat16(o[0]), h1 = __float2bfloat16(o[1]);
        __nv_bfloat16 h2 = __float2bfloat16(o[2]), h3 = __float2bfloat16(o[3]);
        __nv_bfloat162 hp0; hp0.x = h0; hp0.y = h1;
        __nv_bfloat162 hp1; hp1.x = h2; hp1.y = h3;
        __nv_bfloat162 lp0, lp1;
        lp0.x = __float2bfloat16(o[0] - __bfloat162float(h0));
        lp0.y = __float2bfloat16(o[1] - __bfloat162float(h1));
        lp1.x = __float2bfloat16(o[2] - __bfloat162float(h2));
        lp1.y = __float2bfloat16(o[3] - __bfloat162float(h3));
        *(__nv_bfloat162*)&g_Thi[base]   = hp0;
        *(__nv_bfloat162*)&g_Thi[base+2] = hp1;
        *(__nv_bfloat162*)&g_Tlo[base]   = lp0;
        *(__nv_bfloat162*)&g_Tlo[base+2] = lp1;
    }
}

// ---------------------------------------------------------------------------
extern "C" void kernel_launch(void* const* d_in, const int* in_sizes, int n_in,
                              void* d_out, int out_size)
{
    const float* x      = (const float*)d_in[0];
    const float* policy = (const float*)d_in[1];
    const float* qkv_w  = (const float*)d_in[2];
    const float* qkv_b  = (const float*)d_in[3];
    const float* proj_w = (const float*)d_in[4];
    const float* proj_b = (const float*)d_in[5];
    const float* rph    = (const float*)d_in[6];
    const float* rpw    = (const float*)d_in[7];
    float* out = (float*)d_out;

    cudaFuncSetAttribute(flash_kernel,
        cudaFuncAttributeMaxDynamicSharedMemorySize, FLASH_SMEM_BYTES);

    const int n4x = NB*NSEQ*DM/4, n4q = 2304*DM/4, n4p = DM*DM/4;
    split_kernel<<<(n4x+255)/256,256>>>(x,      0, n4x);
    split_kernel<<<(n4q+255)/256,256>>>(qkv_w,  1, n4q);
    split_kernel<<<(n4p+255)/256,256>>>(proj_w, 2, n4p);

    gemm_mma<<<dim3(18,64),256>>>(qkv_b, nullptr, 0);
    rel_kernel<<<NBH*256,256>>>(rph, rpw);
    vsum_kernel<<<NBH,256>>>();
    flash_kernel<<<dim3(8,NBH),256,FLASH_SMEM_BYTES>>>(policy);
    gemm_mma<<<dim3(6,64),256>>>(proj_b, out, 1);
}

// round 7
// speedup vs baseline: 1.2811x; 1.0003x over previous
#include <cuda_runtime.h>
#include <cuda_bf16.h>
#include <math_constants.h>
#include <cstddef>
#include <cstdint>

#define NB 8
#define NH 12
#define HD 64
#define DM 768
#define NSEQ 1024
#define NBH 96
#define SCALE 0.125f
#define EPSV 1e-6f
#define EPSN (1e-6f/1024.0f)
#define WOFF (2304*768)

__device__ float g_Q[NBH*NSEQ*HD];
__device__ float g_K[NBH*NSEQ*HD];
__device__ float g_V[NBH*NSEQ*HD];
__device__ float g_relh[NBH*NSEQ*32];
__device__ float g_relw[NBH*NSEQ*32];
__device__ float g_vsum[NBH*HD];

__device__ __nv_bfloat16 g_Xhi[NB*NSEQ*DM], g_Xlo[NB*NSEQ*DM];
__device__ __nv_bfloat16 g_Whi[3072*DM],    g_Wlo[3072*DM];      // qkv_w (2304) ++ proj_w (768)
__device__ __nv_bfloat16 g_Thi[NB*NSEQ*DM], g_Tlo[NB*NSEQ*DM];   // attention output, split

// ---------------------------------------------------------------------------
// split fp32 -> bf16 hi + bf16 lo.  which: 0 = x, 1 = qkv_w, 2 = proj_w
// ---------------------------------------------------------------------------
__global__ void split_kernel(const float* __restrict__ src, int which, int n4)
{
    int i = blockIdx.x*256 + threadIdx.x;
    if (i >= n4) return;
    __nv_bfloat16 *hi, *lo;
    if (which == 0)      { hi = g_Xhi;        lo = g_Xlo; }
    else if (which == 1) { hi = g_Whi;        lo = g_Wlo; }
    else                 { hi = g_Whi + WOFF; lo = g_Wlo + WOFF; }
    float4 v = ((const float4*)src)[i];
    __nv_bfloat16 h0 = __float2bfloat16(v.x), h1 = __float2bfloat16(v.y);
    __nv_bfloat16 h2 = __float2bfloat16(v.z), h3 = __float2bfloat16(v.w);
    __nv_bfloat162 hh0; hh0.x = h0; hh0.y = h1;
    __nv_bfloat162 hh1; hh1.x = h2; hh1.y = h3;
    __nv_bfloat162 ll0, ll1;
    ll0.x = __float2bfloat16(v.x - __bfloat162float(h0));
    ll0.y = __float2bfloat16(v.y - __bfloat162float(h1));
    ll1.x = __float2bfloat16(v.z - __bfloat162float(h2));
    ll1.y = __float2bfloat16(v.w - __bfloat162float(h3));
    ((__nv_bfloat162*)hi)[i*2]   = hh0;
    ((__nv_bfloat162*)hi)[i*2+1] = hh1;
    ((__nv_bfloat162*)lo)[i*2]   = ll0;
    ((__nv_bfloat162*)lo)[i*2+1] = ll1;
}

// ---------------------------------------------------------------------------
// Tensor-core GEMM (bf16 split, fp32 accum): C[m][c] = sum_k A[m][k]*W[c][k]+b
// M=8192, K=768.  mode 0: A=g_X*, W off 0, C=2304, scatter into g_Q/K/V.
//                 mode 1: A=g_T*, W off WOFF, C=768, plain out.
// CTA 128x128, BK=32, 8 warps (4 M x 2 N), warp tile 32x64 via m16n8k16.
// ---------------------------------------------------------------------------
#define MMA_BF16(d, a, b0, b1)                                             \
  asm volatile("mma.sync.aligned.m16n8k16.row.col.f32.bf16.bf16.f32 "      \
    "{%0,%1,%2,%3},{%4,%5,%6,%7},{%8,%9},{%0,%1,%2,%3};\n"                 \
    : "+f"(d[0]), "+f"(d[1]), "+f"(d[2]), "+f"(d[3])                       \
    : "r"(a[0]), "r"(a[1]), "r"(a[2]), "r"(a[3]), "r"(b0), "r"(b1))

__global__ __launch_bounds__(256) void gemm_mma(
    const float* __restrict__ bias, float* __restrict__ out, int mode)
{
    __shared__ __nv_bfloat16 As[2][128*40];
    __shared__ __nv_bfloat16 Bs[2][128*40];
    const __nv_bfloat16* Ah = mode ? g_Thi : g_Xhi;
    const __nv_bfloat16* Al = mode ? g_Tlo : g_Xlo;
    const __nv_bfloat16* Wh = g_Whi + (mode ? WOFF : 0);
    const __nv_bfloat16* Wl = g_Wlo + (mode ? WOFF : 0);

    const int m0 = blockIdx.y*128, c0 = blockIdx.x*128;
    const int tid = threadIdx.x, lane = tid & 31, wid = tid >> 5;
    const int wm = wid & 3, wn = wid >> 2;
    const int grp = lane >> 2, tig = lane & 3;
    const int ra = tid >> 2, qa = tid & 3;

    const size_t oA0 = (size_t)(m0+ra)*DM    + qa*8;
    const size_t oA1 = (size_t)(m0+ra+64)*DM + qa*8;
    const size_t oB0 = (size_t)(c0+ra)*DM    + qa*8;
    const size_t oB1 = (size_t)(c0+ra+64)*DM + qa*8;
    const int s0 = ra*40 + qa*8, s1 = (ra+64)*40 + qa*8;

    uint4 pAh0 = *(const uint4*)&Ah[oA0];
    uint4 pAh1 = *(const uint4*)&Ah[oA1];
    uint4 pAl0 = *(const uint4*)&Al[oA0];
    uint4 pAl1 = *(const uint4*)&Al[oA1];
    uint4 pBh0 = *(const uint4*)&Wh[oB0];
    uint4 pBh1 = *(const uint4*)&Wh[oB1];
    uint4 pBl0 = *(const uint4*)&Wl[oB0];
    uint4 pBl1 = *(const uint4*)&Wl[oB1];

    float acc[2][8][4];
    #pragma unroll
    for (int mi=0;mi<2;mi++)
        #pragma unroll
        for (int ni=0;ni<8;ni++)
            #pragma unroll
            for (int c=0;c<4;c++) acc[mi][ni][c] = 0.f;

    for (int kt=0; kt<DM; kt+=32) {
        *(uint4*)&As[0][s0] = pAh0;  *(uint4*)&As[0][s1] = pAh1;
        *(uint4*)&As[1][s0] = pAl0;  *(uint4*)&As[1][s1] = pAl1;
        *(uint4*)&Bs[0][s0] = pBh0;  *(uint4*)&Bs[0][s1] = pBh1;
        *(uint4*)&Bs[1][s0] = pBl0;  *(uint4*)&Bs[1][s1] = pBl1;
        __syncthreads();
        if (kt + 32 < DM) {
            const int kn = kt + 32;
            pAh0 = *(const uint4*)&Ah[oA0 + kn];
            pAh1 = *(const uint4*)&Ah[oA1 + kn];
            pAl0 = *(const uint4*)&Al[oA0 + kn];
            pAl1 = *(const uint4*)&Al[oA1 + kn];
            pBh0 = *(const uint4*)&Wh[oB0 + kn];
            pBh1 = *(const uint4*)&Wh[oB1 + kn];
            pBl0 = *(const uint4*)&Wl[oB0 + kn];
            pBl1 = *(const uint4*)&Wl[oB1 + kn];
        }
        #pragma unroll
        for (int ks=0; ks<2; ++ks) {
            const int kb = ks*16 + tig*2;
            uint32_t ah[2][4], al[2][4];
            #pragma unroll
            for (int mi=0;mi<2;mi++) {
                const int row = wm*32 + mi*16 + grp;
                ah[mi][0] = *(const uint32_t*)&As[0][row*40     + kb];
                ah[mi][1] = *(const uint32_t*)&As[0][(row+8)*40 + kb];
                ah[mi][2] = *(const uint32_t*)&As[0][row*40     + kb + 8];
                ah[mi][3] = *(const uint32_t*)&As[0][(row+8)*40 + kb + 8];
                al[mi][0] = *(const uint32_t*)&As[1][row*40     + kb];
                al[mi][1] = *(const uint32_t*)&As[1][(row+8)*40 + kb];
                al[mi][2] = *(const uint32_t*)&As[1][row*40     + kb + 8];
                al[mi][3] = *(const uint32_t*)&As[1][(row+8)*40 + kb + 8];
            }
            #pragma unroll
            for (int ni=0;ni<8;ni++) {
                const int col = wn*64 + ni*8 + grp;
                const uint32_t bh0 = *(const uint32_t*)&Bs[0][col*40 + kb];
                const uint32_t bh1 = *(const uint32_t*)&Bs[0][col*40 + kb + 8];
                const uint32_t bl0 = *(const uint32_t*)&Bs[1][col*40 + kb];
                const uint32_t bl1 = *(const uint32_t*)&Bs[1][col*40 + kb + 8];
                #pragma unroll
                for (int mi=0;mi<2;mi++) {
                    MMA_BF16(acc[mi][ni], ah[mi], bh0, bh1);
                    MMA_BF16(acc[mi][ni], ah[mi], bl0, bl1);
                    MMA_BF16(acc[mi][ni], al[mi], bh0, bh1);
                }
            }
        }
        __syncthreads();
    }

    #pragma unroll
    for (int mi=0;mi<2;mi++) {
        #pragma unroll
        for (int ni=0;ni<8;ni++) {
            const int c = c0 + wn*64 + ni*8 + tig*2;
            const float b0v = bias[c], b1v = bias[c+1];
            #pragma unroll
            for (int hr=0;hr<2;hr++) {
                const int m = m0 + wm*32 + mi*16 + grp + hr*8;
                const float v0 = acc[mi][ni][hr*2+0] + b0v;
                const float v1 = acc[mi][ni][hr*2+1] + b1v;
                if (mode == 1) {
                    *(float2*)&out[(size_t)m*DM + c] = make_float2(v0, v1);
                } else {
                    const int t  = (c >= 1536) ? 2 : (c >= 768 ? 1 : 0);
                    const int rr = c - t*DM;
                    const int hh = rr >> 6, d = rr & 63;
                    const int b_ = m >> 10, n = m & 1023;
                    float* dst = (t==0) ? g_Q : (t==1) ? g_K : g_V;
                    *(float2*)&dst[((size_t)((b_*NH+hh)*NSEQ + n))*HD + d]
                        = make_float2(v0, v1);
                }
            }
        }
    }
}

// ---------------------------------------------------------------------------
// relh[bh,n,kh] = q[bh,n,:] . rel_pos_h[qh-kh+31,:],  relw analogous.
// ---------------------------------------------------------------------------
__global__ __launch_bounds__(256) void rel_kernel(
    const float* __restrict__ rph, const float* __restrict__ rpw)
{
    __shared__ float qs[4*64];
    const int blk = blockIdx.x;
    const int bh = blk >> 8, ng = blk & 255;
    const int tid = threadIdx.x, ln = tid >> 6, t = tid & 63;
    const int n = (ng << 2) + ln;
    qs[ln*64 + t] = g_Q[((size_t)(bh*NSEQ + n))*HD + t];
    __syncthreads();

    const int j = t & 31, half = t >> 5;
    const int qh = n >> 5, qw = n & 31;
    const float* tab = half ? rpw : rph;
    const int ref = half ? qw : qh;
    const float4* row = (const float4*)&tab[(ref - j + 31)*HD];
    const float4* q4  = (const float4*)&qs[ln*64];
    float a = 0.f;
    #pragma unroll
    for (int d4=0; d4<16; ++d4) {
        float4 rr = row[d4], qq = q4[d4];
        a += rr.x*qq.x + rr.y*qq.y + rr.z*qq.z + rr.w*qq.w;
    }
    float* dst = half ? g_relw : g_relh;
    dst[((size_t)(bh*NSEQ + n))*32 + j] = a;
}

// ---------------------------------------------------------------------------
__global__ void vsum_kernel()
{
    __shared__ float red[256];
    const int bh = blockIdx.x, tid = threadIdx.x;
    const int d = tid & 63, part = tid >> 6;
    float s = 0.f;
    for (int k = part*256; k < part*256 + 256; ++k)
        s += g_V[((size_t)(bh*NSEQ + k))*HD + d];
    red[tid] = s;
    __syncthreads();
    if (tid < 64)
        g_vsum[bh*HD + tid] = red[tid] + red[tid+64] + red[tid+128] + red[tid+192];
}

// ---------------------------------------------------------------------------
// Fused flash attention (fp32) — epilogue now emits bf16 hi/lo for proj GEMM.
// ---------------------------------------------------------------------------
#define FLASH_SMEM_FLOATS (128*68*3 + 128*129 + 128*32 + 128*4 + 128)
#define FLASH_SMEM_BYTES  (FLASH_SMEM_FLOATS*4)

__global__ __launch_bounds__(256,1) void flash_kernel(const float* __restrict__ policy)
{
    extern __shared__ float sm[];
    float* Qs    = sm;
    float* Ks    = Qs   + 128*68;
    float* Vs    = Ks   + 128*68;
    float* Ps    = Vs   + 128*68;
    float* rw_s  = Ps   + 128*129;
    float* rh_s  = rw_s + 128*32;
    float* pol_s = rh_s + 128*4;

    const int bh = blockIdx.y, q0 = blockIdx.x << 7;
    const int b_ = bh / NH, hh = bh - b_*NH;
    const int tid = threadIdx.x, tx = tid & 15, ty = tid >> 4;

    #pragma unroll
    for (int it=0; it<8; ++it) {
        int idx = it*256 + tid, mrow = idx >> 4, d4 = idx & 15;
        *(float4*)&Qs[mrow*68 + (d4<<2)] =
            *(const float4*)&g_Q[((size_t)(bh*NSEQ + q0 + mrow))*HD + (d4<<2)];
    }
    #pragma unroll
    for (int it=0; it<4; ++it) {
        int idx = it*256 + tid, mrow = idx >> 3, w4 = idx & 7;
        *(float4*)&rw_s[mrow*32 + (w4<<2)] =
            *(const float4*)&g_relw[((size_t)(bh*NSEQ + q0 + mrow))*32 + (w4<<2)];
    }

    float m[8], l[8], oa[8][4];
    #pragma unroll
    for (int i=0;i<8;i++) {
        m[i] = -CUDART_INF_F; l[i] = 0.f;
        oa[i][0]=oa[i][1]=oa[i][2]=oa[i][3]=0.f;
    }

    for (int k0=0; k0<NSEQ; k0+=128) {
        __syncthreads();
        #pragma unroll
        for (int it=0; it<8; ++it) {
            int idx = it*256 + tid, mrow = idx >> 4, d4 = idx & 15;
            *(float4*)&Ks[mrow*68 + (d4<<2)] =
                *(const float4*)&g_K[((size_t)(bh*NSEQ + k0 + mrow))*HD + (d4<<2)];
            *(float4*)&Vs[mrow*68 + (d4<<2)] =
                *(const float4*)&g_V[((size_t)(bh*NSEQ + k0 + mrow))*HD + (d4<<2)];
        }
        if (tid < 128) {
            *(float4*)&rh_s[tid*4] =
                *(const float4*)&g_relh[((size_t)(bh*NSEQ + q0 + tid))*32 + (k0>>5)];
            pol_s[tid] = policy[(b_<<10) + k0 + tid];
        }
        __syncthreads();

        float acc[8][8];
        #pragma unroll
        for (int i=0;i<8;i++)
            #pragma unroll
            for (int j=0;j<8;j++) acc[i][j] = 0.f;

        #pragma unroll
        for (int kk=0; kk<16; ++kk) {
            float4 a[8];
            #pragma unroll
            for (int i=0;i<8;i++) a[i] = *(const float4*)&Qs[(ty*8+i)*68 + (kk<<2)];
            #pragma unroll
            for (int j=0;j<8;j++) {
                float4 b = *(const float4*)&Ks[(tx + j*16)*68 + (kk<<2)];
                #pragma unroll
                for (int i=0;i<8;i++) {
                    acc[i][j] = fmaf(a[i].x, b.x, acc[i][j]);
                    acc[i][j] = fmaf(a[i].y, b.y, acc[i][j]);
                    acc[i][j] = fmaf(a[i].z, b.z, acc[i][j]);
                    acc[i][j] = fmaf(a[i].w, b.w, acc[i][j]);
                }
            }
        }

        #pragma unroll
        for (int i=0;i<8;i++) {
            const int r = ty*8 + i, qg = q0 + r;
            float tmax = -CUDART_INF_F;
            #pragma unroll
            for (int j=0;j<8;j++) {
                float s = acc[i][j]*SCALE + rh_s[r*4 + (j>>1)]
                        + rw_s[r*32 + ((j&1)<<4) + tx];
                acc[i][j] = s;
                tmax = fmaxf(tmax, s);
            }
            #pragma unroll
            for (int o_=1;o_<16;o_<<=1)
                tmax = fmaxf(tmax, __shfl_xor_sync(0xffffffffu, tmax, o_));
            const float mnew = fmaxf(m[i], tmax);
            const float f = __expf(m[i] - mnew);
            m[i] = mnew;
            float rs = 0.f;
            #pragma unroll
            for (int j=0;j<8;j++) {
                const int c = tx + j*16;
                const int kg = k0 + c;
                const float ap = (kg == qg) ? 1.f : pol_s[c];
                const float e = __expf(acc[i][j] - mnew) * ap;
                rs += e;
                Ps[r*129 + c] = e;
            }
            #pragma unroll
            for (int o_=1;o_<16;o_<<=1)
                rs += __shfl_xor_sync(0xffffffffu, rs, o_);
            l[i] = l[i]*f + rs;
            oa[i][0]*=f; oa[i][1]*=f; oa[i][2]*=f; oa[i][3]*=f;
        }
        __syncthreads();

        #pragma unroll 4
        for (int c=0; c<128; ++c) {
            const float4 vv = *(const float4*)&Vs[c*68 + (tx<<2)];
            #pragma unroll
            for (int i=0;i<8;i++) {
                const float p = Ps[(ty*8+i)*129 + c];
                oa[i][0] = fmaf(p, vv.x, oa[i][0]);
                oa[i][1] = fmaf(p, vv.y, oa[i][1]);
                oa[i][2] = fmaf(p, vv.z, oa[i][2]);
                oa[i][3] = fmaf(p, vv.w, oa[i][3]);
            }
        }
    }

    // epilogue: out = (o + EPSN*vsum) / (l + EPSV), split to bf16 hi/lo
    const float4 vs4 = *(const float4*)&g_vsum[bh*HD + (tx<<2)];
    #pragma unroll
    for (int i=0;i<8;i++) {
        const int r = ty*8 + i;
        const float inv = 1.f / (l[i] + EPSV);
        float o[4];
        o[0] = (oa[i][0] + EPSN*vs4.x) * inv;
        o[1] = (oa[i][1] + EPSN*vs4.y) * inv;
        o[2] = (oa[i][2] + EPSN*vs4.z) * inv;
        o[3] = (oa[i][3] + EPSN*vs4.w) * inv;
        const size_t base = ((size_t)(b_*NSEQ + q0 + r))*DM + hh*HD + (tx<<2);
        __nv_bfloat16 h0 = __float2bfloat16(o[0]), h1 = __float2bfloat16(o[1]);
        __nv_bfloat16 h2 = __float2bfloat16(o[2]), h3 = __float2bfloat16(o[3]);
        __nv_bfloat162 hp0; hp0.x = h0; hp0.y = h1;
        __nv_bfloat162 hp1; hp1.x = h2; hp1.y = h3;
        __nv_bfloat162 lp0, lp1;
        lp0.x = __float2bfloat16(o[0] - __bfloat162float(h0));
        lp0.y = __float2bfloat16(o[1] - __bfloat162float(h1));
        lp1.x = __float2bfloat16(o[2] - __bfloat162float(h2));
        lp1.y = __float2bfloat16(o[3] - __bfloat162float(h3));
        *(__nv_bfloat162*)&g_Thi[base]   = hp0;
        *(__nv_bfloat162*)&g_Thi[base+2] = hp1;
        *(__nv_bfloat162*)&g_Tlo[base]   = lp0;
        *(__nv_bfloat162*)&g_Tlo[base+2] = lp1;
    }
}

// ---------------------------------------------------------------------------
extern "C" void kernel_launch(void* const* d_in, const int* in_sizes, int n_in,
                              void* d_out, int out_size)
{
    const float* x      = (const float*)d_in[0];
    const float* policy = (const float*)d_in[1];
    const float* qkv_w  = (const float*)d_in[2];
    const float* qkv_b  = (const float*)d_in[3];
    const float* proj_w = (const float*)d_in[4];
    const float* proj_b = (const float*)d_in[5];
    const float* rph    = (const float*)d_in[6];
    const float* rpw    = (const float*)d_in[7];
    float* out = (float*)d_out;

    cudaFuncSetAttribute(flash_kernel,
        cudaFuncAttributeMaxDynamicSharedMemorySize, FLASH_SMEM_BYTES);

    const int n4x = NB*NSEQ*DM/4, n4q = 2304*DM/4, n4p = DM*DM/4;
    split_kernel<<<(n4x+255)/256,256>>>(x,      0, n4x);
    split_kernel<<<(n4q+255)/256,256>>>(qkv_w,  1, n4q);
    split_kernel<<<(n4p+255)/256,256>>>(proj_w, 2, n4p);

    gemm_mma<<<dim3(18,64),256>>>(qkv_b, nullptr, 0);
    rel_kernel<<<NBH*256,256>>>(rph, rpw);
    vsum_kernel<<<NBH,256>>>();
    flash_kernel<<<dim3(8,NBH),256,FLASH_SMEM_BYTES>>>(policy);
    gemm_mma<<<dim3(6,64),256>>>(proj_b, out, 1);
}

// round 8
// speedup vs baseline: 1.6700x; 1.3036x over previous
#include <cuda_runtime.h>
#include <cuda_bf16.h>
#include <math_constants.h>
#include <cstddef>
#include <cstdint>

#define NB 8
#define NH 12
#define HD 64
#define DM 768
#define NSEQ 1024
#define NBH 96
#define SCALE 0.125f
#define EPSV 1e-6f
#define EPSN (1e-6f/1024.0f)
#define WOFF (2304*768)

__device__ float g_Q[NBH*NSEQ*HD];
__device__ float g_K[NBH*NSEQ*HD];
__device__ float g_V[NBH*NSEQ*HD];
__device__ float g_relh[NBH*NSEQ*32];
__device__ float g_relw[NBH*NSEQ*32];
__device__ float g_vsum[NBH*HD];

__device__ __nv_bfloat16 g_Xhi[NB*NSEQ*DM], g_Xlo[NB*NSEQ*DM];
__device__ __nv_bfloat16 g_Whi[3072*DM],    g_Wlo[3072*DM];
__device__ __nv_bfloat16 g_Thi[NB*NSEQ*DM], g_Tlo[NB*NSEQ*DM];

#define MMA_BF16(d, a, b0, b1)                                             \
  asm volatile("mma.sync.aligned.m16n8k16.row.col.f32.bf16.bf16.f32 "      \
    "{%0,%1,%2,%3},{%4,%5,%6,%7},{%8,%9},{%0,%1,%2,%3};\n"                 \
    : "+f"(d[0]), "+f"(d[1]), "+f"(d[2]), "+f"(d[3])                       \
    : "r"(a[0]), "r"(a[1]), "r"(a[2]), "r"(a[3]), "r"(b0), "r"(b1))

__device__ __forceinline__ void split2(float a, float b, uint32_t& hi, uint32_t& lo)
{
    __nv_bfloat162 h = __floats2bfloat162_rn(a, b);
    float ra = a - __bfloat162float(h.x);
    float rb = b - __bfloat162float(h.y);
    __nv_bfloat162 l = __floats2bfloat162_rn(ra, rb);
    hi = *(uint32_t*)&h;
    lo = *(uint32_t*)&l;
}

// ---------------------------------------------------------------------------
// split fp32 -> bf16 hi + bf16 lo.  which: 0 = x, 1 = qkv_w, 2 = proj_w
// ---------------------------------------------------------------------------
__global__ void split_kernel(const float* __restrict__ src, int which, int n4)
{
    int i = blockIdx.x*256 + threadIdx.x;
    if (i >= n4) return;
    __nv_bfloat16 *hi, *lo;
    if (which == 0)      { hi = g_Xhi;        lo = g_Xlo; }
    else if (which == 1) { hi = g_Whi;        lo = g_Wlo; }
    else                 { hi = g_Whi + WOFF; lo = g_Wlo + WOFF; }
    float4 v = ((const float4*)src)[i];
    uint32_t h0, l0, h1, l1;
    split2(v.x, v.y, h0, l0);
    split2(v.z, v.w, h1, l1);
    ((uint32_t*)hi)[i*2]   = h0;
    ((uint32_t*)hi)[i*2+1] = h1;
    ((uint32_t*)lo)[i*2]   = l0;
    ((uint32_t*)lo)[i*2+1] = l1;
}

// ---------------------------------------------------------------------------
// Tensor-core GEMM (bf16 split, fp32 accum) — unchanged from R5.
// ---------------------------------------------------------------------------
__global__ __launch_bounds__(256) void gemm_mma(
    const float* __restrict__ bias, float* __restrict__ out, int mode)
{
    __shared__ __nv_bfloat16 As[2][128*40];
    __shared__ __nv_bfloat16 Bs[2][128*40];
    const __nv_bfloat16* Ah = mode ? g_Thi : g_Xhi;
    const __nv_bfloat16* Al = mode ? g_Tlo : g_Xlo;
    const __nv_bfloat16* Wh = g_Whi + (mode ? WOFF : 0);
    const __nv_bfloat16* Wl = g_Wlo + (mode ? WOFF : 0);

    const int m0 = blockIdx.y*128, c0 = blockIdx.x*128;
    const int tid = threadIdx.x, lane = tid & 31, wid = tid >> 5;
    const int wm = wid & 3, wn = wid >> 2;
    const int grp = lane >> 2, tig = lane & 3;
    const int ra = tid >> 2, qa = tid & 3;

    const size_t oA0 = (size_t)(m0+ra)*DM    + qa*8;
    const size_t oA1 = (size_t)(m0+ra+64)*DM + qa*8;
    const size_t oB0 = (size_t)(c0+ra)*DM    + qa*8;
    const size_t oB1 = (size_t)(c0+ra+64)*DM + qa*8;
    const int s0 = ra*40 + qa*8, s1 = (ra+64)*40 + qa*8;

    uint4 pAh0 = *(const uint4*)&Ah[oA0];
    uint4 pAh1 = *(const uint4*)&Ah[oA1];
    uint4 pAl0 = *(const uint4*)&Al[oA0];
    uint4 pAl1 = *(const uint4*)&Al[oA1];
    uint4 pBh0 = *(const uint4*)&Wh[oB0];
    uint4 pBh1 = *(const uint4*)&Wh[oB1];
    uint4 pBl0 = *(const uint4*)&Wl[oB0];
    uint4 pBl1 = *(const uint4*)&Wl[oB1];

    float acc[2][8][4];
    #pragma unroll
    for (int mi=0;mi<2;mi++)
        #pragma unroll
        for (int ni=0;ni<8;ni++)
            #pragma unroll
            for (int c=0;c<4;c++) acc[mi][ni][c] = 0.f;

    for (int kt=0; kt<DM; kt+=32) {
        *(uint4*)&As[0][s0] = pAh0;  *(uint4*)&As[0][s1] = pAh1;
        *(uint4*)&As[1][s0] = pAl0;  *(uint4*)&As[1][s1] = pAl1;
        *(uint4*)&Bs[0][s0] = pBh0;  *(uint4*)&Bs[0][s1] = pBh1;
        *(uint4*)&Bs[1][s0] = pBl0;  *(uint4*)&Bs[1][s1] = pBl1;
        __syncthreads();
        if (kt + 32 < DM) {
            const int kn = kt + 32;
            pAh0 = *(const uint4*)&Ah[oA0 + kn];
            pAh1 = *(const uint4*)&Ah[oA1 + kn];
            pAl0 = *(const uint4*)&Al[oA0 + kn];
            pAl1 = *(const uint4*)&Al[oA1 + kn];
            pBh0 = *(const uint4*)&Wh[oB0 + kn];
            pBh1 = *(const uint4*)&Wh[oB1 + kn];
            pBl0 = *(const uint4*)&Wl[oB0 + kn];
            pBl1 = *(const uint4*)&Wl[oB1 + kn];
        }
        #pragma unroll
        for (int ks=0; ks<2; ++ks) {
            const int kb = ks*16 + tig*2;
            uint32_t ah[2][4], al[2][4];
            #pragma unroll
            for (int mi=0;mi<2;mi++) {
                const int row = wm*32 + mi*16 + grp;
                ah[mi][0] = *(const uint32_t*)&As[0][row*40     + kb];
                ah[mi][1] = *(const uint32_t*)&As[0][(row+8)*40 + kb];
                ah[mi][2] = *(const uint32_t*)&As[0][row*40     + kb + 8];
                ah[mi][3] = *(const uint32_t*)&As[0][(row+8)*40 + kb + 8];
                al[mi][0] = *(const uint32_t*)&As[1][row*40     + kb];
                al[mi][1] = *(const uint32_t*)&As[1][(row+8)*40 + kb];
                al[mi][2] = *(const uint32_t*)&As[1][row*40     + kb + 8];
                al[mi][3] = *(const uint32_t*)&As[1][(row+8)*40 + kb + 8];
            }
            #pragma unroll
            for (int ni=0;ni<8;ni++) {
                const int col = wn*64 + ni*8 + grp;
                const uint32_t bh0 = *(const uint32_t*)&Bs[0][col*40 + kb];
                const uint32_t bh1 = *(const uint32_t*)&Bs[0][col*40 + kb + 8];
                const uint32_t bl0 = *(const uint32_t*)&Bs[1][col*40 + kb];
                const uint32_t bl1 = *(const uint32_t*)&Bs[1][col*40 + kb + 8];
                #pragma unroll
                for (int mi=0;mi<2;mi++) {
                    MMA_BF16(acc[mi][ni], ah[mi], bh0, bh1);
                    MMA_BF16(acc[mi][ni], ah[mi], bl0, bl1);
                    MMA_BF16(acc[mi][ni], al[mi], bh0, bh1);
                }
            }
        }
        __syncthreads();
    }

    #pragma unroll
    for (int mi=0;mi<2;mi++) {
        #pragma unroll
        for (int ni=0;ni<8;ni++) {
            const int c = c0 + wn*64 + ni*8 + tig*2;
            const float b0v = bias[c], b1v = bias[c+1];
            #pragma unroll
            for (int hr=0;hr<2;hr++) {
                const int m = m0 + wm*32 + mi*16 + grp + hr*8;
                const float v0 = acc[mi][ni][hr*2+0] + b0v;
                const float v1 = acc[mi][ni][hr*2+1] + b1v;
                if (mode == 1) {
                    *(float2*)&out[(size_t)m*DM + c] = make_float2(v0, v1);
                } else {
                    const int t  = (c >= 1536) ? 2 : (c >= 768 ? 1 : 0);
                    const int rr = c - t*DM;
                    const int hh = rr >> 6, d = rr & 63;
                    const int b_ = m >> 10, n = m & 1023;
                    float* dst = (t==0) ? g_Q : (t==1) ? g_K : g_V;
                    *(float2*)&dst[((size_t)((b_*NH+hh)*NSEQ + n))*HD + d]
                        = make_float2(v0, v1);
                }
            }
        }
    }
}

// ---------------------------------------------------------------------------
__global__ __launch_bounds__(256) void rel_kernel(
    const float* __restrict__ rph, const float* __restrict__ rpw)
{
    __shared__ float qs[4*64];
    const int blk = blockIdx.x;
    const int bh = blk >> 8, ng = blk & 255;
    const int tid = threadIdx.x, ln = tid >> 6, t = tid & 63;
    const int n = (ng << 2) + ln;
    qs[ln*64 + t] = g_Q[((size_t)(bh*NSEQ + n))*HD + t];
    __syncthreads();

    const int j = t & 31, half = t >> 5;
    const int qh = n >> 5, qw = n & 31;
    const float* tab = half ? rpw : rph;
    const int ref = half ? qw : qh;
    const float4* row = (const float4*)&tab[(ref - j + 31)*HD];
    const float4* q4  = (const float4*)&qs[ln*64];
    float a = 0.f;
    #pragma unroll
    for (int d4=0; d4<16; ++d4) {
        float4 rr = row[d4], qq = q4[d4];
        a += rr.x*qq.x + rr.y*qq.y + rr.z*qq.z + rr.w*qq.w;
    }
    float* dst = half ? g_relw : g_relh;
    dst[((size_t)(bh*NSEQ + n))*32 + j] = a;
}

// ---------------------------------------------------------------------------
__global__ void vsum_kernel()
{
    __shared__ float red[256];
    const int bh = blockIdx.x, tid = threadIdx.x;
    const int d = tid & 63, part = tid >> 6;
    float s = 0.f;
    for (int k = part*256; k < part*256 + 256; ++k)
        s += g_V[((size_t)(bh*NSEQ + k))*HD + d];
    red[tid] = s;
    __syncthreads();
    if (tid < 64)
        g_vsum[bh*HD + tid] = red[tid] + red[tid+64] + red[tid+128] + red[tid+192];
}

// ---------------------------------------------------------------------------
// Flash attention on tensor cores (bf16 hi/lo 3-MMA split, fp32 softmax).
// CTA = (q-tile 128, bh), 8 warps, warp owns 16 q rows.
// S C-fragment re-packed in registers as A-fragment of P.V (flash-2 trick).
// ---------------------------------------------------------------------------
#define QKS 72
#define VTS 136
#define FL_SMEM_BYTES (4*128*QKS*2 + 2*64*VTS*2 + 128*33*4 + 128*4)

__global__ __launch_bounds__(256,1) void flash_mma(const float* __restrict__ policy)
{
    extern __shared__ char smraw[];
    __nv_bfloat16* Qh  = (__nv_bfloat16*)smraw;
    __nv_bfloat16* Ql  = Qh  + 128*QKS;
    __nv_bfloat16* Kh  = Ql  + 128*QKS;
    __nv_bfloat16* Kl  = Kh  + 128*QKS;
    __nv_bfloat16* Vth = Kl  + 128*QKS;
    __nv_bfloat16* Vtl = Vth + 64*VTS;
    float* rw_s  = (float*)(Vtl + 64*VTS);
    float* pol_s = rw_s + 128*33;

    const int bh = blockIdx.y, q0 = blockIdx.x << 7;
    const int b_ = bh / NH, hh = bh - b_*NH;
    const int tid = threadIdx.x, lane = tid & 31, w = tid >> 5;
    const int grp = lane >> 2, tig = lane & 3;
    const int r0 = w*16 + grp, r1 = r0 + 8;
    const int qg0 = q0 + r0, qg1 = q0 + r1;

    // ---- Q tile -> bf16 hi/lo smem (once)
    #pragma unroll
    for (int it=0; it<8; ++it) {
        int idx = it*256 + tid, mrow = idx >> 4, d4 = idx & 15;
        float4 v = *(const float4*)&g_Q[((size_t)(bh*NSEQ + q0 + mrow))*HD + (d4<<2)];
        uint32_t h0,l0,h1,l1;
        split2(v.x, v.y, h0, l0);
        split2(v.z, v.w, h1, l1);
        *(uint32_t*)&Qh[mrow*QKS + (d4<<2)]     = h0;
        *(uint32_t*)&Qh[mrow*QKS + (d4<<2) + 2] = h1;
        *(uint32_t*)&Ql[mrow*QKS + (d4<<2)]     = l0;
        *(uint32_t*)&Ql[mrow*QKS + (d4<<2) + 2] = l1;
    }
    // ---- rw (once), padded stride 33
    for (int idx = tid; idx < 128*32; idx += 256) {
        int r = idx >> 5, c = idx & 31;
        rw_s[r*33 + c] = g_relw[((size_t)(bh*NSEQ + q0 + r))*32 + c];
    }

    float m0 = -CUDART_INF_F, m1 = -CUDART_INF_F, l0v = 0.f, l1v = 0.f;
    float o[8][4];
    #pragma unroll
    for (int nd=0; nd<8; ++nd) { o[nd][0]=o[nd][1]=o[nd][2]=o[nd][3]=0.f; }

    for (int k0=0; k0<NSEQ; k0+=128) {
        __syncthreads();
        // ---- K tile -> bf16 hi/lo
        #pragma unroll
        for (int it=0; it<8; ++it) {
            int idx = it*256 + tid, krow = idx >> 4, d4 = idx & 15;
            float4 v = *(const float4*)&g_K[((size_t)(bh*NSEQ + k0 + krow))*HD + (d4<<2)];
            uint32_t h0,l0,h1,l1;
            split2(v.x, v.y, h0, l0);
            split2(v.z, v.w, h1, l1);
            *(uint32_t*)&Kh[krow*QKS + (d4<<2)]     = h0;
            *(uint32_t*)&Kh[krow*QKS + (d4<<2) + 2] = h1;
            *(uint32_t*)&Kl[krow*QKS + (d4<<2)]     = l0;
            *(uint32_t*)&Kl[krow*QKS + (d4<<2) + 2] = l1;
        }
        // ---- V tile -> transposed bf16 hi/lo  Vt[d][k]
        #pragma unroll
        for (int it=0; it<8; ++it) {
            int idx = it*256 + tid, krow = idx >> 4, d4 = idx & 15;
            float4 v = *(const float4*)&g_V[((size_t)(bh*NSEQ + k0 + krow))*HD + (d4<<2)];
            #pragma unroll
            for (int e=0; e<4; ++e) {
                float f = (e==0)?v.x:(e==1)?v.y:(e==2)?v.z:v.w;
                __nv_bfloat16 hb = __float2bfloat16(f);
                Vth[((d4<<2)+e)*VTS + krow] = hb;
                Vtl[((d4<<2)+e)*VTS + krow] = __float2bfloat16(f - __bfloat162float(hb));
            }
        }
        if (tid < 128) pol_s[tid] = policy[(b_<<10) + k0 + tid];
        __syncthreads();

        // rel_h values for this k-tile (4 per row)
        float4 rh0 = *(const float4*)&g_relh[((size_t)(bh*NSEQ + q0 + r0))*32 + (k0>>5)];
        float4 rh1 = *(const float4*)&g_relh[((size_t)(bh*NSEQ + q0 + r1))*32 + (k0>>5)];

        // ---- S = Q.K^T (3-MMA bf16 split, fp32 accum)
        float acc[16][4];
        #pragma unroll
        for (int jb=0; jb<16; ++jb) { acc[jb][0]=acc[jb][1]=acc[jb][2]=acc[jb][3]=0.f; }

        #pragma unroll
        for (int kb=0; kb<4; ++kb) {
            const int kk = kb*16 + tig*2;
            uint32_t qhf[4], qlf[4];
            qhf[0] = *(const uint32_t*)&Qh[r0*QKS + kk];
            qhf[1] = *(const uint32_t*)&Qh[r1*QKS + kk];
            qhf[2] = *(const uint32_t*)&Qh[r0*QKS + kk + 8];
            qhf[3] = *(const uint32_t*)&Qh[r1*QKS + kk + 8];
            qlf[0] = *(const uint32_t*)&Ql[r0*QKS + kk];
            qlf[1] = *(const uint32_t*)&Ql[r1*QKS + kk];
            qlf[2] = *(const uint32_t*)&Ql[r0*QKS + kk + 8];
            qlf[3] = *(const uint32_t*)&Ql[r1*QKS + kk + 8];
            #pragma unroll
            for (int jb=0; jb<16; ++jb) {
                const int col = jb*8 + grp;
                const uint32_t kh0 = *(const uint32_t*)&Kh[col*QKS + kk];
                const uint32_t kh1 = *(const uint32_t*)&Kh[col*QKS + kk + 8];
                const uint32_t kl0 = *(const uint32_t*)&Kl[col*QKS + kk];
                const uint32_t kl1 = *(const uint32_t*)&Kl[col*QKS + kk + 8];
                MMA_BF16(acc[jb], qhf, kh0, kh1);
                MMA_BF16(acc[jb], qhf, kl0, kl1);
                MMA_BF16(acc[jb], qlf, kh0, kh1);
            }
        }

        // ---- bias + row max (over full 128 cols, BEFORE mask — as reference)
        float tmax0 = -CUDART_INF_F, tmax1 = -CUDART_INF_F;
        #pragma unroll
        for (int jb=0; jb<16; ++jb) {
            const float rh0v = (jb<4)?((jb&3)==0?rh0.x:(jb&3)==1?rh0.y:(jb&3)==2?rh0.z:rh0.w)
                              : (jb<8)?(((jb&3)==0)?rh0.y:rh0.y) : 0.f; // placeholder (replaced below)
            (void)rh0v;
            const int kh = jb >> 2;
            const float rhv0 = (kh==0)?rh0.x:(kh==1)?rh0.y:(kh==2)?rh0.z:rh0.w;
            const float rhv1 = (kh==0)?rh1.x:(kh==1)?rh1.y:(kh==2)?rh1.z:rh1.w;
            const int cw = ((jb & 3) << 3) + (tig << 1);
            acc[jb][0] = acc[jb][0]*SCALE + rhv0 + rw_s[r0*33 + cw];
            acc[jb][1] = acc[jb][1]*SCALE + rhv0 + rw_s[r0*33 + cw + 1];
            acc[jb][2] = acc[jb][2]*SCALE + rhv1 + rw_s[r1*33 + cw];
            acc[jb][3] = acc[jb][3]*SCALE + rhv1 + rw_s[r1*33 + cw + 1];
            tmax0 = fmaxf(tmax0, fmaxf(acc[jb][0], acc[jb][1]));
            tmax1 = fmaxf(tmax1, fmaxf(acc[jb][2], acc[jb][3]));
        }
        tmax0 = fmaxf(tmax0, __shfl_xor_sync(0xffffffffu, tmax0, 1));
        tmax0 = fmaxf(tmax0, __shfl_xor_sync(0xffffffffu, tmax0, 2));
        tmax1 = fmaxf(tmax1, __shfl_xor_sync(0xffffffffu, tmax1, 1));
        tmax1 = fmaxf(tmax1, __shfl_xor_sync(0xffffffffu, tmax1, 2));

        const float mn0 = fmaxf(m0, tmax0);
        const float mn1 = fmaxf(m1, tmax1);
        const float f0 = __expf(m0 - mn0);
        const float f1 = __expf(m1 - mn1);
        m0 = mn0; m1 = mn1;
        #pragma unroll
        for (int nd=0; nd<8; ++nd) {
            o[nd][0]*=f0; o[nd][1]*=f0; o[nd][2]*=f1; o[nd][3]*=f1;
        }

        float rs0 = 0.f, rs1 = 0.f;
        // ---- two halves of 64 keys: exp + pack + PV MMAs
        #pragma unroll
        for (int half=0; half<2; ++half) {
            uint32_t pha[8], phb[8], pla[8], plb[8];
            #pragma unroll
            for (int j=0; j<8; ++j) {
                const int jb = half*8 + j;
                const int cb = (jb<<3) + (tig<<1);
                const int kg = k0 + cb;
                const float ap00 = (kg   == qg0) ? 1.f : pol_s[cb];
                const float ap01 = (kg+1 == qg0) ? 1.f : pol_s[cb+1];
                const float ap10 = (kg   == qg1) ? 1.f : pol_s[cb];
                const float ap11 = (kg+1 == qg1) ? 1.f : pol_s[cb+1];
                const float e00 = __expf(acc[jb][0] - mn0) * ap00;
                const float e01 = __expf(acc[jb][1] - mn0) * ap01;
                const float e10 = __expf(acc[jb][2] - mn1) * ap10;
                const float e11 = __expf(acc[jb][3] - mn1) * ap11;
                rs0 += e00 + e01;
                rs1 += e10 + e11;
                split2(e00, e01, pha[j], pla[j]);
                split2(e10, e11, phb[j], plb[j]);
            }
            #pragma unroll
            for (int j2=0; j2<4; ++j2) {
                const int g = half*4 + j2;
                uint32_t ahi[4] = { pha[j2*2], phb[j2*2], pha[j2*2+1], phb[j2*2+1] };
                uint32_t alo[4] = { pla[j2*2], plb[j2*2], pla[j2*2+1], plb[j2*2+1] };
                #pragma unroll
                for (int nd=0; nd<8; ++nd) {
                    const int dcol = nd*8 + grp;
                    const uint32_t vh0 = *(const uint32_t*)&Vth[dcol*VTS + g*16 + tig*2];
                    const uint32_t vh1 = *(const uint32_t*)&Vth[dcol*VTS + g*16 + tig*2 + 8];
                    const uint32_t vl0 = *(const uint32_t*)&Vtl[dcol*VTS + g*16 + tig*2];
                    const uint32_t vl1 = *(const uint32_t*)&Vtl[dcol*VTS + g*16 + tig*2 + 8];
                    MMA_BF16(o[nd], ahi, vh0, vh1);
                    MMA_BF16(o[nd], ahi, vl0, vl1);
                    MMA_BF16(o[nd], alo, vh0, vh1);
                }
            }
        }
        rs0 += __shfl_xor_sync(0xffffffffu, rs0, 1);
        rs0 += __shfl_xor_sync(0xffffffffu, rs0, 2);
        rs1 += __shfl_xor_sync(0xffffffffu, rs1, 1);
        rs1 += __shfl_xor_sync(0xffffffffu, rs1, 2);
        l0v = l0v*f0 + rs0;
        l1v = l1v*f1 + rs1;
    }

    // ---- epilogue: out = (o + EPSN*vsum)/(l + EPSV), split bf16 hi/lo
    const float inv0 = 1.f / (l0v + EPSV);
    const float inv1 = 1.f / (l1v + EPSV);
    #pragma unroll
    for (int nd=0; nd<8; ++nd) {
        const int d = nd*8 + tig*2;
        const float2 vs = *(const float2*)&g_vsum[bh*HD + d];
        const float a0 = (o[nd][0] + EPSN*vs.x) * inv0;
        const float a1 = (o[nd][1] + EPSN*vs.y) * inv0;
        const float a2 = (o[nd][2] + EPSN*vs.x) * inv1;
        const float a3 = (o[nd][3] + EPSN*vs.y) * inv1;
        uint32_t h0,l0,h1,l1;
        split2(a0, a1, h0, l0);
        split2(a2, a3, h1, l1);
        const size_t base0 = ((size_t)(b_*NSEQ + qg0 - q0 + q0))*DM; // = (b_*NSEQ+qg0)*DM
        const size_t base1 = ((size_t)(b_*NSEQ + qg1))*DM;
        *(uint32_t*)&g_Thi[((size_t)(b_*NSEQ + qg0))*DM + hh*HD + d] = h0;
        *(uint32_t*)&g_Tlo[((size_t)(b_*NSEQ + qg0))*DM + hh*HD + d] = l0;
        *(uint32_t*)&g_Thi[base1 + hh*HD + d] = h1;
        *(uint32_t*)&g_Tlo[base1 + hh*HD + d] = l1;
        (void)base0;
    }
}

// ---------------------------------------------------------------------------
extern "C" void kernel_launch(void* const* d_in, const int* in_sizes, int n_in,
                              void* d_out, int out_size)
{
    const float* x      = (const float*)d_in[0];
    const float* policy = (const float*)d_in[1];
    const float* qkv_w  = (const float*)d_in[2];
    const float* qkv_b  = (const float*)d_in[3];
    const float* proj_w = (const float*)d_in[4];
    const float* proj_b = (const float*)d_in[5];
    const float* rph    = (const float*)d_in[6];
    const float* rpw    = (const float*)d_in[7];
    float* out = (float*)d_out;

    cudaFuncSetAttribute(flash_mma,
        cudaFuncAttributeMaxDynamicSharedMemorySize, FL_SMEM_BYTES);

    const int n4x = NB*NSEQ*DM/4, n4q = 2304*DM/4, n4p = DM*DM/4;
    split_kernel<<<(n4x+255)/256,256>>>(x,      0, n4x);
    split_kernel<<<(n4q+255)/256,256>>>(qkv_w,  1, n4q);
    split_kernel<<<(n4p+255)/256,256>>>(proj_w, 2, n4p);

    gemm_mma<<<dim3(18,64),256>>>(qkv_b, nullptr, 0);
    rel_kernel<<<NBH*256,256>>>(rph, rpw);
    vsum_kernel<<<NBH,256>>>();
    flash_mma<<<dim3(8,NBH),256,FL_SMEM_BYTES>>>(policy);
    gemm_mma<<<dim3(6,64),256>>>(proj_b, out, 1);
}

// round 9
// speedup vs baseline: 1.8281x; 1.0947x over previous
#include <cuda_runtime.h>
#include <cuda_bf16.h>
#include <math_constants.h>
#include <cstddef>
#include <cstdint>

#define NB 8
#define NH 12
#define HD 64
#define DM 768
#define NSEQ 1024
#define NBH 96
#define SCALE 0.125f
#define EPSV 1e-6f
#define EPSN (1e-6f/1024.0f)
#define WOFF (2304*768)

__device__ float g_Q[NBH*NSEQ*HD];
__device__ float g_V[NBH*NSEQ*HD];
__device__ float g_relh[NBH*NSEQ*32];
__device__ float g_relw[NBH*NSEQ*32];
__device__ float g_vsum[NBH*HD];

__device__ __nv_bfloat16 g_Xhi[NB*NSEQ*DM], g_Xlo[NB*NSEQ*DM];
__device__ __nv_bfloat16 g_Whi[3072*DM],    g_Wlo[3072*DM];
__device__ __nv_bfloat16 g_Thi[NB*NSEQ*DM], g_Tlo[NB*NSEQ*DM];

// bf16 hi/lo operands for flash (written by gemm epilogue / vtrans)
__device__ __nv_bfloat16 g_Qhi[NBH*NSEQ*HD], g_Qlo[NBH*NSEQ*HD];
__device__ __nv_bfloat16 g_Khi[NBH*NSEQ*HD], g_Klo[NBH*NSEQ*HD];
__device__ __nv_bfloat16 g_VThi[NBH*HD*NSEQ], g_VTlo[NBH*HD*NSEQ];  // [bh][d][k]

#define MMA_BF16(d, a, b0, b1)                                             \
  asm volatile("mma.sync.aligned.m16n8k16.row.col.f32.bf16.bf16.f32 "      \
    "{%0,%1,%2,%3},{%4,%5,%6,%7},{%8,%9},{%0,%1,%2,%3};\n"                 \
    : "+f"(d[0]), "+f"(d[1]), "+f"(d[2]), "+f"(d[3])                       \
    : "r"(a[0]), "r"(a[1]), "r"(a[2]), "r"(a[3]), "r"(b0), "r"(b1))

__device__ __forceinline__ void split2(float a, float b, uint32_t& hi, uint32_t& lo)
{
    __nv_bfloat162 h = __floats2bfloat162_rn(a, b);
    float ra = a - __bfloat162float(h.x);
    float rb = b - __bfloat162float(h.y);
    __nv_bfloat162 l = __floats2bfloat162_rn(ra, rb);
    hi = *(uint32_t*)&h;
    lo = *(uint32_t*)&l;
}

__device__ __forceinline__ void cp16(void* smem, const void* gmem)
{
    uint32_t s = (uint32_t)__cvta_generic_to_shared(smem);
    asm volatile("cp.async.cg.shared.global [%0], [%1], 16;\n" :: "r"(s), "l"(gmem));
}
__device__ __forceinline__ void cp_commit()
{
    asm volatile("cp.async.commit_group;\n");
}
template<int N> __device__ __forceinline__ void cp_wait()
{
    asm volatile("cp.async.wait_group %0;\n" :: "n"(N));
}

// ---------------------------------------------------------------------------
// split fp32 -> bf16 hi + bf16 lo.  which: 0 = x, 1 = qkv_w, 2 = proj_w
// ---------------------------------------------------------------------------
__global__ void split_kernel(const float* __restrict__ src, int which, int n4)
{
    int i = blockIdx.x*256 + threadIdx.x;
    if (i >= n4) return;
    __nv_bfloat16 *hi, *lo;
    if (which == 0)      { hi = g_Xhi;        lo = g_Xlo; }
    else if (which == 1) { hi = g_Whi;        lo = g_Wlo; }
    else                 { hi = g_Whi + WOFF; lo = g_Wlo + WOFF; }
    float4 v = ((const float4*)src)[i];
    uint32_t h0, l0, h1, l1;
    split2(v.x, v.y, h0, l0);
    split2(v.z, v.w, h1, l1);
    ((uint32_t*)hi)[i*2]   = h0;
    ((uint32_t*)hi)[i*2+1] = h1;
    ((uint32_t*)lo)[i*2]   = l0;
    ((uint32_t*)lo)[i*2+1] = l1;
}

// ---------------------------------------------------------------------------
// Tensor-core GEMM, cp.async double-buffered, 2 CTAs/SM.
// mode 0: QKV -> Q: fp32 + bf16 hi/lo, K: bf16 hi/lo, V: fp32. mode 1: proj.
// ---------------------------------------------------------------------------
#define GSTRIDE 5120            // 128*40 bf16 per (stage, hl) plane
#define GEMM_SMEM_BYTES (2*2*GSTRIDE*2*2*2)   // A + B, 2 stages, 2 hl = 81920

__global__ __launch_bounds__(256,2) void gemm_mma(
    const float* __restrict__ bias, float* __restrict__ out, int mode)
{
    extern __shared__ __nv_bfloat16 smg[];
    __nv_bfloat16* As = smg;                     // [(stage*2+hl)][128*40]
    __nv_bfloat16* Bs = smg + 2*2*GSTRIDE;
    const __nv_bfloat16* Ah = mode ? g_Thi : g_Xhi;
    const __nv_bfloat16* Al = mode ? g_Tlo : g_Xlo;
    const __nv_bfloat16* Wh = g_Whi + (mode ? WOFF : 0);
    const __nv_bfloat16* Wl = g_Wlo + (mode ? WOFF : 0);

    const int m0 = blockIdx.y*128, c0 = blockIdx.x*128;
    const int tid = threadIdx.x, lane = tid & 31, wid = tid >> 5;
    const int wm = wid & 3, wn = wid >> 2;
    const int grp = lane >> 2, tig = lane & 3;
    const int ra = tid >> 2, qa = tid & 3;

    const size_t oA0 = (size_t)(m0+ra)*DM    + qa*8;
    const size_t oA1 = (size_t)(m0+ra+64)*DM + qa*8;
    const size_t oB0 = (size_t)(c0+ra)*DM    + qa*8;
    const size_t oB1 = (size_t)(c0+ra+64)*DM + qa*8;
    const int s0 = ra*40 + qa*8, s1 = (ra+64)*40 + qa*8;

    float acc[2][8][4];
    #pragma unroll
    for (int mi=0;mi<2;mi++)
        #pragma unroll
        for (int ni=0;ni<8;ni++)
            #pragma unroll
            for (int c=0;c<4;c++) acc[mi][ni][c] = 0.f;

    // prologue: stage 0
    {
        cp16(&As[0*GSTRIDE + s0], &Ah[oA0]);
        cp16(&As[0*GSTRIDE + s1], &Ah[oA1]);
        cp16(&As[1*GSTRIDE + s0], &Al[oA0]);
        cp16(&As[1*GSTRIDE + s1], &Al[oA1]);
        cp16(&Bs[0*GSTRIDE + s0], &Wh[oB0]);
        cp16(&Bs[0*GSTRIDE + s1], &Wh[oB1]);
        cp16(&Bs[1*GSTRIDE + s0], &Wl[oB0]);
        cp16(&Bs[1*GSTRIDE + s1], &Wl[oB1]);
        cp_commit();
    }

    #pragma unroll 1
    for (int t=0; t<24; ++t) {
        if (t < 23) {
            const int kn = (t+1)*32;
            const int sp = ((t+1)&1)*2;
            cp16(&As[(sp+0)*GSTRIDE + s0], &Ah[oA0 + kn]);
            cp16(&As[(sp+0)*GSTRIDE + s1], &Ah[oA1 + kn]);
            cp16(&As[(sp+1)*GSTRIDE + s0], &Al[oA0 + kn]);
            cp16(&As[(sp+1)*GSTRIDE + s1], &Al[oA1 + kn]);
            cp16(&Bs[(sp+0)*GSTRIDE + s0], &Wh[oB0 + kn]);
            cp16(&Bs[(sp+0)*GSTRIDE + s1], &Wh[oB1 + kn]);
            cp16(&Bs[(sp+1)*GSTRIDE + s0], &Wl[oB0 + kn]);
            cp16(&Bs[(sp+1)*GSTRIDE + s1], &Wl[oB1 + kn]);
            cp_commit();
            cp_wait<1>();
        } else {
            cp_wait<0>();
        }
        __syncthreads();

        const __nv_bfloat16* AsH = As + ((t&1)*2+0)*GSTRIDE;
        const __nv_bfloat16* AsL = As + ((t&1)*2+1)*GSTRIDE;
        const __nv_bfloat16* BsH = Bs + ((t&1)*2+0)*GSTRIDE;
        const __nv_bfloat16* BsL = Bs + ((t&1)*2+1)*GSTRIDE;

        #pragma unroll
        for (int ks=0; ks<2; ++ks) {
            const int kb = ks*16 + tig*2;
            uint32_t ah[2][4], al[2][4];
            #pragma unroll
            for (int mi=0;mi<2;mi++) {
                const int row = wm*32 + mi*16 + grp;
                ah[mi][0] = *(const uint32_t*)&AsH[row*40     + kb];
                ah[mi][1] = *(const uint32_t*)&AsH[(row+8)*40 + kb];
                ah[mi][2] = *(const uint32_t*)&AsH[row*40     + kb + 8];
                ah[mi][3] = *(const uint32_t*)&AsH[(row+8)*40 + kb + 8];
                al[mi][0] = *(const uint32_t*)&AsL[row*40     + kb];
                al[mi][1] = *(const uint32_t*)&AsL[(row+8)*40 + kb];
                al[mi][2] = *(const uint32_t*)&AsL[row*40     + kb + 8];
                al[mi][3] = *(const uint32_t*)&AsL[(row+8)*40 + kb + 8];
            }
            #pragma unroll
            for (int ni=0;ni<8;ni++) {
                const int col = wn*64 + ni*8 + grp;
                const uint32_t bh0 = *(const uint32_t*)&BsH[col*40 + kb];
                const uint32_t bh1 = *(const uint32_t*)&BsH[col*40 + kb + 8];
                const uint32_t bl0 = *(const uint32_t*)&BsL[col*40 + kb];
                const uint32_t bl1 = *(const uint32_t*)&BsL[col*40 + kb + 8];
                #pragma unroll
                for (int mi=0;mi<2;mi++) {
                    MMA_BF16(acc[mi][ni], ah[mi], bh0, bh1);
                    MMA_BF16(acc[mi][ni], ah[mi], bl0, bl1);
                    MMA_BF16(acc[mi][ni], al[mi], bh0, bh1);
                }
            }
        }
        __syncthreads();
    }

    #pragma unroll
    for (int mi=0;mi<2;mi++) {
        #pragma unroll
        for (int ni=0;ni<8;ni++) {
            const int c = c0 + wn*64 + ni*8 + tig*2;
            const float b0v = bias[c], b1v = bias[c+1];
            #pragma unroll
            for (int hr=0;hr<2;hr++) {
                const int m = m0 + wm*32 + mi*16 + grp + hr*8;
                const float v0 = acc[mi][ni][hr*2+0] + b0v;
                const float v1 = acc[mi][ni][hr*2+1] + b1v;
                if (mode == 1) {
                    *(float2*)&out[(size_t)m*DM + c] = make_float2(v0, v1);
                } else {
                    const int t  = (c >= 1536) ? 2 : (c >= 768 ? 1 : 0);
                    const int rr = c - t*DM;
                    const int hh = rr >> 6, d = rr & 63;
                    const int b_ = m >> 10, n = m & 1023;
                    const size_t di = ((size_t)((b_*NH+hh)*NSEQ + n))*HD + d;
                    if (t == 0) {
                        *(float2*)&g_Q[di] = make_float2(v0, v1);
                        uint32_t hh32, ll32;
                        split2(v0, v1, hh32, ll32);
                        *(uint32_t*)&g_Qhi[di] = hh32;
                        *(uint32_t*)&g_Qlo[di] = ll32;
                    } else if (t == 1) {
                        uint32_t hh32, ll32;
                        split2(v0, v1, hh32, ll32);
                        *(uint32_t*)&g_Khi[di] = hh32;
                        *(uint32_t*)&g_Klo[di] = ll32;
                    } else {
                        *(float2*)&g_V[di] = make_float2(v0, v1);
                    }
                }
            }
        }
    }
}

// ---------------------------------------------------------------------------
// V transpose + bf16 split: g_VT*[bh][d][k]  (once per head; flash re-uses)
// ---------------------------------------------------------------------------
__global__ __launch_bounds__(256) void vtrans_kernel()
{
    __shared__ float ts[64*68];
    const int bh = blockIdx.y, k0 = blockIdx.x*64;
    const int tid = threadIdx.x;
    #pragma unroll
    for (int it=0; it<4; ++it) {
        int idx = it*256 + tid;      // 1024 float4 = 64 k x 16 quads
        int k = idx >> 4, dq = idx & 15;
        float4 v = *(const float4*)&g_V[((size_t)(bh*NSEQ + k0 + k))*HD + dq*4];
        *(float4*)&ts[k*68 + dq*4] = v;
    }
    __syncthreads();
    const int d = tid >> 2, kq = tid & 3;
    uint32_t hw[8], lw[8];
    #pragma unroll
    for (int i=0;i<8;++i) {
        float f0 = ts[(kq*16 + 2*i  )*68 + d];
        float f1 = ts[(kq*16 + 2*i+1)*68 + d];
        split2(f0, f1, hw[i], lw[i]);
    }
    const size_t base = ((size_t)(bh*HD + d))*NSEQ + k0 + kq*16;
    *(uint4*)&g_VThi[base]   = make_uint4(hw[0], hw[1], hw[2], hw[3]);
    *(uint4*)&g_VThi[base+8] = make_uint4(hw[4], hw[5], hw[6], hw[7]);
    *(uint4*)&g_VTlo[base]   = make_uint4(lw[0], lw[1], lw[2], lw[3]);
    *(uint4*)&g_VTlo[base+8] = make_uint4(lw[4], lw[5], lw[6], lw[7]);
}

// ---------------------------------------------------------------------------
__global__ __launch_bounds__(256) void rel_kernel(
    const float* __restrict__ rph, const float* __restrict__ rpw)
{
    __shared__ float qs[4*64];
    const int blk = blockIdx.x;
    const int bh = blk >> 8, ng = blk & 255;
    const int tid = threadIdx.x, ln = tid >> 6, t = tid & 63;
    const int n = (ng << 2) + ln;
    qs[ln*64 + t] = g_Q[((size_t)(bh*NSEQ + n))*HD + t];
    __syncthreads();

    const int j = t & 31, half = t >> 5;
    const int qh = n >> 5, qw = n & 31;
    const float* tab = half ? rpw : rph;
    const int ref = half ? qw : qh;
    const float4* row = (const float4*)&tab[(ref - j + 31)*HD];
    const float4* q4  = (const float4*)&qs[ln*64];
    float a = 0.f;
    #pragma unroll
    for (int d4=0; d4<16; ++d4) {
        float4 rr = row[d4], qq = q4[d4];
        a += rr.x*qq.x + rr.y*qq.y + rr.z*qq.z + rr.w*qq.w;
    }
    float* dst = half ? g_relw : g_relh;
    dst[((size_t)(bh*NSEQ + n))*32 + j] = a;
}

// ---------------------------------------------------------------------------
__global__ void vsum_kernel()
{
    __shared__ float red[256];
    const int bh = blockIdx.x, tid = threadIdx.x;
    const int d = tid & 63, part = tid >> 6;
    float s = 0.f;
    for (int k = part*256; k < part*256 + 256; ++k)
        s += g_V[((size_t)(bh*NSEQ + k))*HD + d];
    red[tid] = s;
    __syncthreads();
    if (tid < 64)
        g_vsum[bh*HD + tid] = red[tid] + red[tid+64] + red[tid+128] + red[tid+192];
}

// ---------------------------------------------------------------------------
// Flash attention on tensor cores; K/Vt tiles cp.async double-buffered,
// operands pre-split in gmem (no per-tile convert work).
// ---------------------------------------------------------------------------
#define QKS 72
#define VTS 136
#define KPL (128*QKS)   // bf16 per (stage,hl) K plane
#define VPL (64*VTS)
#define FL_SMEM_BYTES (2*128*QKS*2 + 2*2*KPL*2 + 2*2*VPL*2 + 128*33*4 + 2*128*4)

__global__ __launch_bounds__(256,1) void flash_mma(const float* __restrict__ policy)
{
    extern __shared__ char smraw[];
    __nv_bfloat16* Qh   = (__nv_bfloat16*)smraw;       // 128*QKS
    __nv_bfloat16* Ql   = Qh + 128*QKS;
    __nv_bfloat16* Kbuf = Ql + 128*QKS;                // [(stage*2+hl)][KPL]
    __nv_bfloat16* Vbuf = Kbuf + 2*2*KPL;              // [(stage*2+hl)][VPL]
    float* rw_s  = (float*)(Vbuf + 2*2*VPL);           // 128*33
    float* pol_s = rw_s + 128*33;                      // [2][128]

    const int bh = blockIdx.y, q0 = blockIdx.x << 7;
    const int b_ = bh / NH, hh = bh - b_*NH;
    const int tid = threadIdx.x, lane = tid & 31, w = tid >> 5;
    const int grp = lane >> 2, tig = lane & 3;
    const int r0 = w*16 + grp, r1 = r0 + 8;
    const int qg0 = q0 + r0, qg1 = q0 + r1;

    // ---- Q tile hi/lo (plain copies, once)
    #pragma unroll
    for (int it=0; it<4; ++it) {
        int idx = it*256 + tid, r = idx >> 3, q = idx & 7;   // 1024 quads of 8 bf16
        const size_t src = ((size_t)(bh*NSEQ + q0 + r))*HD + q*8;
        *(uint4*)&Qh[r*QKS + q*8] = *(const uint4*)&g_Qhi[src];
        *(uint4*)&Ql[r*QKS + q*8] = *(const uint4*)&g_Qlo[src];
    }
    for (int idx = tid; idx < 128*32; idx += 256) {
        int r = idx >> 5, c = idx & 31;
        rw_s[r*33 + c] = g_relw[((size_t)(bh*NSEQ + q0 + r))*32 + c];
    }

    // ---- prologue: stage 0 tile
    {
        #pragma unroll
        for (int it=0; it<4; ++it) {
            int idx = it*256 + tid;
            int kr = idx >> 3, q = idx & 7;
            cp16(&Kbuf[0*KPL + kr*QKS + q*8], &g_Khi[((size_t)(bh*NSEQ + kr))*HD + q*8]);
            cp16(&Kbuf[1*KPL + kr*QKS + q*8], &g_Klo[((size_t)(bh*NSEQ + kr))*HD + q*8]);
            int d = idx >> 4, vq = idx & 15;
            cp16(&Vbuf[0*VPL + d*VTS + vq*8], &g_VThi[((size_t)(bh*HD + d))*NSEQ + vq*8]);
            cp16(&Vbuf[1*VPL + d*VTS + vq*8], &g_VTlo[((size_t)(bh*HD + d))*NSEQ + vq*8]);
        }
        if (tid < 32) cp16(&pol_s[tid*4], &policy[(b_<<10) + tid*4]);
        cp_commit();
    }

    float m0 = -CUDART_INF_F, m1 = -CUDART_INF_F, l0v = 0.f, l1v = 0.f;
    float o[8][4];
    #pragma unroll
    for (int nd=0; nd<8; ++nd) { o[nd][0]=o[nd][1]=o[nd][2]=o[nd][3]=0.f; }

    #pragma unroll 1
    for (int t=0; t<8; ++t) {
        const int k0 = t << 7;
        if (t < 7) {
            const int kn = k0 + 128;
            const int sp = ((t+1)&1)*2;
            #pragma unroll
            for (int it=0; it<4; ++it) {
                int idx = it*256 + tid;
                int kr = idx >> 3, q = idx & 7;
                cp16(&Kbuf[(sp+0)*KPL + kr*QKS + q*8], &g_Khi[((size_t)(bh*NSEQ + kn + kr))*HD + q*8]);
                cp16(&Kbuf[(sp+1)*KPL + kr*QKS + q*8], &g_Klo[((size_t)(bh*NSEQ + kn + kr))*HD + q*8]);
                int d = idx >> 4, vq = idx & 15;
                cp16(&Vbuf[(sp+0)*VPL + d*VTS + vq*8], &g_VThi[((size_t)(bh*HD + d))*NSEQ + kn + vq*8]);
                cp16(&Vbuf[(sp+1)*VPL + d*VTS + vq*8], &g_VTlo[((size_t)(bh*HD + d))*NSEQ + kn + vq*8]);
            }
            if (tid < 32) cp16(&pol_s[((t+1)&1)*128 + tid*4], &policy[(b_<<10) + kn + tid*4]);
            cp_commit();
            cp_wait<1>();
        } else {
            cp_wait<0>();
        }
        __syncthreads();

        const __nv_bfloat16* Kh  = Kbuf + ((t&1)*2+0)*KPL;
        const __nv_bfloat16* Kl  = Kbuf + ((t&1)*2+1)*KPL;
        const __nv_bfloat16* Vth = Vbuf + ((t&1)*2+0)*VPL;
        const __nv_bfloat16* Vtl = Vbuf + ((t&1)*2+1)*VPL;
        const float* pol = pol_s + (t&1)*128;

        float4 rh0 = *(const float4*)&g_relh[((size_t)(bh*NSEQ + qg0))*32 + (k0>>5)];
        float4 rh1 = *(const float4*)&g_relh[((size_t)(bh*NSEQ + qg1))*32 + (k0>>5)];

        // ---- S = Q.K^T (3-MMA bf16 split)
        float acc[16][4];
        #pragma unroll
        for (int jb=0; jb<16; ++jb) { acc[jb][0]=acc[jb][1]=acc[jb][2]=acc[jb][3]=0.f; }

        #pragma unroll
        for (int kb=0; kb<4; ++kb) {
            const int kk = kb*16 + tig*2;
            uint32_t qhf[4], qlf[4];
            qhf[0] = *(const uint32_t*)&Qh[r0*QKS + kk];
            qhf[1] = *(const uint32_t*)&Qh[r1*QKS + kk];
            qhf[2] = *(const uint32_t*)&Qh[r0*QKS + kk + 8];
            qhf[3] = *(const uint32_t*)&Qh[r1*QKS + kk + 8];
            qlf[0] = *(const uint32_t*)&Ql[r0*QKS + kk];
            qlf[1] = *(const uint32_t*)&Ql[r1*QKS + kk];
            qlf[2] = *(const uint32_t*)&Ql[r0*QKS + kk + 8];
            qlf[3] = *(const uint32_t*)&Ql[r1*QKS + kk + 8];
            #pragma unroll
            for (int jb=0; jb<16; ++jb) {
                const int col = jb*8 + grp;
                const uint32_t kh0 = *(const uint32_t*)&Kh[col*QKS + kk];
                const uint32_t kh1 = *(const uint32_t*)&Kh[col*QKS + kk + 8];
                const uint32_t kl0 = *(const uint32_t*)&Kl[col*QKS + kk];
                const uint32_t kl1 = *(const uint32_t*)&Kl[col*QKS + kk + 8];
                MMA_BF16(acc[jb], qhf, kh0, kh1);
                MMA_BF16(acc[jb], qhf, kl0, kl1);
                MMA_BF16(acc[jb], qlf, kh0, kh1);
            }
        }

        // ---- bias + row max (full 128 cols, BEFORE mask — as reference)
        float tmax0 = -CUDART_INF_F, tmax1 = -CUDART_INF_F;
        #pragma unroll
        for (int jb=0; jb<16; ++jb) {
            const int kh = jb >> 2;
            const float rhv0 = (kh==0)?rh0.x:(kh==1)?rh0.y:(kh==2)?rh0.z:rh0.w;
            const float rhv1 = (kh==0)?rh1.x:(kh==1)?rh1.y:(kh==2)?rh1.z:rh1.w;
            const int cw = ((jb & 3) << 3) + (tig << 1);
            acc[jb][0] = acc[jb][0]*SCALE + rhv0 + rw_s[r0*33 + cw];
            acc[jb][1] = acc[jb][1]*SCALE + rhv0 + rw_s[r0*33 + cw + 1];
            acc[jb][2] = acc[jb][2]*SCALE + rhv1 + rw_s[r1*33 + cw];
            acc[jb][3] = acc[jb][3]*SCALE + rhv1 + rw_s[r1*33 + cw + 1];
            tmax0 = fmaxf(tmax0, fmaxf(acc[jb][0], acc[jb][1]));
            tmax1 = fmaxf(tmax1, fmaxf(acc[jb][2], acc[jb][3]));
        }
        tmax0 = fmaxf(tmax0, __shfl_xor_sync(0xffffffffu, tmax0, 1));
        tmax0 = fmaxf(tmax0, __shfl_xor_sync(0xffffffffu, tmax0, 2));
        tmax1 = fmaxf(tmax1, __shfl_xor_sync(0xffffffffu, tmax1, 1));
        tmax1 = fmaxf(tmax1, __shfl_xor_sync(0xffffffffu, tmax1, 2));

        const float mn0 = fmaxf(m0, tmax0);
        const float mn1 = fmaxf(m1, tmax1);
        const float f0 = __expf(m0 - mn0);
        const float f1 = __expf(m1 - mn1);
        m0 = mn0; m1 = mn1;
        #pragma unroll
        for (int nd=0; nd<8; ++nd) {
            o[nd][0]*=f0; o[nd][1]*=f0; o[nd][2]*=f1; o[nd][3]*=f1;
        }

        float rs0 = 0.f, rs1 = 0.f;
        #pragma unroll
        for (int half=0; half<2; ++half) {
            uint32_t pha[8], phb[8], pla[8], plb[8];
            #pragma unroll
            for (int j=0; j<8; ++j) {
                const int jb = half*8 + j;
                const int cb = (jb<<3) + (tig<<1);
                const int kg = k0 + cb;
                const float ap00 = (kg   == qg0) ? 1.f : pol[cb];
                const float ap01 = (kg+1 == qg0) ? 1.f : pol[cb+1];
                const float ap10 = (kg   == qg1) ? 1.f : pol[cb];
                const float ap11 = (kg+1 == qg1) ? 1.f : pol[cb+1];
                const float e00 = __expf(acc[jb][0] - mn0) * ap00;
                const float e01 = __expf(acc[jb][1] - mn0) * ap01;
                const float e10 = __expf(acc[jb][2] - mn1) * ap10;
                const float e11 = __expf(acc[jb][3] - mn1) * ap11;
                rs0 += e00 + e01;
                rs1 += e10 + e11;
                split2(e00, e01, pha[j], pla[j]);
                split2(e10, e11, phb[j], plb[j]);
            }
            #pragma unroll
            for (int j2=0; j2<4; ++j2) {
                const int g = half*4 + j2;
                uint32_t ahi[4] = { pha[j2*2], phb[j2*2], pha[j2*2+1], phb[j2*2+1] };
                uint32_t alo[4] = { pla[j2*2], plb[j2*2], pla[j2*2+1], plb[j2*2+1] };
                #pragma unroll
                for (int nd=0; nd<8; ++nd) {
                    const int dcol = nd*8 + grp;
                    const uint32_t vh0 = *(const uint32_t*)&Vth[dcol*VTS + g*16 + tig*2];
                    const uint32_t vh1 = *(const uint32_t*)&Vth[dcol*VTS + g*16 + tig*2 + 8];
                    const uint32_t vl0 = *(const uint32_t*)&Vtl[dcol*VTS + g*16 + tig*2];
                    const uint32_t vl1 = *(const uint32_t*)&Vtl[dcol*VTS + g*16 + tig*2 + 8];
                    MMA_BF16(o[nd], ahi, vh0, vh1);
                    MMA_BF16(o[nd], ahi, vl0, vl1);
                    MMA_BF16(o[nd], alo, vh0, vh1);
                }
            }
        }
        rs0 += __shfl_xor_sync(0xffffffffu, rs0, 1);
        rs0 += __shfl_xor_sync(0xffffffffu, rs0, 2);
        rs1 += __shfl_xor_sync(0xffffffffu, rs1, 1);
        rs1 += __shfl_xor_sync(0xffffffffu, rs1, 2);
        l0v = l0v*f0 + rs0;
        l1v = l1v*f1 + rs1;
        __syncthreads();
    }

    // ---- epilogue: out = (o + EPSN*vsum)/(l + EPSV), split bf16 hi/lo
    const float inv0 = 1.f / (l0v + EPSV);
    const float inv1 = 1.f / (l1v + EPSV);
    #pragma unroll
    for (int nd=0; nd<8; ++nd) {
        const int d = nd*8 + tig*2;
        const float2 vs = *(const float2*)&g_vsum[bh*HD + d];
        const float a0 = (o[nd][0] + EPSN*vs.x) * inv0;
        const float a1 = (o[nd][1] + EPSN*vs.y) * inv0;
        const float a2 = (o[nd][2] + EPSN*vs.x) * inv1;
        const float a3 = (o[nd][3] + EPSN*vs.y) * inv1;
        uint32_t h0,l0,h1,l1;
        split2(a0, a1, h0, l0);
        split2(a2, a3, h1, l1);
        const size_t base0 = ((size_t)(b_*NSEQ + qg0))*DM + hh*HD + d;
        const size_t base1 = ((size_t)(b_*NSEQ + qg1))*DM + hh*HD + d;
        *(uint32_t*)&g_Thi[base0] = h0;
        *(uint32_t*)&g_Tlo[base0] = l0;
        *(uint32_t*)&g_Thi[base1] = h1;
        *(uint32_t*)&g_Tlo[base1] = l1;
    }
}

// ---------------------------------------------------------------------------
extern "C" void kernel_launch(void* const* d_in, const int* in_sizes, int n_in,
                              void* d_out, int out_size)
{
    const float* x      = (const float*)d_in[0];
    const float* policy = (const float*)d_in[1];
    const float* qkv_w  = (const float*)d_in[2];
    const float* qkv_b  = (const float*)d_in[3];
    const float* proj_w = (const float*)d_in[4];
    const float* proj_b = (const float*)d_in[5];
    const float* rph    = (const float*)d_in[6];
    const float* rpw    = (const float*)d_in[7];
    float* out = (float*)d_out;

    cudaFuncSetAttribute(flash_mma,
        cudaFuncAttributeMaxDynamicSharedMemorySize, FL_SMEM_BYTES);
    cudaFuncSetAttribute(gemm_mma,
        cudaFuncAttributeMaxDynamicSharedMemorySize, GEMM_SMEM_BYTES);

    const int n4x = NB*NSEQ*DM/4, n4q = 2304*DM/4, n4p = DM*DM/4;
    split_kernel<<<(n4x+255)/256,256>>>(x,      0, n4x);
    split_kernel<<<(n4q+255)/256,256>>>(qkv_w,  1, n4q);
    split_kernel<<<(n4p+255)/256,256>>>(proj_w, 2, n4p);

    gemm_mma<<<dim3(18,64),256,GEMM_SMEM_BYTES>>>(qkv_b, nullptr, 0);
    vtrans_kernel<<<dim3(16,NBH),256>>>();
    rel_kernel<<<NBH*256,256>>>(rph, rpw);
    vsum_kernel<<<NBH,256>>>();
    flash_mma<<<dim3(8,NBH),256,FL_SMEM_BYTES>>>(policy);
    gemm_mma<<<dim3(6,64),256,GEMM_SMEM_BYTES>>>(proj_b, out, 1);
}

// round 10
// speedup vs baseline: 1.9095x; 1.0445x over previous
#include <cuda_runtime.h>
#include <cuda_bf16.h>
#include <math_constants.h>
#include <cstddef>
#include <cstdint>

#define NB 8
#define NH 12
#define HD 64
#define DM 768
#define NSEQ 1024
#define NBH 96
#define SCALE 0.125f
#define EPSV 1e-6f
#define EPSN (1e-6f/1024.0f)
#define WOFF (2304*768)

__device__ float g_Q[NBH*NSEQ*HD];
__device__ float g_V[NBH*NSEQ*HD];
__device__ float g_relh[NBH*NSEQ*32];
__device__ float g_relw[NBH*NSEQ*32];
__device__ float g_vsum[NBH*HD];

__device__ __nv_bfloat16 g_Xhi[NB*NSEQ*DM], g_Xlo[NB*NSEQ*DM];
__device__ __nv_bfloat16 g_Whi[3072*DM],    g_Wlo[3072*DM];
__device__ __nv_bfloat16 g_Thi[NB*NSEQ*DM], g_Tlo[NB*NSEQ*DM];

// bf16 hi/lo operands for flash (written by gemm epilogue / vtrans)
__device__ __nv_bfloat16 g_Qhi[NBH*NSEQ*HD], g_Qlo[NBH*NSEQ*HD];
__device__ __nv_bfloat16 g_Khi[NBH*NSEQ*HD], g_Klo[NBH*NSEQ*HD];
__device__ __nv_bfloat16 g_VThi[NBH*HD*NSEQ], g_VTlo[NBH*HD*NSEQ];  // [bh][d][k]

#define MMA_BF16(d, a, b0, b1)                                             \
  asm volatile("mma.sync.aligned.m16n8k16.row.col.f32.bf16.bf16.f32 "      \
    "{%0,%1,%2,%3},{%4,%5,%6,%7},{%8,%9},{%0,%1,%2,%3};\n"                 \
    : "+f"(d[0]), "+f"(d[1]), "+f"(d[2]), "+f"(d[3])                       \
    : "r"(a[0]), "r"(a[1]), "r"(a[2]), "r"(a[3]), "r"(b0), "r"(b1))

__device__ __forceinline__ void split2(float a, float b, uint32_t& hi, uint32_t& lo)
{
    __nv_bfloat162 h = __floats2bfloat162_rn(a, b);
    float ra = a - __bfloat162float(h.x);
    float rb = b - __bfloat162float(h.y);
    __nv_bfloat162 l = __floats2bfloat162_rn(ra, rb);
    hi = *(uint32_t*)&h;
    lo = *(uint32_t*)&l;
}

__device__ __forceinline__ void cp16(void* smem, const void* gmem)
{
    uint32_t s = (uint32_t)__cvta_generic_to_shared(smem);
    asm volatile("cp.async.cg.shared.global [%0], [%1], 16;\n" :: "r"(s), "l"(gmem));
}
__device__ __forceinline__ void cp_commit()
{
    asm volatile("cp.async.commit_group;\n");
}
template<int N> __device__ __forceinline__ void cp_wait()
{
    asm volatile("cp.async.wait_group %0;\n" :: "n"(N));
}

// ---------------------------------------------------------------------------
// split fp32 -> bf16 hi + bf16 lo.  which: 0 = x, 1 = qkv_w, 2 = proj_w
// ---------------------------------------------------------------------------
__global__ void split_kernel(const float* __restrict__ src, int which, int n4)
{
    int i = blockIdx.x*256 + threadIdx.x;
    if (i >= n4) return;
    __nv_bfloat16 *hi, *lo;
    if (which == 0)      { hi = g_Xhi;        lo = g_Xlo; }
    else if (which == 1) { hi = g_Whi;        lo = g_Wlo; }
    else                 { hi = g_Whi + WOFF; lo = g_Wlo + WOFF; }
    float4 v = ((const float4*)src)[i];
    uint32_t h0, l0, h1, l1;
    split2(v.x, v.y, h0, l0);
    split2(v.z, v.w, h1, l1);
    ((uint32_t*)hi)[i*2]   = h0;
    ((uint32_t*)hi)[i*2+1] = h1;
    ((uint32_t*)lo)[i*2]   = l0;
    ((uint32_t*)lo)[i*2+1] = l1;
}

// ---------------------------------------------------------------------------
// Tensor-core GEMM, cp.async double-buffered, 2 CTAs/SM.
// mode 0: QKV -> Q: fp32 + bf16 hi/lo, K: bf16 hi/lo, V: fp32. mode 1: proj.
// ---------------------------------------------------------------------------
#define GSTRIDE 5120            // 128*40 bf16 per (stage, hl) plane
// As: 4 planes * 5120 bf16 = 40960 B; Bs same. Total = 81920 B.
#define GEMM_SMEM_BYTES (2 * 4 * GSTRIDE * 2)

__global__ __launch_bounds__(256,2) void gemm_mma(
    const float* __restrict__ bias, float* __restrict__ out, int mode)
{
    extern __shared__ __nv_bfloat16 smg[];
    __nv_bfloat16* As = smg;                     // [(stage*2+hl)][128*40]
    __nv_bfloat16* Bs = smg + 2*2*GSTRIDE;
    const __nv_bfloat16* Ah = mode ? g_Thi : g_Xhi;
    const __nv_bfloat16* Al = mode ? g_Tlo : g_Xlo;
    const __nv_bfloat16* Wh = g_Whi + (mode ? WOFF : 0);
    const __nv_bfloat16* Wl = g_Wlo + (mode ? WOFF : 0);

    const int m0 = blockIdx.y*128, c0 = blockIdx.x*128;
    const int tid = threadIdx.x, lane = tid & 31, wid = tid >> 5;
    const int wm = wid & 3, wn = wid >> 2;
    const int grp = lane >> 2, tig = lane & 3;
    const int ra = tid >> 2, qa = tid & 3;

    const size_t oA0 = (size_t)(m0+ra)*DM    + qa*8;
    const size_t oA1 = (size_t)(m0+ra+64)*DM + qa*8;
    const size_t oB0 = (size_t)(c0+ra)*DM    + qa*8;
    const size_t oB1 = (size_t)(c0+ra+64)*DM + qa*8;
    const int s0 = ra*40 + qa*8, s1 = (ra+64)*40 + qa*8;

    float acc[2][8][4];
    #pragma unroll
    for (int mi=0;mi<2;mi++)
        #pragma unroll
        for (int ni=0;ni<8;ni++)
            #pragma unroll
            for (int c=0;c<4;c++) acc[mi][ni][c] = 0.f;

    // prologue: stage 0
    {
        cp16(&As[0*GSTRIDE + s0], &Ah[oA0]);
        cp16(&As[0*GSTRIDE + s1], &Ah[oA1]);
        cp16(&As[1*GSTRIDE + s0], &Al[oA0]);
        cp16(&As[1*GSTRIDE + s1], &Al[oA1]);
        cp16(&Bs[0*GSTRIDE + s0], &Wh[oB0]);
        cp16(&Bs[0*GSTRIDE + s1], &Wh[oB1]);
        cp16(&Bs[1*GSTRIDE + s0], &Wl[oB0]);
        cp16(&Bs[1*GSTRIDE + s1], &Wl[oB1]);
        cp_commit();
    }

    #pragma unroll 1
    for (int t=0; t<24; ++t) {
        if (t < 23) {
            const int kn = (t+1)*32;
            const int sp = ((t+1)&1)*2;
            cp16(&As[(sp+0)*GSTRIDE + s0], &Ah[oA0 + kn]);
            cp16(&As[(sp+0)*GSTRIDE + s1], &Ah[oA1 + kn]);
            cp16(&As[(sp+1)*GSTRIDE + s0], &Al[oA0 + kn]);
            cp16(&As[(sp+1)*GSTRIDE + s1], &Al[oA1 + kn]);
            cp16(&Bs[(sp+0)*GSTRIDE + s0], &Wh[oB0 + kn]);
            cp16(&Bs[(sp+0)*GSTRIDE + s1], &Wh[oB1 + kn]);
            cp16(&Bs[(sp+1)*GSTRIDE + s0], &Wl[oB0 + kn]);
            cp16(&Bs[(sp+1)*GSTRIDE + s1], &Wl[oB1 + kn]);
            cp_commit();
            cp_wait<1>();
        } else {
            cp_wait<0>();
        }
        __syncthreads();

        const __nv_bfloat16* AsH = As + ((t&1)*2+0)*GSTRIDE;
        const __nv_bfloat16* AsL = As + ((t&1)*2+1)*GSTRIDE;
        const __nv_bfloat16* BsH = Bs + ((t&1)*2+0)*GSTRIDE;
        const __nv_bfloat16* BsL = Bs + ((t&1)*2+1)*GSTRIDE;

        #pragma unroll
        for (int ks=0; ks<2; ++ks) {
            const int kb = ks*16 + tig*2;
            uint32_t ah[2][4], al[2][4];
            #pragma unroll
            for (int mi=0;mi<2;mi++) {
                const int row = wm*32 + mi*16 + grp;
                ah[mi][0] = *(const uint32_t*)&AsH[row*40     + kb];
                ah[mi][1] = *(const uint32_t*)&AsH[(row+8)*40 + kb];
                ah[mi][2] = *(const uint32_t*)&AsH[row*40     + kb + 8];
                ah[mi][3] = *(const uint32_t*)&AsH[(row+8)*40 + kb + 8];
                al[mi][0] = *(const uint32_t*)&AsL[row*40     + kb];
                al[mi][1] = *(const uint32_t*)&AsL[(row+8)*40 + kb];
                al[mi][2] = *(const uint32_t*)&AsL[row*40     + kb + 8];
                al[mi][3] = *(const uint32_t*)&AsL[(row+8)*40 + kb + 8];
            }
            #pragma unroll
            for (int ni=0;ni<8;ni++) {
                const int col = wn*64 + ni*8 + grp;
                const uint32_t bh0 = *(const uint32_t*)&BsH[col*40 + kb];
                const uint32_t bh1 = *(const uint32_t*)&BsH[col*40 + kb + 8];
                const uint32_t bl0 = *(const uint32_t*)&BsL[col*40 + kb];
                const uint32_t bl1 = *(const uint32_t*)&BsL[col*40 + kb + 8];
                #pragma unroll
                for (int mi=0;mi<2;mi++) {
                    MMA_BF16(acc[mi][ni], ah[mi], bh0, bh1);
                    MMA_BF16(acc[mi][ni], ah[mi], bl0, bl1);
                    MMA_BF16(acc[mi][ni], al[mi], bh0, bh1);
                }
            }
        }
        __syncthreads();
    }

    #pragma unroll
    for (int mi=0;mi<2;mi++) {
        #pragma unroll
        for (int ni=0;ni<8;ni++) {
            const int c = c0 + wn*64 + ni*8 + tig*2;
            const float b0v = bias[c], b1v = bias[c+1];
            #pragma unroll
            for (int hr=0;hr<2;hr++) {
                const int m = m0 + wm*32 + mi*16 + grp + hr*8;
                const float v0 = acc[mi][ni][hr*2+0] + b0v;
                const float v1 = acc[mi][ni][hr*2+1] + b1v;
                if (mode == 1) {
                    *(float2*)&out[(size_t)m*DM + c] = make_float2(v0, v1);
                } else {
                    const int t  = (c >= 1536) ? 2 : (c >= 768 ? 1 : 0);
                    const int rr = c - t*DM;
                    const int hh = rr >> 6, d = rr & 63;
                    const int b_ = m >> 10, n = m & 1023;
                    const size_t di = ((size_t)((b_*NH+hh)*NSEQ + n))*HD + d;
                    if (t == 0) {
                        *(float2*)&g_Q[di] = make_float2(v0, v1);
                        uint32_t hh32, ll32;
                        split2(v0, v1, hh32, ll32);
                        *(uint32_t*)&g_Qhi[di] = hh32;
                        *(uint32_t*)&g_Qlo[di] = ll32;
                    } else if (t == 1) {
                        uint32_t hh32, ll32;
                        split2(v0, v1, hh32, ll32);
                        *(uint32_t*)&g_Khi[di] = hh32;
                        *(uint32_t*)&g_Klo[di] = ll32;
                    } else {
                        *(float2*)&g_V[di] = make_float2(v0, v1);
                    }
                }
            }
        }
    }
}

// ---------------------------------------------------------------------------
// V transpose + bf16 split: g_VT*[bh][d][k]  (once per head; flash re-uses)
// ---------------------------------------------------------------------------
__global__ __launch_bounds__(256) void vtrans_kernel()
{
    __shared__ float ts[64*68];
    const int bh = blockIdx.y, k0 = blockIdx.x*64;
    const int tid = threadIdx.x;
    #pragma unroll
    for (int it=0; it<4; ++it) {
        int idx = it*256 + tid;      // 1024 float4 = 64 k x 16 quads
        int k = idx >> 4, dq = idx & 15;
        float4 v = *(const float4*)&g_V[((size_t)(bh*NSEQ + k0 + k))*HD + dq*4];
        *(float4*)&ts[k*68 + dq*4] = v;
    }
    __syncthreads();
    const int d = tid >> 2, kq = tid & 3;
    uint32_t hw[8], lw[8];
    #pragma unroll
    for (int i=0;i<8;++i) {
        float f0 = ts[(kq*16 + 2*i  )*68 + d];
        float f1 = ts[(kq*16 + 2*i+1)*68 + d];
        split2(f0, f1, hw[i], lw[i]);
    }
    const size_t base = ((size_t)(bh*HD + d))*NSEQ + k0 + kq*16;
    *(uint4*)&g_VThi[base]   = make_uint4(hw[0], hw[1], hw[2], hw[3]);
    *(uint4*)&g_VThi[base+8] = make_uint4(hw[4], hw[5], hw[6], hw[7]);
    *(uint4*)&g_VTlo[base]   = make_uint4(lw[0], lw[1], lw[2], lw[3]);
    *(uint4*)&g_VTlo[base+8] = make_uint4(lw[4], lw[5], lw[6], lw[7]);
}

// ---------------------------------------------------------------------------
__global__ __launch_bounds__(256) void rel_kernel(
    const float* __restrict__ rph, const float* __restrict__ rpw)
{
    __shared__ float qs[4*64];
    const int blk = blockIdx.x;
    const int bh = blk >> 8, ng = blk & 255;
    const int tid = threadIdx.x, ln = tid >> 6, t = tid & 63;
    const int n = (ng << 2) + ln;
    qs[ln*64 + t] = g_Q[((size_t)(bh*NSEQ + n))*HD + t];
    __syncthreads();

    const int j = t & 31, half = t >> 5;
    const int qh = n >> 5, qw = n & 31;
    const float* tab = half ? rpw : rph;
    const int ref = half ? qw : qh;
    const float4* row = (const float4*)&tab[(ref - j + 31)*HD];
    const float4* q4  = (const float4*)&qs[ln*64];
    float a = 0.f;
    #pragma unroll
    for (int d4=0; d4<16; ++d4) {
        float4 rr = row[d4], qq = q4[d4];
        a += rr.x*qq.x + rr.y*qq.y + rr.z*qq.z + rr.w*qq.w;
    }
    float* dst = half ? g_relw : g_relh;
    dst[((size_t)(bh*NSEQ + n))*32 + j] = a;
}

// ---------------------------------------------------------------------------
__global__ void vsum_kernel()
{
    __shared__ float red[256];
    const int bh = blockIdx.x, tid = threadIdx.x;
    const int d = tid & 63, part = tid >> 6;
    float s = 0.f;
    for (int k = part*256; k < part*256 + 256; ++k)
        s += g_V[((size_t)(bh*NSEQ + k))*HD + d];
    red[tid] = s;
    __syncthreads();
    if (tid < 64)
        g_vsum[bh*HD + tid] = red[tid] + red[tid+64] + red[tid+128] + red[tid+192];
}

// ---------------------------------------------------------------------------
// Flash attention on tensor cores; K/Vt tiles cp.async double-buffered,
// operands pre-split in gmem (no per-tile convert work).
// ---------------------------------------------------------------------------
#define QKS 72
#define VTS 136
#define KPL (128*QKS)   // bf16 per (stage,hl) K plane
#define VPL (64*VTS)
#define FL_SMEM_BYTES (2*128*QKS*2 + 2*2*KPL*2 + 2*2*VPL*2 + 128*33*4 + 2*128*4)

__global__ __launch_bounds__(256,1) void flash_mma(const float* __restrict__ policy)
{
    extern __shared__ char smraw[];
    __nv_bfloat16* Qh   = (__nv_bfloat16*)smraw;       // 128*QKS
    __nv_bfloat16* Ql   = Qh + 128*QKS;
    __nv_bfloat16* Kbuf = Ql + 128*QKS;                // [(stage*2+hl)][KPL]
    __nv_bfloat16* Vbuf = Kbuf + 2*2*KPL;              // [(stage*2+hl)][VPL]
    float* rw_s  = (float*)(Vbuf + 2*2*VPL);           // 128*33
    float* pol_s = rw_s + 128*33;                      // [2][128]

    const int bh = blockIdx.y, q0 = blockIdx.x << 7;
    const int b_ = bh / NH, hh = bh - b_*NH;
    const int tid = threadIdx.x, lane = tid & 31, w = tid >> 5;
    const int grp = lane >> 2, tig = lane & 3;
    const int r0 = w*16 + grp, r1 = r0 + 8;
    const int qg0 = q0 + r0, qg1 = q0 + r1;

    // ---- Q tile hi/lo (plain copies, once)
    #pragma unroll
    for (int it=0; it<4; ++it) {
        int idx = it*256 + tid, r = idx >> 3, q = idx & 7;   // 1024 quads of 8 bf16
        const size_t src = ((size_t)(bh*NSEQ + q0 + r))*HD + q*8;
        *(uint4*)&Qh[r*QKS + q*8] = *(const uint4*)&g_Qhi[src];
        *(uint4*)&Ql[r*QKS + q*8] = *(const uint4*)&g_Qlo[src];
    }
    for (int idx = tid; idx < 128*32; idx += 256) {
        int r = idx >> 5, c = idx & 31;
        rw_s[r*33 + c] = g_relw[((size_t)(bh*NSEQ + q0 + r))*32 + c];
    }

    // ---- prologue: stage 0 tile
    {
        #pragma unroll
        for (int it=0; it<4; ++it) {
            int idx = it*256 + tid;
            int kr = idx >> 3, q = idx & 7;
            cp16(&Kbuf[0*KPL + kr*QKS + q*8], &g_Khi[((size_t)(bh*NSEQ + kr))*HD + q*8]);
            cp16(&Kbuf[1*KPL + kr*QKS + q*8], &g_Klo[((size_t)(bh*NSEQ + kr))*HD + q*8]);
            int d = idx >> 4, vq = idx & 15;
            cp16(&Vbuf[0*VPL + d*VTS + vq*8], &g_VThi[((size_t)(bh*HD + d))*NSEQ + vq*8]);
            cp16(&Vbuf[1*VPL + d*VTS + vq*8], &g_VTlo[((size_t)(bh*HD + d))*NSEQ + vq*8]);
        }
        if (tid < 32) cp16(&pol_s[tid*4], &policy[(b_<<10) + tid*4]);
        cp_commit();
    }

    float m0 = -CUDART_INF_F, m1 = -CUDART_INF_F, l0v = 0.f, l1v = 0.f;
    float o[8][4];
    #pragma unroll
    for (int nd=0; nd<8; ++nd) { o[nd][0]=o[nd][1]=o[nd][2]=o[nd][3]=0.f; }

    #pragma unroll 1
    for (int t=0; t<8; ++t) {
        const int k0 = t << 7;
        if (t < 7) {
            const int kn = k0 + 128;
            const int sp = ((t+1)&1)*2;
            #pragma unroll
            for (int it=0; it<4; ++it) {
                int idx = it*256 + tid;
                int kr = idx >> 3, q = idx & 7;
                cp16(&Kbuf[(sp+0)*KPL + kr*QKS + q*8], &g_Khi[((size_t)(bh*NSEQ + kn + kr))*HD + q*8]);
                cp16(&Kbuf[(sp+1)*KPL + kr*QKS + q*8], &g_Klo[((size_t)(bh*NSEQ + kn + kr))*HD + q*8]);
                int d = idx >> 4, vq = idx & 15;
                cp16(&Vbuf[(sp+0)*VPL + d*VTS + vq*8], &g_VThi[((size_t)(bh*HD + d))*NSEQ + kn + vq*8]);
                cp16(&Vbuf[(sp+1)*VPL + d*VTS + vq*8], &g_VTlo[((size_t)(bh*HD + d))*NSEQ + kn + vq*8]);
            }
            if (tid < 32) cp16(&pol_s[((t+1)&1)*128 + tid*4], &policy[(b_<<10) + kn + tid*4]);
            cp_commit();
            cp_wait<1>();
        } else {
            cp_wait<0>();
        }
        __syncthreads();

        const __nv_bfloat16* Kh  = Kbuf + ((t&1)*2+0)*KPL;
        const __nv_bfloat16* Kl  = Kbuf + ((t&1)*2+1)*KPL;
        const __nv_bfloat16* Vth = Vbuf + ((t&1)*2+0)*VPL;
        const __nv_bfloat16* Vtl = Vbuf + ((t&1)*2+1)*VPL;
        const float* pol = pol_s + (t&1)*128;

        float4 rh0 = *(const float4*)&g_relh[((size_t)(bh*NSEQ + qg0))*32 + (k0>>5)];
        float4 rh1 = *(const float4*)&g_relh[((size_t)(bh*NSEQ + qg1))*32 + (k0>>5)];

        // ---- S = Q.K^T (3-MMA bf16 split)
        float acc[16][4];
        #pragma unroll
        for (int jb=0; jb<16; ++jb) { acc[jb][0]=acc[jb][1]=acc[jb][2]=acc[jb][3]=0.f; }

        #pragma unroll
        for (int kb=0; kb<4; ++kb) {
            const int kk = kb*16 + tig*2;
            uint32_t qhf[4], qlf[4];
            qhf[0] = *(const uint32_t*)&Qh[r0*QKS + kk];
            qhf[1] = *(const uint32_t*)&Qh[r1*QKS + kk];
            qhf[2] = *(const uint32_t*)&Qh[r0*QKS + kk + 8];
            qhf[3] = *(const uint32_t*)&Qh[r1*QKS + kk + 8];
            qlf[0] = *(const uint32_t*)&Ql[r0*QKS + kk];
            qlf[1] = *(const uint32_t*)&Ql[r1*QKS + kk];
            qlf[2] = *(const uint32_t*)&Ql[r0*QKS + kk + 8];
            qlf[3] = *(const uint32_t*)&Ql[r1*QKS + kk + 8];
            #pragma unroll
            for (int jb=0; jb<16; ++jb) {
                const int col = jb*8 + grp;
                const uint32_t kh0 = *(const uint32_t*)&Kh[col*QKS + kk];
                const uint32_t kh1 = *(const uint32_t*)&Kh[col*QKS + kk + 8];
                const uint32_t kl0 = *(const uint32_t*)&Kl[col*QKS + kk];
                const uint32_t kl1 = *(const uint32_t*)&Kl[col*QKS + kk + 8];
                MMA_BF16(acc[jb], qhf, kh0, kh1);
                MMA_BF16(acc[jb], qhf, kl0, kl1);
                MMA_BF16(acc[jb], qlf, kh0, kh1);
            }
        }

        // ---- bias + row max (full 128 cols, BEFORE mask — as reference)
        float tmax0 = -CUDART_INF_F, tmax1 = -CUDART_INF_F;
        #pragma unroll
        for (int jb=0; jb<16; ++jb) {
            const int kh = jb >> 2;
            const float rhv0 = (kh==0)?rh0.x:(kh==1)?rh0.y:(kh==2)?rh0.z:rh0.w;
            const float rhv1 = (kh==0)?rh1.x:(kh==1)?rh1.y:(kh==2)?rh1.z:rh1.w;
            const int cw = ((jb & 3) << 3) + (tig << 1);
            acc[jb][0] = acc[jb][0]*SCALE + rhv0 + rw_s[r0*33 + cw];
            acc[jb][1] = acc[jb][1]*SCALE + rhv0 + rw_s[r0*33 + cw + 1];
            acc[jb][2] = acc[jb][2]*SCALE + rhv1 + rw_s[r1*33 + cw];
            acc[jb][3] = acc[jb][3]*SCALE + rhv1 + rw_s[r1*33 + cw + 1];
            tmax0 = fmaxf(tmax0, fmaxf(acc[jb][0], acc[jb][1]));
            tmax1 = fmaxf(tmax1, fmaxf(acc[jb][2], acc[jb][3]));
        }
        tmax0 = fmaxf(tmax0, __shfl_xor_sync(0xffffffffu, tmax0, 1));
        tmax0 = fmaxf(tmax0, __shfl_xor_sync(0xffffffffu, tmax0, 2));
        tmax1 = fmaxf(tmax1, __shfl_xor_sync(0xffffffffu, tmax1, 1));
        tmax1 = fmaxf(tmax1, __shfl_xor_sync(0xffffffffu, tmax1, 2));

        const float mn0 = fmaxf(m0, tmax0);
        const float mn1 = fmaxf(m1, tmax1);
        const float f0 = __expf(m0 - mn0);
        const float f1 = __expf(m1 - mn1);
        m0 = mn0; m1 = mn1;
        #pragma unroll
        for (int nd=0; nd<8; ++nd) {
            o[nd][0]*=f0; o[nd][1]*=f0; o[nd][2]*=f1; o[nd][3]*=f1;
        }

        float rs0 = 0.f, rs1 = 0.f;
        #pragma unroll
        for (int half=0; half<2; ++half) {
            uint32_t pha[8], phb[8], pla[8], plb[8];
            #pragma unroll
            for (int j=0; j<8; ++j) {
                const int jb = half*8 + j;
                const int cb = (jb<<3) + (tig<<1);
                const int kg = k0 + cb;
                const float ap00 = (kg   == qg0) ? 1.f : pol[cb];
                const float ap01 = (kg+1 == qg0) ? 1.f : pol[cb+1];
                const float ap10 = (kg   == qg1) ? 1.f : pol[cb];
                const float ap11 = (kg+1 == qg1) ? 1.f : pol[cb+1];
                const float e00 = __expf(acc[jb][0] - mn0) * ap00;
                const float e01 = __expf(acc[jb][1] - mn0) * ap01;
                const float e10 = __expf(acc[jb][2] - mn1) * ap10;
                const float e11 = __expf(acc[jb][3] - mn1) * ap11;
                rs0 += e00 + e01;
                rs1 += e10 + e11;
                split2(e00, e01, pha[j], pla[j]);
                split2(e10, e11, phb[j], plb[j]);
            }
            #pragma unroll
            for (int j2=0; j2<4; ++j2) {
                const int g = half*4 + j2;
                uint32_t ahi[4] = { pha[j2*2], phb[j2*2], pha[j2*2+1], phb[j2*2+1] };
                uint32_t alo[4] = { pla[j2*2], plb[j2*2], pla[j2*2+1], plb[j2*2+1] };
                #pragma unroll
                for (int nd=0; nd<8; ++nd) {
                    const int dcol = nd*8 + grp;
                    const uint32_t vh0 = *(const uint32_t*)&Vth[dcol*VTS + g*16 + tig*2];
                    const uint32_t vh1 = *(const uint32_t*)&Vth[dcol*VTS + g*16 + tig*2 + 8];
                    const uint32_t vl0 = *(const uint32_t*)&Vtl[dcol*VTS + g*16 + tig*2];
                    const uint32_t vl1 = *(const uint32_t*)&Vtl[dcol*VTS + g*16 + tig*2 + 8];
                    MMA_BF16(o[nd], ahi, vh0, vh1);
                    MMA_BF16(o[nd], ahi, vl0, vl1);
                    MMA_BF16(o[nd], alo, vh0, vh1);
                }
            }
        }
        rs0 += __shfl_xor_sync(0xffffffffu, rs0, 1);
        rs0 += __shfl_xor_sync(0xffffffffu, rs0, 2);
        rs1 += __shfl_xor_sync(0xffffffffu, rs1, 1);
        rs1 += __shfl_xor_sync(0xffffffffu, rs1, 2);
        l0v = l0v*f0 + rs0;
        l1v = l1v*f1 + rs1;
        __syncthreads();
    }

    // ---- epilogue: out = (o + EPSN*vsum)/(l + EPSV), split bf16 hi/lo
    const float inv0 = 1.f / (l0v + EPSV);
    const float inv1 = 1.f / (l1v + EPSV);
    #pragma unroll
    for (int nd=0; nd<8; ++nd) {
        const int d = nd*8 + tig*2;
        const float2 vs = *(const float2*)&g_vsum[bh*HD + d];
        const float a0 = (o[nd][0] + EPSN*vs.x) * inv0;
        const float a1 = (o[nd][1] + EPSN*vs.y) * inv0;
        const float a2 = (o[nd][2] + EPSN*vs.x) * inv1;
        const float a3 = (o[nd][3] + EPSN*vs.y) * inv1;
        uint32_t h0,l0,h1,l1;
        split2(a0, a1, h0, l0);
        split2(a2, a3, h1, l1);
        const size_t base0 = ((size_t)(b_*NSEQ + qg0))*DM + hh*HD + d;
        const size_t base1 = ((size_t)(b_*NSEQ + qg1))*DM + hh*HD + d;
        *(uint32_t*)&g_Thi[base0] = h0;
        *(uint32_t*)&g_Tlo[base0] = l0;
        *(uint32_t*)&g_Thi[base1] = h1;
        *(uint32_t*)&g_Tlo[base1] = l1;
    }
}

// ---------------------------------------------------------------------------
extern "C" void kernel_launch(void* const* d_in, const int* in_sizes, int n_in,
                              void* d_out, int out_size)
{
    const float* x      = (const float*)d_in[0];
    const float* policy = (const float*)d_in[1];
    const float* qkv_w  = (const float*)d_in[2];
    const float* qkv_b  = (const float*)d_in[3];
    const float* proj_w = (const float*)d_in[4];
    const float* proj_b = (const float*)d_in[5];
    const float* rph    = (const float*)d_in[6];
    const float* rpw    = (const float*)d_in[7];
    float* out = (float*)d_out;

    cudaFuncSetAttribute(flash_mma,
        cudaFuncAttributeMaxDynamicSharedMemorySize, FL_SMEM_BYTES);
    cudaFuncSetAttribute(gemm_mma,
        cudaFuncAttributeMaxDynamicSharedMemorySize, GEMM_SMEM_BYTES);

    const int n4x = NB*NSEQ*DM/4, n4q = 2304*DM/4, n4p = DM*DM/4;
    split_kernel<<<(n4x+255)/256,256>>>(x,      0, n4x);
    split_kernel<<<(n4q+255)/256,256>>>(qkv_w,  1, n4q);
    split_kernel<<<(n4p+255)/256,256>>>(proj_w, 2, n4p);

    gemm_mma<<<dim3(18,64),256,GEMM_SMEM_BYTES>>>(qkv_b, nullptr, 0);
    vtrans_kernel<<<dim3(16,NBH),256>>>();
    rel_kernel<<<NBH*256,256>>>(rph, rpw);
    vsum_kernel<<<NBH,256>>>();
    flash_mma<<<dim3(8,NBH),256,FL_SMEM_BYTES>>>(policy);
    gemm_mma<<<dim3(6,64),256,GEMM_SMEM_BYTES>>>(proj_b, out, 1);
}

// round 11
// speedup vs baseline: 1.9552x; 1.0240x over previous
#include <cuda_runtime.h>
#include <cuda_bf16.h>
#include <math_constants.h>
#include <cstddef>
#include <cstdint>

#define NB 8
#define NH 12
#define HD 64
#define DM 768
#define NSEQ 1024
#define NBH 96
#define SCALE 0.125f
#define EPSV 1e-6f
#define EPSN (1e-6f/1024.0f)
#define WOFF (2304*768)

__device__ float g_Q[NBH*NSEQ*HD];
__device__ float g_V[NBH*NSEQ*HD];
__device__ float g_relh[NBH*NSEQ*32];
__device__ float g_relw[NBH*NSEQ*32];
__device__ float g_vsum[NBH*HD];

__device__ __nv_bfloat16 g_Xhi[NB*NSEQ*DM], g_Xlo[NB*NSEQ*DM];
__device__ __nv_bfloat16 g_Whi[3072*DM],    g_Wlo[3072*DM];
__device__ __nv_bfloat16 g_Thi[NB*NSEQ*DM], g_Tlo[NB*NSEQ*DM];

__device__ __nv_bfloat16 g_Qhi[NBH*NSEQ*HD], g_Qlo[NBH*NSEQ*HD];
__device__ __nv_bfloat16 g_Khi[NBH*NSEQ*HD], g_Klo[NBH*NSEQ*HD];
__device__ __nv_bfloat16 g_VThi[NBH*HD*NSEQ], g_VTlo[NBH*HD*NSEQ];  // [bh][d][k]

#define MMA_BF16(d, a, b0, b1)                                             \
  asm volatile("mma.sync.aligned.m16n8k16.row.col.f32.bf16.bf16.f32 "      \
    "{%0,%1,%2,%3},{%4,%5,%6,%7},{%8,%9},{%0,%1,%2,%3};\n"                 \
    : "+f"(d[0]), "+f"(d[1]), "+f"(d[2]), "+f"(d[3])                       \
    : "r"(a[0]), "r"(a[1]), "r"(a[2]), "r"(a[3]), "r"(b0), "r"(b1))

__device__ __forceinline__ uint32_t scvta(const void* p)
{
    return (uint32_t)__cvta_generic_to_shared(p);
}

__device__ __forceinline__ void ldsm_x4(uint32_t& r0, uint32_t& r1,
                                        uint32_t& r2, uint32_t& r3, uint32_t a)
{
    asm volatile("ldmatrix.sync.aligned.m8n8.x4.shared.b16 {%0,%1,%2,%3}, [%4];\n"
        : "=r"(r0), "=r"(r1), "=r"(r2), "=r"(r3) : "r"(a));
}

__device__ __forceinline__ void split2(float a, float b, uint32_t& hi, uint32_t& lo)
{
    __nv_bfloat162 h = __floats2bfloat162_rn(a, b);
    float ra = a - __bfloat162float(h.x);
    float rb = b - __bfloat162float(h.y);
    __nv_bfloat162 l = __floats2bfloat162_rn(ra, rb);
    hi = *(uint32_t*)&h;
    lo = *(uint32_t*)&l;
}

__device__ __forceinline__ void cp16(void* smem, const void* gmem)
{
    uint32_t s = scvta(smem);
    asm volatile("cp.async.cg.shared.global [%0], [%1], 16;\n" :: "r"(s), "l"(gmem));
}
__device__ __forceinline__ void cp_commit()
{
    asm volatile("cp.async.commit_group;\n");
}
template<int N> __device__ __forceinline__ void cp_wait()
{
    asm volatile("cp.async.wait_group %0;\n" :: "n"(N));
}

// ---------------------------------------------------------------------------
__global__ void split_kernel(const float* __restrict__ src, int which, int n4)
{
    int i = blockIdx.x*256 + threadIdx.x;
    if (i >= n4) return;
    __nv_bfloat16 *hi, *lo;
    if (which == 0)      { hi = g_Xhi;        lo = g_Xlo; }
    else if (which == 1) { hi = g_Whi;        lo = g_Wlo; }
    else                 { hi = g_Whi + WOFF; lo = g_Wlo + WOFF; }
    float4 v = ((const float4*)src)[i];
    uint32_t h0, l0, h1, l1;
    split2(v.x, v.y, h0, l0);
    split2(v.z, v.w, h1, l1);
    ((uint32_t*)hi)[i*2]   = h0;
    ((uint32_t*)hi)[i*2+1] = h1;
    ((uint32_t*)lo)[i*2]   = l0;
    ((uint32_t*)lo)[i*2+1] = l1;
}

// ---------------------------------------------------------------------------
// Tensor-core GEMM, cp.async double-buffered, 2 CTAs/SM, ldmatrix operands.
// ---------------------------------------------------------------------------
#define GSTRIDE 5120
#define GEMM_SMEM_BYTES (2 * 4 * GSTRIDE * 2)

__global__ __launch_bounds__(256,2) void gemm_mma(
    const float* __restrict__ bias, float* __restrict__ out, int mode)
{
    extern __shared__ __nv_bfloat16 smg[];
    __nv_bfloat16* As = smg;
    __nv_bfloat16* Bs = smg + 2*2*GSTRIDE;
    const __nv_bfloat16* Ah = mode ? g_Thi : g_Xhi;
    const __nv_bfloat16* Al = mode ? g_Tlo : g_Xlo;
    const __nv_bfloat16* Wh = g_Whi + (mode ? WOFF : 0);
    const __nv_bfloat16* Wl = g_Wlo + (mode ? WOFF : 0);

    const int m0 = blockIdx.y*128, c0 = blockIdx.x*128;
    const int tid = threadIdx.x, lane = tid & 31, wid = tid >> 5;
    const int wm = wid & 3, wn = wid >> 2;
    const int grp = lane >> 2, tig = lane & 3;
    const int ra = tid >> 2, qa = tid & 3;

    // ldmatrix per-lane offsets (elements)
    const int laneA = ((lane&7) + ((lane>>3)&1)*8)*40 + (lane>>4)*8;
    const int laneB = ((lane&7) + (lane>>4)*8)*40 + ((lane>>3)&1)*8;

    const size_t oA0 = (size_t)(m0+ra)*DM    + qa*8;
    const size_t oA1 = (size_t)(m0+ra+64)*DM + qa*8;
    const size_t oB0 = (size_t)(c0+ra)*DM    + qa*8;
    const size_t oB1 = (size_t)(c0+ra+64)*DM + qa*8;
    const int s0 = ra*40 + qa*8, s1 = (ra+64)*40 + qa*8;

    float acc[2][8][4];
    #pragma unroll
    for (int mi=0;mi<2;mi++)
        #pragma unroll
        for (int ni=0;ni<8;ni++)
            #pragma unroll
            for (int c=0;c<4;c++) acc[mi][ni][c] = 0.f;

    {
        cp16(&As[0*GSTRIDE + s0], &Ah[oA0]);
        cp16(&As[0*GSTRIDE + s1], &Ah[oA1]);
        cp16(&As[1*GSTRIDE + s0], &Al[oA0]);
        cp16(&As[1*GSTRIDE + s1], &Al[oA1]);
        cp16(&Bs[0*GSTRIDE + s0], &Wh[oB0]);
        cp16(&Bs[0*GSTRIDE + s1], &Wh[oB1]);
        cp16(&Bs[1*GSTRIDE + s0], &Wl[oB0]);
        cp16(&Bs[1*GSTRIDE + s1], &Wl[oB1]);
        cp_commit();
    }

    #pragma unroll 1
    for (int t=0; t<24; ++t) {
        if (t < 23) {
            const int kn = (t+1)*32;
            const int sp = ((t+1)&1)*2;
            cp16(&As[(sp+0)*GSTRIDE + s0], &Ah[oA0 + kn]);
            cp16(&As[(sp+0)*GSTRIDE + s1], &Ah[oA1 + kn]);
            cp16(&As[(sp+1)*GSTRIDE + s0], &Al[oA0 + kn]);
            cp16(&As[(sp+1)*GSTRIDE + s1], &Al[oA1 + kn]);
            cp16(&Bs[(sp+0)*GSTRIDE + s0], &Wh[oB0 + kn]);
            cp16(&Bs[(sp+0)*GSTRIDE + s1], &Wh[oB1 + kn]);
            cp16(&Bs[(sp+1)*GSTRIDE + s0], &Wl[oB0 + kn]);
            cp16(&Bs[(sp+1)*GSTRIDE + s1], &Wl[oB1 + kn]);
            cp_commit();
            cp_wait<1>();
        } else {
            cp_wait<0>();
        }
        __syncthreads();

        const __nv_bfloat16* AsH = As + ((t&1)*2+0)*GSTRIDE;
        const __nv_bfloat16* AsL = As + ((t&1)*2+1)*GSTRIDE;
        const __nv_bfloat16* BsH = Bs + ((t&1)*2+0)*GSTRIDE;
        const __nv_bfloat16* BsL = Bs + ((t&1)*2+1)*GSTRIDE;

        #pragma unroll
        for (int ks=0; ks<2; ++ks) {
            const int kb0 = ks*16;
            uint32_t ah[2][4], al[2][4];
            #pragma unroll
            for (int mi=0;mi<2;mi++) {
                const int rb = (wm*32+mi*16)*40 + kb0 + laneA;
                ldsm_x4(ah[mi][0],ah[mi][1],ah[mi][2],ah[mi][3], scvta(&AsH[rb]));
                ldsm_x4(al[mi][0],al[mi][1],al[mi][2],al[mi][3], scvta(&AsL[rb]));
            }
            #pragma unroll
            for (int np=0;np<4;np++) {
                const int nb = (wn*64 + np*16)*40 + kb0 + laneB;
                uint32_t bh[4], bl[4];
                ldsm_x4(bh[0],bh[1],bh[2],bh[3], scvta(&BsH[nb]));
                ldsm_x4(bl[0],bl[1],bl[2],bl[3], scvta(&BsL[nb]));
                #pragma unroll
                for (int s=0;s<2;s++) {
                    const int ni = np*2+s;
                    #pragma unroll
                    for (int mi=0;mi<2;mi++) {
                        MMA_BF16(acc[mi][ni], ah[mi], bh[s*2], bh[s*2+1]);
                        MMA_BF16(acc[mi][ni], ah[mi], bl[s*2], bl[s*2+1]);
                        MMA_BF16(acc[mi][ni], al[mi], bh[s*2], bh[s*2+1]);
                    }
                }
            }
        }
        __syncthreads();
    }

    #pragma unroll
    for (int mi=0;mi<2;mi++) {
        #pragma unroll
        for (int ni=0;ni<8;ni++) {
            const int c = c0 + wn*64 + ni*8 + tig*2;
            const float b0v = bias[c], b1v = bias[c+1];
            #pragma unroll
            for (int hr=0;hr<2;hr++) {
                const int m = m0 + wm*32 + mi*16 + grp + hr*8;
                const float v0 = acc[mi][ni][hr*2+0] + b0v;
                const float v1 = acc[mi][ni][hr*2+1] + b1v;
                if (mode == 1) {
                    *(float2*)&out[(size_t)m*DM + c] = make_float2(v0, v1);
                } else {
                    const int t  = (c >= 1536) ? 2 : (c >= 768 ? 1 : 0);
                    const int rr = c - t*DM;
                    const int hh = rr >> 6, d = rr & 63;
                    const int b_ = m >> 10, n = m & 1023;
                    const size_t di = ((size_t)((b_*NH+hh)*NSEQ + n))*HD + d;
                    if (t == 0) {
                        *(float2*)&g_Q[di] = make_float2(v0, v1);
                        uint32_t hh32, ll32;
                        split2(v0, v1, hh32, ll32);
                        *(uint32_t*)&g_Qhi[di] = hh32;
                        *(uint32_t*)&g_Qlo[di] = ll32;
                    } else if (t == 1) {
                        uint32_t hh32, ll32;
                        split2(v0, v1, hh32, ll32);
                        *(uint32_t*)&g_Khi[di] = hh32;
                        *(uint32_t*)&g_Klo[di] = ll32;
                    } else {
                        *(float2*)&g_V[di] = make_float2(v0, v1);
                    }
                }
            }
        }
    }
}

// ---------------------------------------------------------------------------
__global__ __launch_bounds__(256) void vtrans_kernel()
{
    __shared__ float ts[64*68];
    const int bh = blockIdx.y, k0 = blockIdx.x*64;
    const int tid = threadIdx.x;
    #pragma unroll
    for (int it=0; it<4; ++it) {
        int idx = it*256 + tid;
        int k = idx >> 4, dq = idx & 15;
        float4 v = *(const float4*)&g_V[((size_t)(bh*NSEQ + k0 + k))*HD + dq*4];
        *(float4*)&ts[k*68 + dq*4] = v;
    }
    __syncthreads();
    const int d = tid >> 2, kq = tid & 3;
    uint32_t hw[8], lw[8];
    #pragma unroll
    for (int i=0;i<8;++i) {
        float f0 = ts[(kq*16 + 2*i  )*68 + d];
        float f1 = ts[(kq*16 + 2*i+1)*68 + d];
        split2(f0, f1, hw[i], lw[i]);
    }
    const size_t base = ((size_t)(bh*HD + d))*NSEQ + k0 + kq*16;
    *(uint4*)&g_VThi[base]   = make_uint4(hw[0], hw[1], hw[2], hw[3]);
    *(uint4*)&g_VThi[base+8] = make_uint4(hw[4], hw[5], hw[6], hw[7]);
    *(uint4*)&g_VTlo[base]   = make_uint4(lw[0], lw[1], lw[2], lw[3]);
    *(uint4*)&g_VTlo[base+8] = make_uint4(lw[4], lw[5], lw[6], lw[7]);
}

// ---------------------------------------------------------------------------
__global__ __launch_bounds__(256) void rel_kernel(
    const float* __restrict__ rph, const float* __restrict__ rpw)
{
    __shared__ float qs[4*64];
    const int blk = blockIdx.x;
    const int bh = blk >> 8, ng = blk & 255;
    const int tid = threadIdx.x, ln = tid >> 6, t = tid & 63;
    const int n = (ng << 2) + ln;
    qs[ln*64 + t] = g_Q[((size_t)(bh*NSEQ + n))*HD + t];
    __syncthreads();

    const int j = t & 31, half = t >> 5;
    const int qh = n >> 5, qw = n & 31;
    const float* tab = half ? rpw : rph;
    const int ref = half ? qw : qh;
    const float4* row = (const float4*)&tab[(ref - j + 31)*HD];
    const float4* q4  = (const float4*)&qs[ln*64];
    float a = 0.f;
    #pragma unroll
    for (int d4=0; d4<16; ++d4) {
        float4 rr = row[d4], qq = q4[d4];
        a += rr.x*qq.x + rr.y*qq.y + rr.z*qq.z + rr.w*qq.w;
    }
    float* dst = half ? g_relw : g_relh;
    dst[((size_t)(bh*NSEQ + n))*32 + j] = a;
}

// ---------------------------------------------------------------------------
__global__ void vsum_kernel()
{
    __shared__ float red[256];
    const int bh = blockIdx.x, tid = threadIdx.x;
    const int d = tid & 63, part = tid >> 6;
    float s = 0.f;
    for (int k = part*256; k < part*256 + 256; ++k)
        s += g_V[((size_t)(bh*NSEQ + k))*HD + d];
    red[tid] = s;
    __syncthreads();
    if (tid < 64)
        g_vsum[bh*HD + tid] = red[tid] + red[tid+64] + red[tid+128] + red[tid+192];
}

// ---------------------------------------------------------------------------
// Flash attention, tensor cores + ldmatrix operands, cp.async double buffer.
// ---------------------------------------------------------------------------
#define QKS 72
#define VTS 136
#define KPL (128*QKS)
#define VPL (64*VTS)
#define FL_SMEM_BYTES (2*128*QKS*2 + 2*2*KPL*2 + 2*2*VPL*2 + 128*33*4 + 2*128*4)

__global__ __launch_bounds__(256,1) void flash_mma(const float* __restrict__ policy)
{
    extern __shared__ char smraw[];
    __nv_bfloat16* Qh   = (__nv_bfloat16*)smraw;
    __nv_bfloat16* Ql   = Qh + 128*QKS;
    __nv_bfloat16* Kbuf = Ql + 128*QKS;
    __nv_bfloat16* Vbuf = Kbuf + 2*2*KPL;
    float* rw_s  = (float*)(Vbuf + 2*2*VPL);
    float* pol_s = rw_s + 128*33;

    const int bh = blockIdx.y, q0 = blockIdx.x << 7;
    const int b_ = bh / NH, hh = bh - b_*NH;
    const int tid = threadIdx.x, lane = tid & 31, w = tid >> 5;
    const int grp = lane >> 2, tig = lane & 3;
    const int r0 = w*16 + grp, r1 = r0 + 8;
    const int qg0 = q0 + r0, qg1 = q0 + r1;

    // ldmatrix per-lane offsets
    const int laneAq = ((lane&7) + ((lane>>3)&1)*8)*QKS + (lane>>4)*8;   // A frag, stride QKS
    const int laneBk = ((lane&7) + (lane>>4)*8)*QKS + ((lane>>3)&1)*8;   // B frag, stride QKS
    const int laneBv = ((lane&7) + (lane>>4)*8)*VTS + ((lane>>3)&1)*8;   // B frag, stride VTS

    #pragma unroll
    for (int it=0; it<4; ++it) {
        int idx = it*256 + tid, r = idx >> 3, q = idx & 7;
        const size_t src = ((size_t)(bh*NSEQ + q0 + r))*HD + q*8;
        *(uint4*)&Qh[r*QKS + q*8] = *(const uint4*)&g_Qhi[src];
        *(uint4*)&Ql[r*QKS + q*8] = *(const uint4*)&g_Qlo[src];
    }
    for (int idx = tid; idx < 128*32; idx += 256) {
        int r = idx >> 5, c = idx & 31;
        rw_s[r*33 + c] = g_relw[((size_t)(bh*NSEQ + q0 + r))*32 + c];
    }

    {
        #pragma unroll
        for (int it=0; it<4; ++it) {
            int idx = it*256 + tid;
            int kr = idx >> 3, q = idx & 7;
            cp16(&Kbuf[0*KPL + kr*QKS + q*8], &g_Khi[((size_t)(bh*NSEQ + kr))*HD + q*8]);
            cp16(&Kbuf[1*KPL + kr*QKS + q*8], &g_Klo[((size_t)(bh*NSEQ + kr))*HD + q*8]);
            int d = idx >> 4, vq = idx & 15;
            cp16(&Vbuf[0*VPL + d*VTS + vq*8], &g_VThi[((size_t)(bh*HD + d))*NSEQ + vq*8]);
            cp16(&Vbuf[1*VPL + d*VTS + vq*8], &g_VTlo[((size_t)(bh*HD + d))*NSEQ + vq*8]);
        }
        if (tid < 32) cp16(&pol_s[tid*4], &policy[(b_<<10) + tid*4]);
        cp_commit();
    }

    float m0 = -CUDART_INF_F, m1 = -CUDART_INF_F, l0v = 0.f, l1v = 0.f;
    float o[8][4];
    #pragma unroll
    for (int nd=0; nd<8; ++nd) { o[nd][0]=o[nd][1]=o[nd][2]=o[nd][3]=0.f; }

    #pragma unroll 1
    for (int t=0; t<8; ++t) {
        const int k0 = t << 7;
        if (t < 7) {
            const int kn = k0 + 128;
            const int sp = ((t+1)&1)*2;
            #pragma unroll
            for (int it=0; it<4; ++it) {
                int idx = it*256 + tid;
                int kr = idx >> 3, q = idx & 7;
                cp16(&Kbuf[(sp+0)*KPL + kr*QKS + q*8], &g_Khi[((size_t)(bh*NSEQ + kn + kr))*HD + q*8]);
                cp16(&Kbuf[(sp+1)*KPL + kr*QKS + q*8], &g_Klo[((size_t)(bh*NSEQ + kn + kr))*HD + q*8]);
                int d = idx >> 4, vq = idx & 15;
                cp16(&Vbuf[(sp+0)*VPL + d*VTS + vq*8], &g_VThi[((size_t)(bh*HD + d))*NSEQ + kn + vq*8]);
                cp16(&Vbuf[(sp+1)*VPL + d*VTS + vq*8], &g_VTlo[((size_t)(bh*HD + d))*NSEQ + kn + vq*8]);
            }
            if (tid < 32) cp16(&pol_s[((t+1)&1)*128 + tid*4], &policy[(b_<<10) + kn + tid*4]);
            cp_commit();
            cp_wait<1>();
        } else {
            cp_wait<0>();
        }
        __syncthreads();

        const __nv_bfloat16* Kh  = Kbuf + ((t&1)*2+0)*KPL;
        const __nv_bfloat16* Kl  = Kbuf + ((t&1)*2+1)*KPL;
        const __nv_bfloat16* Vth = Vbuf + ((t&1)*2+0)*VPL;
        const __nv_bfloat16* Vtl = Vbuf + ((t&1)*2+1)*VPL;
        const float* pol = pol_s + (t&1)*128;

        float4 rh0 = *(const float4*)&g_relh[((size_t)(bh*NSEQ + qg0))*32 + (k0>>5)];
        float4 rh1 = *(const float4*)&g_relh[((size_t)(bh*NSEQ + qg1))*32 + (k0>>5)];

        // ---- S = Q.K^T (3-MMA bf16 split, ldmatrix operands)
        float acc[16][4];
        #pragma unroll
        for (int jb=0; jb<16; ++jb) { acc[jb][0]=acc[jb][1]=acc[jb][2]=acc[jb][3]=0.f; }

        #pragma unroll
        for (int kb=0; kb<4; ++kb) {
            const int kk0 = kb*16;
            uint32_t qhf[4], qlf[4];
            ldsm_x4(qhf[0],qhf[1],qhf[2],qhf[3], scvta(&Qh[w*16*QKS + kk0 + laneAq]));
            ldsm_x4(qlf[0],qlf[1],qlf[2],qlf[3], scvta(&Ql[w*16*QKS + kk0 + laneAq]));
            #pragma unroll
            for (int jp=0; jp<8; ++jp) {
                uint32_t kh[4], kl[4];
                ldsm_x4(kh[0],kh[1],kh[2],kh[3], scvta(&Kh[jp*16*QKS + kk0 + laneBk]));
                ldsm_x4(kl[0],kl[1],kl[2],kl[3], scvta(&Kl[jp*16*QKS + kk0 + laneBk]));
                #pragma unroll
                for (int s=0;s<2;s++) {
                    const int jb = jp*2+s;
                    MMA_BF16(acc[jb], qhf, kh[s*2], kh[s*2+1]);
                    MMA_BF16(acc[jb], qhf, kl[s*2], kl[s*2+1]);
                    MMA_BF16(acc[jb], qlf, kh[s*2], kh[s*2+1]);
                }
            }
        }

        // ---- bias + row max (full 128 cols, BEFORE mask — as reference)
        float tmax0 = -CUDART_INF_F, tmax1 = -CUDART_INF_F;
        #pragma unroll
        for (int jb=0; jb<16; ++jb) {
            const int kh = jb >> 2;
            const float rhv0 = (kh==0)?rh0.x:(kh==1)?rh0.y:(kh==2)?rh0.z:rh0.w;
            const float rhv1 = (kh==0)?rh1.x:(kh==1)?rh1.y:(kh==2)?rh1.z:rh1.w;
            const int cw = ((jb & 3) << 3) + (tig << 1);
            acc[jb][0] = acc[jb][0]*SCALE + rhv0 + rw_s[r0*33 + cw];
            acc[jb][1] = acc[jb][1]*SCALE + rhv0 + rw_s[r0*33 + cw + 1];
            acc[jb][2] = acc[jb][2]*SCALE + rhv1 + rw_s[r1*33 + cw];
            acc[jb][3] = acc[jb][3]*SCALE + rhv1 + rw_s[r1*33 + cw + 1];
            tmax0 = fmaxf(tmax0, fmaxf(acc[jb][0], acc[jb][1]));
            tmax1 = fmaxf(tmax1, fmaxf(acc[jb][2], acc[jb][3]));
        }
        tmax0 = fmaxf(tmax0, __shfl_xor_sync(0xffffffffu, tmax0, 1));
        tmax0 = fmaxf(tmax0, __shfl_xor_sync(0xffffffffu, tmax0, 2));
        tmax1 = fmaxf(tmax1, __shfl_xor_sync(0xffffffffu, tmax1, 1));
        tmax1 = fmaxf(tmax1, __shfl_xor_sync(0xffffffffu, tmax1, 2));

        const float mn0 = fmaxf(m0, tmax0);
        const float mn1 = fmaxf(m1, tmax1);
        const float f0 = __expf(m0 - mn0);
        const float f1 = __expf(m1 - mn1);
        m0 = mn0; m1 = mn1;
        #pragma unroll
        for (int nd=0; nd<8; ++nd) {
            o[nd][0]*=f0; o[nd][1]*=f0; o[nd][2]*=f1; o[nd][3]*=f1;
        }

        float rs0 = 0.f, rs1 = 0.f;
        #pragma unroll
        for (int half=0; half<2; ++half) {
            uint32_t pha[8], phb[8], pla[8], plb[8];
            #pragma unroll
            for (int j=0; j<8; ++j) {
                const int jb = half*8 + j;
                const int cb = (jb<<3) + (tig<<1);
                const int kg = k0 + cb;
                const float ap00 = (kg   == qg0) ? 1.f : pol[cb];
                const float ap01 = (kg+1 == qg0) ? 1.f : pol[cb+1];
                const float ap10 = (kg   == qg1) ? 1.f : pol[cb];
                const float ap11 = (kg+1 == qg1) ? 1.f : pol[cb+1];
                const float e00 = __expf(acc[jb][0] - mn0) * ap00;
                const float e01 = __expf(acc[jb][1] - mn0) * ap01;
                const float e10 = __expf(acc[jb][2] - mn1) * ap10;
                const float e11 = __expf(acc[jb][3] - mn1) * ap11;
                rs0 += e00 + e01;
                rs1 += e10 + e11;
                split2(e00, e01, pha[j], pla[j]);
                split2(e10, e11, phb[j], plb[j]);
            }
            #pragma unroll
            for (int j2=0; j2<4; ++j2) {
                const int g = half*4 + j2;
                uint32_t ahi[4] = { pha[j2*2], phb[j2*2], pha[j2*2+1], phb[j2*2+1] };
                uint32_t alo[4] = { pla[j2*2], plb[j2*2], pla[j2*2+1], plb[j2*2+1] };
                #pragma unroll
                for (int np=0; np<4; ++np) {
                    uint32_t vh[4], vl[4];
                    ldsm_x4(vh[0],vh[1],vh[2],vh[3], scvta(&Vth[np*16*VTS + g*16 + laneBv]));
                    ldsm_x4(vl[0],vl[1],vl[2],vl[3], scvta(&Vtl[np*16*VTS + g*16 + laneBv]));
                    #pragma unroll
                    for (int s=0;s<2;s++) {
                        const int nd = np*2+s;
                        MMA_BF16(o[nd], ahi, vh[s*2], vh[s*2+1]);
                        MMA_BF16(o[nd], ahi, vl[s*2], vl[s*2+1]);
                        MMA_BF16(o[nd], alo, vh[s*2], vh[s*2+1]);
                    }
                }
            }
        }
        rs0 += __shfl_xor_sync(0xffffffffu, rs0, 1);
        rs0 += __shfl_xor_sync(0xffffffffu, rs0, 2);
        rs1 += __shfl_xor_sync(0xffffffffu, rs1, 1);
        rs1 += __shfl_xor_sync(0xffffffffu, rs1, 2);
        l0v = l0v*f0 + rs0;
        l1v = l1v*f1 + rs1;
        __syncthreads();
    }

    const float inv0 = 1.f / (l0v + EPSV);
    const float inv1 = 1.f / (l1v + EPSV);
    #pragma unroll
    for (int nd=0; nd<8; ++nd) {
        const int d = nd*8 + tig*2;
        const float2 vs = *(const float2*)&g_vsum[bh*HD + d];
        const float a0 = (o[nd][0] + EPSN*vs.x) * inv0;
        const float a1 = (o[nd][1] + EPSN*vs.y) * inv0;
        const float a2 = (o[nd][2] + EPSN*vs.x) * inv1;
        const float a3 = (o[nd][3] + EPSN*vs.y) * inv1;
        uint32_t h0,l0,h1,l1;
        split2(a0, a1, h0, l0);
        split2(a2, a3, h1, l1);
        const size_t base0 = ((size_t)(b_*NSEQ + qg0))*DM + hh*HD + d;
        const size_t base1 = ((size_t)(b_*NSEQ + qg1))*DM + hh*HD + d;
        *(uint32_t*)&g_Thi[base0] = h0;
        *(uint32_t*)&g_Tlo[base0] = l0;
        *(uint32_t*)&g_Thi[base1] = h1;
        *(uint32_t*)&g_Tlo[base1] = l1;
    }
}

// ---------------------------------------------------------------------------
extern "C" void kernel_launch(void* const* d_in, const int* in_sizes, int n_in,
                              void* d_out, int out_size)
{
    const float* x      = (const float*)d_in[0];
    const float* policy = (const float*)d_in[1];
    const float* qkv_w  = (const float*)d_in[2];
    const float* qkv_b  = (const float*)d_in[3];
    const float* proj_w = (const float*)d_in[4];
    const float* proj_b = (const float*)d_in[5];
    const float* rph    = (const float*)d_in[6];
    const float* rpw    = (const float*)d_in[7];
    float* out = (float*)d_out;

    cudaFuncSetAttribute(flash_mma,
        cudaFuncAttributeMaxDynamicSharedMemorySize, FL_SMEM_BYTES);
    cudaFuncSetAttribute(gemm_mma,
        cudaFuncAttributeMaxDynamicSharedMemorySize, GEMM_SMEM_BYTES);

    const int n4x = NB*NSEQ*DM/4, n4q = 2304*DM/4, n4p = DM*DM/4;
    split_kernel<<<(n4x+255)/256,256>>>(x,      0, n4x);
    split_kernel<<<(n4q+255)/256,256>>>(qkv_w,  1, n4q);
    split_kernel<<<(n4p+255)/256,256>>>(proj_w, 2, n4p);

    gemm_mma<<<dim3(18,64),256,GEMM_SMEM_BYTES>>>(qkv_b, nullptr, 0);
    vtrans_kernel<<<dim3(16,NBH),256>>>();
    rel_kernel<<<NBH*256,256>>>(rph, rpw);
    vsum_kernel<<<NBH,256>>>();
    flash_mma<<<dim3(8,NBH),256,FL_SMEM_BYTES>>>(policy);
    gemm_mma<<<dim3(6,64),256,GEMM_SMEM_BYTES>>>(proj_b, out, 1);
}

// round 14
// speedup vs baseline: 2.0559x; 1.0515x over previous
#include <cuda_runtime.h>
#include <cuda_bf16.h>
#include <math_constants.h>
#include <cstddef>
#include <cstdint>

#define NB 8
#define NH 12
#define HD 64
#define DM 768
#define NSEQ 1024
#define NBH 96
#define SCALE 0.125f
#define EPSV 1e-6f
#define EPSN (1e-6f/1024.0f)
#define WOFF (2304*768)

__device__ float g_Q[NBH*NSEQ*HD];
__device__ float g_V[NBH*NSEQ*HD];
__device__ float g_relh[NBH*NSEQ*32];
__device__ float g_relw[NBH*NSEQ*32];
__device__ float g_vsum[NBH*HD];

__device__ __nv_bfloat16 g_Xhi[NB*NSEQ*DM], g_Xlo[NB*NSEQ*DM];
__device__ __nv_bfloat16 g_Whi[3072*DM],    g_Wlo[3072*DM];
__device__ __nv_bfloat16 g_Thi[NB*NSEQ*DM], g_Tlo[NB*NSEQ*DM];

__device__ __nv_bfloat16 g_Qhi[NBH*NSEQ*HD], g_Qlo[NBH*NSEQ*HD];
__device__ __nv_bfloat16 g_Khi[NBH*NSEQ*HD], g_Klo[NBH*NSEQ*HD];
__device__ __nv_bfloat16 g_VThi[NBH*HD*NSEQ], g_VTlo[NBH*HD*NSEQ];  // [bh][d][k]

#define MMA_BF16(d, a, b0, b1)                                             \
  asm volatile("mma.sync.aligned.m16n8k16.row.col.f32.bf16.bf16.f32 "      \
    "{%0,%1,%2,%3},{%4,%5,%6,%7},{%8,%9},{%0,%1,%2,%3};\n"                 \
    : "+f"(d[0]), "+f"(d[1]), "+f"(d[2]), "+f"(d[3])                       \
    : "r"(a[0]), "r"(a[1]), "r"(a[2]), "r"(a[3]), "r"(b0), "r"(b1))

__device__ __forceinline__ uint32_t scvta(const void* p)
{
    return (uint32_t)__cvta_generic_to_shared(p);
}

__device__ __forceinline__ void ldsm_x4(uint32_t& r0, uint32_t& r1,
                                        uint32_t& r2, uint32_t& r3, uint32_t a)
{
    asm volatile("ldmatrix.sync.aligned.m8n8.x4.shared.b16 {%0,%1,%2,%3}, [%4];\n"
        : "=r"(r0), "=r"(r1), "=r"(r2), "=r"(r3) : "r"(a));
}

__device__ __forceinline__ void split2(float a, float b, uint32_t& hi, uint32_t& lo)
{
    __nv_bfloat162 h = __floats2bfloat162_rn(a, b);
    float ra = a - __bfloat162float(h.x);
    float rb = b - __bfloat162float(h.y);
    __nv_bfloat162 l = __floats2bfloat162_rn(ra, rb);
    hi = *(uint32_t*)&h;
    lo = *(uint32_t*)&l;
}

__device__ __forceinline__ void cp16(void* smem, const void* gmem)
{
    uint32_t s = scvta(smem);
    asm volatile("cp.async.cg.shared.global [%0], [%1], 16;\n" :: "r"(s), "l"(gmem));
}
__device__ __forceinline__ void cp_commit()
{
    asm volatile("cp.async.commit_group;\n");
}
template<int N> __device__ __forceinline__ void cp_wait()
{
    asm volatile("cp.async.wait_group %0;\n" :: "n"(N));
}

// ---------------------------------------------------------------------------
__global__ void split_kernel(const float* __restrict__ src, int which, int n4)
{
    int i = blockIdx.x*256 + threadIdx.x;
    if (i >= n4) return;
    __nv_bfloat16 *hi, *lo;
    if (which == 0)      { hi = g_Xhi;        lo = g_Xlo; }
    else if (which == 1) { hi = g_Whi;        lo = g_Wlo; }
    else                 { hi = g_Whi + WOFF; lo = g_Wlo + WOFF; }
    float4 v = ((const float4*)src)[i];
    uint32_t h0, l0, h1, l1;
    split2(v.x, v.y, h0, l0);
    split2(v.z, v.w, h1, l1);
    ((uint32_t*)hi)[i*2]   = h0;
    ((uint32_t*)hi)[i*2+1] = h1;
    ((uint32_t*)lo)[i*2]   = l0;
    ((uint32_t*)lo)[i*2+1] = l1;
}

// ---------------------------------------------------------------------------
// Tensor-core GEMM (HMMA), cp.async double-buffered, 2 CTAs/SM, ldmatrix.
// (proven R10 version, unchanged)
// ---------------------------------------------------------------------------
#define GSTRIDE 5120
#define GEMM_SMEM_BYTES (2 * 4 * GSTRIDE * 2)

__global__ __launch_bounds__(256,2) void gemm_mma(
    const float* __restrict__ bias, float* __restrict__ out, int mode)
{
    extern __shared__ __nv_bfloat16 smg[];
    __nv_bfloat16* As = smg;
    __nv_bfloat16* Bs = smg + 2*2*GSTRIDE;
    const __nv_bfloat16* Ah = mode ? g_Thi : g_Xhi;
    const __nv_bfloat16* Al = mode ? g_Tlo : g_Xlo;
    const __nv_bfloat16* Wh = g_Whi + (mode ? WOFF : 0);
    const __nv_bfloat16* Wl = g_Wlo + (mode ? WOFF : 0);

    const int m0 = blockIdx.y*128, c0 = blockIdx.x*128;
    const int tid = threadIdx.x, lane = tid & 31, wid = tid >> 5;
    const int wm = wid & 3, wn = wid >> 2;
    const int grp = lane >> 2, tig = lane & 3;
    const int ra = tid >> 2, qa = tid & 3;

    const int laneA = ((lane&7) + ((lane>>3)&1)*8)*40 + (lane>>4)*8;
    const int laneB = ((lane&7) + (lane>>4)*8)*40 + ((lane>>3)&1)*8;

    const size_t oA0 = (size_t)(m0+ra)*DM    + qa*8;
    const size_t oA1 = (size_t)(m0+ra+64)*DM + qa*8;
    const size_t oB0 = (size_t)(c0+ra)*DM    + qa*8;
    const size_t oB1 = (size_t)(c0+ra+64)*DM + qa*8;
    const int s0 = ra*40 + qa*8, s1 = (ra+64)*40 + qa*8;

    float acc[2][8][4];
    #pragma unroll
    for (int mi=0;mi<2;mi++)
        #pragma unroll
        for (int ni=0;ni<8;ni++)
            #pragma unroll
            for (int c=0;c<4;c++) acc[mi][ni][c] = 0.f;

    {
        cp16(&As[0*GSTRIDE + s0], &Ah[oA0]);
        cp16(&As[0*GSTRIDE + s1], &Ah[oA1]);
        cp16(&As[1*GSTRIDE + s0], &Al[oA0]);
        cp16(&As[1*GSTRIDE + s1], &Al[oA1]);
        cp16(&Bs[0*GSTRIDE + s0], &Wh[oB0]);
        cp16(&Bs[0*GSTRIDE + s1], &Wh[oB1]);
        cp16(&Bs[1*GSTRIDE + s0], &Wl[oB0]);
        cp16(&Bs[1*GSTRIDE + s1], &Wl[oB1]);
        cp_commit();
    }

    #pragma unroll 1
    for (int t=0; t<24; ++t) {
        if (t < 23) {
            const int kn = (t+1)*32;
            const int sp = ((t+1)&1)*2;
            cp16(&As[(sp+0)*GSTRIDE + s0], &Ah[oA0 + kn]);
            cp16(&As[(sp+0)*GSTRIDE + s1], &Ah[oA1 + kn]);
            cp16(&As[(sp+1)*GSTRIDE + s0], &Al[oA0 + kn]);
            cp16(&As[(sp+1)*GSTRIDE + s1], &Al[oA1 + kn]);
            cp16(&Bs[(sp+0)*GSTRIDE + s0], &Wh[oB0 + kn]);
            cp16(&Bs[(sp+0)*GSTRIDE + s1], &Wh[oB1 + kn]);
            cp16(&Bs[(sp+1)*GSTRIDE + s0], &Wl[oB0 + kn]);
            cp16(&Bs[(sp+1)*GSTRIDE + s1], &Wl[oB1 + kn]);
            cp_commit();
            cp_wait<1>();
        } else {
            cp_wait<0>();
        }
        __syncthreads();

        const __nv_bfloat16* AsH = As + ((t&1)*2+0)*GSTRIDE;
        const __nv_bfloat16* AsL = As + ((t&1)*2+1)*GSTRIDE;
        const __nv_bfloat16* BsH = Bs + ((t&1)*2+0)*GSTRIDE;
        const __nv_bfloat16* BsL = Bs + ((t&1)*2+1)*GSTRIDE;

        #pragma unroll
        for (int ks=0; ks<2; ++ks) {
            const int kb0 = ks*16;
            uint32_t ah[2][4], al[2][4];
            #pragma unroll
            for (int mi=0;mi<2;mi++) {
                const int rb = (wm*32+mi*16)*40 + kb0 + laneA;
                ldsm_x4(ah[mi][0],ah[mi][1],ah[mi][2],ah[mi][3], scvta(&AsH[rb]));
                ldsm_x4(al[mi][0],al[mi][1],al[mi][2],al[mi][3], scvta(&AsL[rb]));
            }
            #pragma unroll
            for (int np=0;np<4;np++) {
                const int nb = (wn*64 + np*16)*40 + kb0 + laneB;
                uint32_t bh[4], bl[4];
                ldsm_x4(bh[0],bh[1],bh[2],bh[3], scvta(&BsH[nb]));
                ldsm_x4(bl[0],bl[1],bl[2],bl[3], scvta(&BsL[nb]));
                #pragma unroll
                for (int s=0;s<2;s++) {
                    const int ni = np*2+s;
                    #pragma unroll
                    for (int mi=0;mi<2;mi++) {
                        MMA_BF16(acc[mi][ni], ah[mi], bh[s*2], bh[s*2+1]);
                        MMA_BF16(acc[mi][ni], ah[mi], bl[s*2], bl[s*2+1]);
                        MMA_BF16(acc[mi][ni], al[mi], bh[s*2], bh[s*2+1]);
                    }
                }
            }
        }
        __syncthreads();
    }

    #pragma unroll
    for (int mi=0;mi<2;mi++) {
        #pragma unroll
        for (int ni=0;ni<8;ni++) {
            const int c = c0 + wn*64 + ni*8 + tig*2;
            const float b0v = bias[c], b1v = bias[c+1];
            #pragma unroll
            for (int hr=0;hr<2;hr++) {
                const int m = m0 + wm*32 + mi*16 + grp + hr*8;
                const float v0 = acc[mi][ni][hr*2+0] + b0v;
                const float v1 = acc[mi][ni][hr*2+1] + b1v;
                if (mode == 1) {
                    *(float2*)&out[(size_t)m*DM + c] = make_float2(v0, v1);
                } else {
                    const int t  = (c >= 1536) ? 2 : (c >= 768 ? 1 : 0);
                    const int rr = c - t*DM;
                    const int hh = rr >> 6, d = rr & 63;
                    const int b_ = m >> 10, n = m & 1023;
                    const size_t di = ((size_t)((b_*NH+hh)*NSEQ + n))*HD + d;
                    if (t == 0) {
                        *(float2*)&g_Q[di] = make_float2(v0, v1);
                        uint32_t hh32, ll32;
                        split2(v0, v1, hh32, ll32);
                        *(uint32_t*)&g_Qhi[di] = hh32;
                        *(uint32_t*)&g_Qlo[di] = ll32;
                    } else if (t == 1) {
                        uint32_t hh32, ll32;
                        split2(v0, v1, hh32, ll32);
                        *(uint32_t*)&g_Khi[di] = hh32;
                        *(uint32_t*)&g_Klo[di] = ll32;
                    } else {
                        *(float2*)&g_V[di] = make_float2(v0, v1);
                    }
                }
            }
        }
    }
}

// ---------------------------------------------------------------------------
__global__ __launch_bounds__(256) void vtrans_kernel()
{
    __shared__ float ts[64*68];
    const int bh = blockIdx.y, k0 = blockIdx.x*64;
    const int tid = threadIdx.x;
    #pragma unroll
    for (int it=0; it<4; ++it) {
        int idx = it*256 + tid;
        int k = idx >> 4, dq = idx & 15;
        float4 v = *(const float4*)&g_V[((size_t)(bh*NSEQ + k0 + k))*HD + dq*4];
        *(float4*)&ts[k*68 + dq*4] = v;
    }
    __syncthreads();
    const int d = tid >> 2, kq = tid & 3;
    uint32_t hw[8], lw[8];
    #pragma unroll
    for (int i=0;i<8;++i) {
        float f0 = ts[(kq*16 + 2*i  )*68 + d];
        float f1 = ts[(kq*16 + 2*i+1)*68 + d];
        split2(f0, f1, hw[i], lw[i]);
    }
    const size_t base = ((size_t)(bh*HD + d))*NSEQ + k0 + kq*16;
    *(uint4*)&g_VThi[base]   = make_uint4(hw[0], hw[1], hw[2], hw[3]);
    *(uint4*)&g_VThi[base+8] = make_uint4(hw[4], hw[5], hw[6], hw[7]);
    *(uint4*)&g_VTlo[base]   = make_uint4(lw[0], lw[1], lw[2], lw[3]);
    *(uint4*)&g_VTlo[base+8] = make_uint4(lw[4], lw[5], lw[6], lw[7]);
}

// ---------------------------------------------------------------------------
__global__ __launch_bounds__(256) void rel_kernel(
    const float* __restrict__ rph, const float* __restrict__ rpw)
{
    __shared__ float qs[4*64];
    const int blk = blockIdx.x;
    const int bh = blk >> 8, ng = blk & 255;
    const int tid = threadIdx.x, ln = tid >> 6, t = tid & 63;
    const int n = (ng << 2) + ln;
    qs[ln*64 + t] = g_Q[((size_t)(bh*NSEQ + n))*HD + t];
    __syncthreads();

    const int j = t & 31, half = t >> 5;
    const int qh = n >> 5, qw = n & 31;
    const float* tab = half ? rpw : rph;
    const int ref = half ? qw : qh;
    const float4* row = (const float4*)&tab[(ref - j + 31)*HD];
    const float4* q4  = (const float4*)&qs[ln*64];
    float a = 0.f;
    #pragma unroll
    for (int d4=0; d4<16; ++d4) {
        float4 rr = row[d4], qq = q4[d4];
        a += rr.x*qq.x + rr.y*qq.y + rr.z*qq.z + rr.w*qq.w;
    }
    float* dst = half ? g_relw : g_relh;
    dst[((size_t)(bh*NSEQ + n))*32 + j] = a;
}

// ---------------------------------------------------------------------------
__global__ void vsum_kernel()
{
    __shared__ float red[256];
    const int bh = blockIdx.x, tid = threadIdx.x;
    const int d = tid & 63, part = tid >> 6;
    float s = 0.f;
    for (int k = part*256; k < part*256 + 256; ++k)
        s += g_V[((size_t)(bh*NSEQ + k))*HD + d];
    red[tid] = s;
    __syncthreads();
    if (tid < 64)
        g_vsum[bh*HD + tid] = red[tid] + red[tid+64] + red[tid+128] + red[tid+192];
}

// ---------------------------------------------------------------------------
// Flash attention v2: k-tile 64, 2 CTAs/SM, rel_w in registers.
// Pipeline FIX vs R12: prefetch of tile t+2 is issued at the BOTTOM of
// iteration t, after the __syncthreads() that retires stage t&1.
// ---------------------------------------------------------------------------
#define QKS 72
#define KPL2 (64*QKS)
#define VPL2 (64*QKS)
#define FL_SMEM_BYTES (2*128*QKS*2 + 4*KPL2*2 + 4*VPL2*2 + 2*64*4)

__global__ __launch_bounds__(256,2) void flash_mma(const float* __restrict__ policy)
{
    extern __shared__ char smraw[];
    __nv_bfloat16* Qh   = (__nv_bfloat16*)smraw;       // 128*QKS
    __nv_bfloat16* Ql   = Qh + 128*QKS;
    __nv_bfloat16* Kbuf = Ql + 128*QKS;                // [(stage*2+hl)][KPL2]
    __nv_bfloat16* Vbuf = Kbuf + 4*KPL2;               // [(stage*2+hl)][VPL2]
    float* pol_s = (float*)(Vbuf + 4*VPL2);            // [2][64]

    const int bh = blockIdx.y, q0 = blockIdx.x << 7;
    const int b_ = bh / NH, hh = bh - b_*NH;
    const int tid = threadIdx.x, lane = tid & 31, w = tid >> 5;
    const int grp = lane >> 2, tig = lane & 3;
    const int r0 = w*16 + grp, r1 = r0 + 8;
    const int qg0 = q0 + r0, qg1 = q0 + r1;

    const int laneAq = ((lane&7) + ((lane>>3)&1)*8)*QKS + (lane>>4)*8;
    const int laneBk = ((lane&7) + (lane>>4)*8)*QKS + ((lane>>3)&1)*8;
    const int laneBv = laneBk;   // same geometry, stride QKS

    // ---- Q tile hi/lo (once)
    #pragma unroll
    for (int it=0; it<4; ++it) {
        int idx = it*256 + tid, r = idx >> 3, q = idx & 7;
        const size_t src = ((size_t)(bh*NSEQ + q0 + r))*HD + q*8;
        *(uint4*)&Qh[r*QKS + q*8] = *(const uint4*)&g_Qhi[src];
        *(uint4*)&Ql[r*QKS + q*8] = *(const uint4*)&g_Qlo[src];
    }

    // ---- rel_w in registers: col pattern repeats mod 32 across tiles
    float rwr[16];
    #pragma unroll
    for (int j=0; j<4; ++j) {
        float2 a = *(const float2*)&g_relw[((size_t)(bh*NSEQ + qg0))*32 + j*8 + tig*2];
        float2 b = *(const float2*)&g_relw[((size_t)(bh*NSEQ + qg1))*32 + j*8 + tig*2];
        rwr[j*2]     = a.x;  rwr[j*2+1]   = a.y;
        rwr[8+j*2]   = b.x;  rwr[8+j*2+1] = b.y;
    }

    // ---- tile loader (64 keys) into stage sp
    auto load_tile = [&](int kt, int sp) {
        const int kb = kt*64;
        #pragma unroll
        for (int it=0; it<2; ++it) {
            int idx = it*256 + tid;
            int kr = idx >> 3, q = idx & 7;
            cp16(&Kbuf[(sp*2+0)*KPL2 + kr*QKS + q*8],
                 &g_Khi[((size_t)(bh*NSEQ + kb + kr))*HD + q*8]);
            cp16(&Kbuf[(sp*2+1)*KPL2 + kr*QKS + q*8],
                 &g_Klo[((size_t)(bh*NSEQ + kb + kr))*HD + q*8]);
            cp16(&Vbuf[(sp*2+0)*VPL2 + kr*QKS + q*8],
                 &g_VThi[((size_t)(bh*HD + kr))*NSEQ + kb + q*8]);
            cp16(&Vbuf[(sp*2+1)*VPL2 + kr*QKS + q*8],
                 &g_VTlo[((size_t)(bh*HD + kr))*NSEQ + kb + q*8]);
        }
        if (tid < 16) cp16(&pol_s[sp*64 + tid*4], &policy[(b_<<10) + kb + tid*4]);
        cp_commit();
    };

    load_tile(0, 0);
    load_tile(1, 1);

    float m0 = -CUDART_INF_F, m1 = -CUDART_INF_F, l0v = 0.f, l1v = 0.f;
    float o[8][4];
    #pragma unroll
    for (int nd=0; nd<8; ++nd) { o[nd][0]=o[nd][1]=o[nd][2]=o[nd][3]=0.f; }

    #pragma unroll 1
    for (int t=0; t<16; ++t) {
        const int k0 = t << 6;
        if (t < 15) cp_wait<1>(); else cp_wait<0>();
        __syncthreads();

        const __nv_bfloat16* Kh  = Kbuf + ((t&1)*2+0)*KPL2;
        const __nv_bfloat16* Kl  = Kbuf + ((t&1)*2+1)*KPL2;
        const __nv_bfloat16* Vth = Vbuf + ((t&1)*2+0)*VPL2;
        const __nv_bfloat16* Vtl = Vbuf + ((t&1)*2+1)*VPL2;
        const float* pol = pol_s + (t&1)*64;

        float2 rh0 = *(const float2*)&g_relh[((size_t)(bh*NSEQ + qg0))*32 + (k0>>5)];
        float2 rh1 = *(const float2*)&g_relh[((size_t)(bh*NSEQ + qg1))*32 + (k0>>5)];

        // ---- S = Q.K^T (3-MMA bf16 split)
        float acc[8][4];
        #pragma unroll
        for (int jb=0; jb<8; ++jb) { acc[jb][0]=acc[jb][1]=acc[jb][2]=acc[jb][3]=0.f; }

        #pragma unroll
        for (int kb=0; kb<4; ++kb) {
            const int kk0 = kb*16;
            uint32_t qhf[4], qlf[4];
            ldsm_x4(qhf[0],qhf[1],qhf[2],qhf[3], scvta(&Qh[w*16*QKS + kk0 + laneAq]));
            ldsm_x4(qlf[0],qlf[1],qlf[2],qlf[3], scvta(&Ql[w*16*QKS + kk0 + laneAq]));
            #pragma unroll
            for (int jp=0; jp<4; ++jp) {
                uint32_t kh[4], kl[4];
                ldsm_x4(kh[0],kh[1],kh[2],kh[3], scvta(&Kh[jp*16*QKS + kk0 + laneBk]));
                ldsm_x4(kl[0],kl[1],kl[2],kl[3], scvta(&Kl[jp*16*QKS + kk0 + laneBk]));
                #pragma unroll
                for (int s=0;s<2;s++) {
                    const int jb = jp*2+s;
                    MMA_BF16(acc[jb], qhf, kh[s*2], kh[s*2+1]);
                    MMA_BF16(acc[jb], qhf, kl[s*2], kl[s*2+1]);
                    MMA_BF16(acc[jb], qlf, kh[s*2], kh[s*2+1]);
                }
            }
        }

        // ---- bias + row max over this 64-key tile (online softmax)
        float tmax0 = -CUDART_INF_F, tmax1 = -CUDART_INF_F;
        #pragma unroll
        for (int jb=0; jb<8; ++jb) {
            const int khs = (jb >> 2) & 1;
            const float rhv0 = khs ? rh0.y : rh0.x;
            const float rhv1 = khs ? rh1.y : rh1.x;
            const int rwi = (jb & 3) * 2;
            acc[jb][0] = acc[jb][0]*SCALE + rhv0 + rwr[rwi];
            acc[jb][1] = acc[jb][1]*SCALE + rhv0 + rwr[rwi+1];
            acc[jb][2] = acc[jb][2]*SCALE + rhv1 + rwr[8+rwi];
            acc[jb][3] = acc[jb][3]*SCALE + rhv1 + rwr[8+rwi+1];
            tmax0 = fmaxf(tmax0, fmaxf(acc[jb][0], acc[jb][1]));
            tmax1 = fmaxf(tmax1, fmaxf(acc[jb][2], acc[jb][3]));
        }
        tmax0 = fmaxf(tmax0, __shfl_xor_sync(0xffffffffu, tmax0, 1));
        tmax0 = fmaxf(tmax0, __shfl_xor_sync(0xffffffffu, tmax0, 2));
        tmax1 = fmaxf(tmax1, __shfl_xor_sync(0xffffffffu, tmax1, 1));
        tmax1 = fmaxf(tmax1, __shfl_xor_sync(0xffffffffu, tmax1, 2));

        const float mn0 = fmaxf(m0, tmax0);
        const float mn1 = fmaxf(m1, tmax1);
        const float f0 = __expf(m0 - mn0);
        const float f1 = __expf(m1 - mn1);
        m0 = mn0; m1 = mn1;
        #pragma unroll
        for (int nd=0; nd<8; ++nd) {
            o[nd][0]*=f0; o[nd][1]*=f0; o[nd][2]*=f1; o[nd][3]*=f1;
        }

        float rs0 = 0.f, rs1 = 0.f;
        #pragma unroll
        for (int g=0; g<4; ++g) {
            uint32_t pA[2], pB[2], lA[2], lB[2];
            #pragma unroll
            for (int jj=0; jj<2; ++jj) {
                const int jb = g*2 + jj;
                const int cb = (jb<<3) + (tig<<1);
                const int kg = k0 + cb;
                const float ap00 = (kg   == qg0) ? 1.f : pol[cb];
                const float ap01 = (kg+1 == qg0) ? 1.f : pol[cb+1];
                const float ap10 = (kg   == qg1) ? 1.f : pol[cb];
                const float ap11 = (kg+1 == qg1) ? 1.f : pol[cb+1];
                const float e00 = __expf(acc[jb][0] - mn0) * ap00;
                const float e01 = __expf(acc[jb][1] - mn0) * ap01;
                const float e10 = __expf(acc[jb][2] - mn1) * ap10;
                const float e11 = __expf(acc[jb][3] - mn1) * ap11;
                rs0 += e00 + e01;
                rs1 += e10 + e11;
                split2(e00, e01, pA[jj], lA[jj]);
                split2(e10, e11, pB[jj], lB[jj]);
            }
            uint32_t ahi[4] = { pA[0], pB[0], pA[1], pB[1] };
            uint32_t alo[4] = { lA[0], lB[0], lA[1], lB[1] };
            #pragma unroll
            for (int np=0; np<4; ++np) {
                uint32_t vh[4], vl[4];
                ldsm_x4(vh[0],vh[1],vh[2],vh[3], scvta(&Vth[np*16*QKS + g*16 + laneBv]));
                ldsm_x4(vl[0],vl[1],vl[2],vl[3], scvta(&Vtl[np*16*QKS + g*16 + laneBv]));
                #pragma unroll
                for (int s=0;s<2;s++) {
                    const int nd = np*2+s;
                    MMA_BF16(o[nd], ahi, vh[s*2], vh[s*2+1]);
                    MMA_BF16(o[nd], ahi, vl[s*2], vl[s*2+1]);
                    MMA_BF16(o[nd], alo, vh[s*2], vh[s*2+1]);
                }
            }
        }
        rs0 += __shfl_xor_sync(0xffffffffu, rs0, 1);
        rs0 += __shfl_xor_sync(0xffffffffu, rs0, 2);
        rs1 += __shfl_xor_sync(0xffffffffu, rs1, 1);
        rs1 += __shfl_xor_sync(0xffffffffu, rs1, 2);
        l0v = l0v*f0 + rs0;
        l1v = l1v*f1 + rs1;

        __syncthreads();                 // stage t&1 fully consumed by ALL warps
        if (t < 14) load_tile(t+2, t&1); // now safe to overwrite it
    }

    const float inv0 = 1.f / (l0v + EPSV);
    const float inv1 = 1.f / (l1v + EPSV);
    #pragma unroll
    for (int nd=0; nd<8; ++nd) {
        const int d = nd*8 + tig*2;
        const float2 vs = *(const float2*)&g_vsum[bh*HD + d];
        const float a0 = (o[nd][0] + EPSN*vs.x) * inv0;
        const float a1 = (o[nd][1] + EPSN*vs.y) * inv0;
        const float a2 = (o[nd][2] + EPSN*vs.x) * inv1;
        const float a3 = (o[nd][3] + EPSN*vs.y) * inv1;
        uint32_t h0,l0,h1,l1;
        split2(a0, a1, h0, l0);
        split2(a2, a3, h1, l1);
        const size_t base0 = ((size_t)(b_*NSEQ + qg0))*DM + hh*HD + d;
        const size_t base1 = ((size_t)(b_*NSEQ + qg1))*DM + hh*HD + d;
        *(uint32_t*)&g_Thi[base0] = h0;
        *(uint32_t*)&g_Tlo[base0] = l0;
        *(uint32_t*)&g_Thi[base1] = h1;
        *(uint32_t*)&g_Tlo[base1] = l1;
    }
}

// ---------------------------------------------------------------------------
extern "C" void kernel_launch(void* const* d_in, const int* in_sizes, int n_in,
                              void* d_out, int out_size)
{
    const float* x      = (const float*)d_in[0];
    const float* policy = (const float*)d_in[1];
    const float* qkv_w  = (const float*)d_in[2];
    const float* qkv_b  = (const float*)d_in[3];
    const float* proj_w = (const float*)d_in[4];
    const float* proj_b = (const float*)d_in[5];
    const float* rph    = (const float*)d_in[6];
    const float* rpw    = (const float*)d_in[7];
    float* out = (float*)d_out;

    cudaFuncSetAttribute(flash_mma,
        cudaFuncAttributeMaxDynamicSharedMemorySize, FL_SMEM_BYTES);
    cudaFuncSetAttribute(gemm_mma,
        cudaFuncAttributeMaxDynamicSharedMemorySize, GEMM_SMEM_BYTES);

    const int n4x = NB*NSEQ*DM/4, n4q = 2304*DM/4, n4p = DM*DM/4;
    split_kernel<<<(n4x+255)/256,256>>>(x,      0, n4x);
    split_kernel<<<(n4q+255)/256,256>>>(qkv_w,  1, n4q);
    split_kernel<<<(n4p+255)/256,256>>>(proj_w, 2, n4p);

    gemm_mma<<<dim3(18,64),256,GEMM_SMEM_BYTES>>>(qkv_b, nullptr, 0);
    vtrans_kernel<<<dim3(16,NBH),256>>>();
    rel_kernel<<<NBH*256,256>>>(rph, rpw);
    vsum_kernel<<<NBH,256>>>();
    flash_mma<<<dim3(8,NBH),256,FL_SMEM_BYTES>>>(policy);
    gemm_mma<<<dim3(6,64),256,GEMM_SMEM_BYTES>>>(proj_b, out, 1);
}